// round 1
// baseline (speedup 1.0000x reference)
#include <cuda_runtime.h>
#include <math.h>

#define B_  4
#define T_  1024
#define D_  768
#define H_  6
#define HD_ 128
#define L_  12
#define BTD (B_*T_*D_)          // 3145728
#define EPSF 1.1920929e-07f

// ---------------- scratch (device globals; no allocation allowed) ----------------
__device__ float g_x   [BTD];
__device__ float g_x0  [BTD];
__device__ float g_xn  [BTD];
__device__ float g_skips[6*BTD];
__device__ float g_ve  [3*BTD];
__device__ float g_qkv [B_*T_*3*H_*HD_];      // [bt][which*768 + h*128 + hd]
__device__ float g_q   [B_*H_*T_*HD_];        // [b][h][t][hd]
__device__ float g_k   [B_*H_*T_*HD_];
__device__ float g_v   [B_*H_*T_*HD_];
__device__ float g_scores[B_*H_*T_*T_];       // [b][h][t][s]
__device__ float g_att [BTD];                 // [b][t][h*128+hd]
__device__ float g_hbuf[B_*T_*4*D_];          // [bt][3072]

// ---------------- helpers ----------------
__device__ __forceinline__ float blockReduceSum256(float v, float* red) {
    int tid = threadIdx.x;
    red[tid] = v; __syncthreads();
    for (int s = 128; s > 0; s >>= 1) {
        if (tid < s) red[tid] += red[tid + s];
        __syncthreads();
    }
    float r = red[0]; __syncthreads();
    return r;
}

// ---------------- embedding + norm + ve gather ----------------
__global__ __launch_bounds__(256)
void gpt_embed(const int* __restrict__ seq, const float* __restrict__ ew,
               const float* __restrict__ vew,
               float* __restrict__ x, float* __restrict__ x0, float* __restrict__ ve)
{
    __shared__ float red[256];
    int bt = blockIdx.x;
    int tid = threadIdx.x;
    int idx = seq[bt];
    const float* er = ew + (long)idx * D_;
    float a0 = er[tid], a1 = er[tid + 256], a2 = er[tid + 512];
    float ss = blockReduceSum256(a0*a0 + a1*a1 + a2*a2, red);
    float r = rsqrtf(ss / (float)D_ + EPSF);
    long o = (long)bt * D_;
    x0[o + tid]       = a0 * r;  x[o + tid]       = a0 * r;
    x0[o + tid + 256] = a1 * r;  x[o + tid + 256] = a1 * r;
    x0[o + tid + 512] = a2 * r;  x[o + tid + 512] = a2 * r;
    #pragma unroll
    for (int j = 0; j < 3; j++) {
        const float* vr = vew + ((long)j * 50257 + idx) * D_;
        float* vo = ve + ((long)j * (B_*T_) + bt) * D_;
        for (int d = tid; d < D_; d += 256) vo[d] = vr[d];
    }
}

// ---------------- rms norm (row = 768) ----------------
__global__ __launch_bounds__(256)
void gpt_rmsnorm(const float* __restrict__ x, float* __restrict__ y)
{
    __shared__ float red[256];
    int tid = threadIdx.x;
    const float* xr = x + (long)blockIdx.x * D_;
    float a0 = xr[tid], a1 = xr[tid + 256], a2 = xr[tid + 512];
    float ss = blockReduceSum256(a0*a0 + a1*a1 + a2*a2, red);
    float r = rsqrtf(ss / (float)D_ + EPSF);
    float* yr = y + (long)blockIdx.x * D_;
    yr[tid] = a0 * r; yr[tid + 256] = a1 * r; yr[tid + 512] = a2 * r;
}

// ---------------- final norm -> output ----------------
__global__ __launch_bounds__(256)
void gpt_finalnorm(const float* __restrict__ x, float* __restrict__ out)
{
    __shared__ float red[256];
    int tid = threadIdx.x;
    const float* xr = x + (long)blockIdx.x * D_;
    float a0 = xr[tid], a1 = xr[tid + 256], a2 = xr[tid + 512];
    float ss = blockReduceSum256(a0*a0 + a1*a1 + a2*a2, red);
    float r = rsqrtf(ss / (float)D_ + EPSF);
    float* yr = out + (long)blockIdx.x * D_;
    yr[tid] = a0 * r; yr[tid + 256] = a1 * r; yr[tid + 512] = a2 * r;
}

// ---------------- residual combine: x = l0*(x + sw*skip) + l1*x0 ----------------
__global__ __launch_bounds__(256)
void gpt_residual(float* __restrict__ x, const float* __restrict__ x0,
                  const float* __restrict__ skip, const float* __restrict__ scalars, int layer)
{
    float l0 = scalars[L_ + 2*layer];
    float l1 = scalars[L_ + 2*layer + 1];
    float sw = skip ? scalars[layer - 6] : 0.f;
    long n = (long)BTD;
    for (long i = (long)blockIdx.x * 256 + threadIdx.x; i < n; i += (long)gridDim.x * 256) {
        float v = x[i];
        if (skip) v += sw * skip[i];
        x[i] = l0 * v + l1 * x0[i];
    }
}

__global__ __launch_bounds__(256)
void gpt_copy(float* __restrict__ dst, const float* __restrict__ src)
{
    long n = (long)BTD;
    for (long i = (long)blockIdx.x * 256 + threadIdx.x; i < n; i += (long)gridDim.x * 256)
        dst[i] = src[i];
}

// ---------------- qk norm + rope + v mix; repack to [b][h][t][hd] ----------------
__global__ __launch_bounds__(128)
void gpt_rope(const float* __restrict__ qkv, const float* __restrict__ ve,
              const float* __restrict__ scalars, int layer,
              float* __restrict__ q, float* __restrict__ k, float* __restrict__ v)
{
    __shared__ float rq[128], rk[128], sq[128], sk[128];
    int z = blockIdx.x;
    int hd = threadIdx.x;
    int h = z % H_;
    int t = (z / H_) % T_;
    int b = z / (H_ * T_);
    long bt = (long)b * T_ + t;
    const float* base = qkv + bt * (3*H_*HD_) + h * HD_;
    float qv = base[hd], kv = base[H_*HD_ + hd], vv = base[2*H_*HD_ + hd];

    rq[hd] = qv * qv; rk[hd] = kv * kv;
    __syncthreads();
    for (int s = 64; s > 0; s >>= 1) {
        if (hd < s) { rq[hd] += rq[hd + s]; rk[hd] += rk[hd + s]; }
        __syncthreads();
    }
    float rnq = rsqrtf(rq[0] / (float)HD_ + EPSF);
    float rnk = rsqrtf(rk[0] / (float)HD_ + EPSF);
    __syncthreads();
    sq[hd] = qv * rnq; sk[hd] = kv * rnk;
    __syncthreads();

    int j = hd & 63;
    float freq = (j < 32) ? exp2f(-10.0f * (float)j / 31.0f) : 0.0f;
    float sn, cs;
    sincosf((float)t * freq, &sn, &cs);
    float oq, ok;
    if (hd < 64) { oq =  sq[hd] * cs + sq[hd + 64] * sn;  ok =  sk[hd] * cs + sk[hd + 64] * sn; }
    else         { oq = -sq[hd - 64] * sn + sq[hd] * cs;  ok = -sk[hd - 64] * sn + sk[hd] * cs; }

    long o = (((long)b * H_ + h) * T_ + t) * HD_ + hd;
    q[o] = oq; k[o] = ok;

    float sa0 = scalars[3*L_ + 2*layer];
    float sa1 = scalars[3*L_ + 2*layer + 1];
    float vo = sa0 * vv;
    if (ve) vo += sa1 * ve[bt * D_ + h * HD_ + hd];
    v[o] = vo;
}

// ---------------- softmax over row of 1024 ----------------
__global__ __launch_bounds__(256)
void gpt_softmax(float* __restrict__ S)
{
    __shared__ float red[256];
    int tid = threadIdx.x;
    float* p = S + (long)blockIdx.x * T_;
    float v[4];
    float mx = -3.4e38f;
    #pragma unroll
    for (int j = 0; j < 4; j++) { v[j] = p[tid + j*256]; mx = fmaxf(mx, v[j]); }
    red[tid] = mx; __syncthreads();
    for (int s = 128; s > 0; s >>= 1) { if (tid < s) red[tid] = fmaxf(red[tid], red[tid+s]); __syncthreads(); }
    float m = red[0]; __syncthreads();
    float sum = 0.f;
    #pragma unroll
    for (int j = 0; j < 4; j++) { v[j] = expf(v[j] - m); sum += v[j]; }
    float tot = blockReduceSum256(sum, red);
    float inv = 1.0f / tot;
    #pragma unroll
    for (int j = 0; j < 4; j++) p[tid + j*256] = v[j] * inv;
}

// ---------------- tiled GEMM: C = op(A,B); 64x64x16, 4x4/thread ----------------
// EPI: 0=store, 1=accumulate into C, 2=relu^2 store, 3=causal scores (alpha scale, -1e30 mask)
// BT:  true -> C[m][n] = sum_k A[m][k]*B[n][k];  false -> C=A*B (B is [K][N])
template<int EPI, bool BT>
__global__ __launch_bounds__(256)
void gpt_gemm(const float* __restrict__ A, const float* __restrict__ Bm, float* __restrict__ C,
              int K, int lda, int ldb, int ldc,
              long aZ, long bZ, int zdiv, long c1, long c2, float alpha)
{
    int z = blockIdx.z;
    A  += (long)z * aZ;
    Bm += (long)z * bZ;
    C  += (long)(z / zdiv) * c1 + (long)(z % zdiv) * c2;

    int m0 = blockIdx.y * 64, n0 = blockIdx.x * 64;
    int tid = threadIdx.x;
    int tx = tid & 15, ty = tid >> 4;

    if (EPI == 3 && n0 > m0 + 63) {
        float4 mi = make_float4(-1e30f, -1e30f, -1e30f, -1e30f);
        #pragma unroll
        for (int i = 0; i < 4; i++) {
            long m = m0 + (ty << 2) + i;
            *(float4*)&C[m * (long)ldc + n0 + (tx << 2)] = mi;
        }
        return;
    }

    __shared__ float As[16][68];
    __shared__ float Bs[16][68];

    int lr = tid >> 2;            // 0..63
    int lk = (tid & 3) << 2;      // 0,4,8,12
    int bk = tid >> 4;            // 0..15  (NN)
    int bn = (tid & 15) << 2;     // 0..60  (NN)

    float acc[4][4] = {};

    for (int k0 = 0; k0 < K; k0 += 16) {
        float4 av = *(const float4*)&A[(long)(m0 + lr) * lda + k0 + lk];
        As[lk+0][lr] = av.x; As[lk+1][lr] = av.y; As[lk+2][lr] = av.z; As[lk+3][lr] = av.w;
        if (BT) {
            float4 bv = *(const float4*)&Bm[(long)(n0 + lr) * ldb + k0 + lk];
            Bs[lk+0][lr] = bv.x; Bs[lk+1][lr] = bv.y; Bs[lk+2][lr] = bv.z; Bs[lk+3][lr] = bv.w;
        } else {
            float4 bv = *(const float4*)&Bm[(long)(k0 + bk) * ldb + n0 + bn];
            *(float4*)&Bs[bk][bn] = bv;
        }
        __syncthreads();
        #pragma unroll
        for (int kk = 0; kk < 16; kk++) {
            float4 a = *(const float4*)&As[kk][ty << 2];
            float4 b = *(const float4*)&Bs[kk][tx << 2];
            float ar[4] = {a.x, a.y, a.z, a.w};
            float br[4] = {b.x, b.y, b.z, b.w};
            #pragma unroll
            for (int i = 0; i < 4; i++)
                #pragma unroll
                for (int j = 0; j < 4; j++)
                    acc[i][j] = fmaf(ar[i], br[j], acc[i][j]);
        }
        __syncthreads();
    }

    #pragma unroll
    for (int i = 0; i < 4; i++) {
        long m = m0 + (ty << 2) + i;
        float* cp = &C[m * (long)ldc + n0 + (tx << 2)];
        float4 r;
        if (EPI == 0) {
            r = make_float4(acc[i][0], acc[i][1], acc[i][2], acc[i][3]);
        } else if (EPI == 1) {
            float4 o = *(const float4*)cp;
            r = make_float4(o.x + acc[i][0], o.y + acc[i][1], o.z + acc[i][2], o.w + acc[i][3]);
        } else if (EPI == 2) {
            float r0 = fmaxf(acc[i][0], 0.f), r1 = fmaxf(acc[i][1], 0.f);
            float r2 = fmaxf(acc[i][2], 0.f), r3 = fmaxf(acc[i][3], 0.f);
            r = make_float4(r0*r0, r1*r1, r2*r2, r3*r3);
        } else {
            int n = n0 + (tx << 2);
            r.x = (n + 0 <= m) ? alpha * acc[i][0] : -1e30f;
            r.y = (n + 1 <= m) ? alpha * acc[i][1] : -1e30f;
            r.z = (n + 2 <= m) ? alpha * acc[i][2] : -1e30f;
            r.w = (n + 3 <= m) ? alpha * acc[i][3] : -1e30f;
        }
        *(float4*)cp = r;
    }
}

// ---------------- host orchestration ----------------
extern "C" void kernel_launch(void* const* d_in, const int* in_sizes, int n_in,
                              void* d_out, int out_size)
{
    const int*   seq         = (const int*)  d_in[0];
    const float* embed_w     = (const float*)d_in[1];
    const float* ve_w        = (const float*)d_in[2];
    const float* qkv_w       = (const float*)d_in[3];
    const float* attn_proj_w = (const float*)d_in[4];
    const float* mlp_fc_w    = (const float*)d_in[5];
    const float* mlp_proj_w  = (const float*)d_in[6];
    const float* scalars     = (const float*)d_in[7];

    float *x, *x0, *xn, *skips, *ve, *qkv, *q, *k, *v, *scores, *att, *hbuf;
    cudaGetSymbolAddress((void**)&x,      g_x);
    cudaGetSymbolAddress((void**)&x0,     g_x0);
    cudaGetSymbolAddress((void**)&xn,     g_xn);
    cudaGetSymbolAddress((void**)&skips,  g_skips);
    cudaGetSymbolAddress((void**)&ve,     g_ve);
    cudaGetSymbolAddress((void**)&qkv,    g_qkv);
    cudaGetSymbolAddress((void**)&q,      g_q);
    cudaGetSymbolAddress((void**)&k,      g_k);
    cudaGetSymbolAddress((void**)&v,      g_v);
    cudaGetSymbolAddress((void**)&scores, g_scores);
    cudaGetSymbolAddress((void**)&att,    g_att);
    cudaGetSymbolAddress((void**)&hbuf,   g_hbuf);

    const int NTOK = B_ * T_;   // 4096

    gpt_embed<<<NTOK, 256>>>(seq, embed_w, ve_w, x, x0, ve);

    for (int i = 0; i < L_; i++) {
        const float* skip = (i >= 6) ? (skips + (long)(11 - i) * BTD) : nullptr;
        gpt_residual<<<4096, 256>>>(x, x0, skip, scalars, i);

        if (i != 7) {
            gpt_rmsnorm<<<NTOK, 256>>>(x, xn);
            // qkv = xn @ W_qkv^T : [4096,768] x [2304,768]^T
            gpt_gemm<0, true><<<dim3(36, 64, 1), 256>>>(
                xn, qkv_w + (long)i * 3 * H_ * HD_ * D_, qkv,
                D_, D_, D_, 3*H_*HD_, 0, 0, 1, 0, 0, 1.f);

            const float* vep = nullptr;
            if (i < 3)       vep = ve + (long)i * BTD;
            else if (i >= 9) vep = ve + (long)(i - 9) * BTD;
            gpt_rope<<<B_*T_*H_, 128>>>(qkv, vep, scalars, i, q, k, v);

            // scores = 0.12 * Q K^T (causal): batched over 24 (b,h)
            gpt_gemm<3, true><<<dim3(16, 16, B_*H_), 256>>>(
                q, k, scores,
                HD_, HD_, HD_, T_,
                (long)T_*HD_, (long)T_*HD_, 1, (long)T_*T_, 0, 0.12f);

            gpt_softmax<<<B_*H_*T_, 256>>>(scores);

            // att[b][t][h*128+hd] = P V  : batched NN GEMM
            gpt_gemm<0, false><<<dim3(2, 16, B_*H_), 256>>>(
                scores, v, att,
                T_, T_, HD_, D_,
                (long)T_*T_, (long)T_*HD_, H_, (long)T_*D_, (long)HD_, 1.f);

            // x += att @ W_proj^T
            gpt_gemm<1, true><<<dim3(12, 64, 1), 256>>>(
                att, attn_proj_w + (long)i * D_ * H_ * HD_, x,
                H_*HD_, H_*HD_, H_*HD_, D_, 0, 0, 1, 0, 0, 1.f);
        }

        gpt_rmsnorm<<<NTOK, 256>>>(x, xn);
        // h = relu(xn @ W_fc^T)^2 : [4096,768] x [3072,768]^T
        gpt_gemm<2, true><<<dim3(48, 64, 1), 256>>>(
            xn, mlp_fc_w + (long)i * 4 * D_ * D_, hbuf,
            D_, D_, D_, 4*D_, 0, 0, 1, 0, 0, 1.f);
        // x += h @ W_proj^T : [4096,3072] x [768,3072]^T
        gpt_gemm<1, true><<<dim3(12, 64, 1), 256>>>(
            hbuf, mlp_proj_w + (long)i * D_ * 4 * D_, x,
            4*D_, 4*D_, 4*D_, D_, 0, 0, 1, 0, 0, 1.f);

        if (i < 6) gpt_copy<<<4096, 256>>>(skips + (long)i * BTD, x);
    }

    gpt_finalnorm<<<NTOK, 256>>>(x, (float*)d_out);
}

// round 2
// speedup vs baseline: 1.7450x; 1.7450x over previous
#include <cuda_runtime.h>
#include <math.h>
#include <stdint.h>

#define B_  4
#define T_  1024
#define D_  768
#define H_  6
#define HD_ 128
#define L_  12
#define BTD (B_*T_*D_)          // 3145728
#define EPSF 1.1920929e-07f

// ---------------- scratch (device globals; no allocation allowed) ----------------
__device__ float g_x   [BTD];
__device__ float g_x0  [BTD];
__device__ float g_xn  [BTD];
__device__ float g_skips[6*BTD];
__device__ float g_ve  [3*BTD];
__device__ float g_qkv [B_*T_*3*H_*HD_];      // [bt][which*768 + h*128 + hd]
__device__ float g_q   [B_*H_*T_*HD_];        // [b][h][t][hd]
__device__ float g_k   [B_*H_*T_*HD_];
__device__ float g_v   [B_*H_*T_*HD_];
__device__ float g_scores[B_*H_*T_*T_];       // [b][h][t][s]
__device__ float g_att [BTD];                 // [b][t][h*128+hd]
__device__ float g_hbuf[B_*T_*4*D_];          // [bt][3072]

// ---------------- helpers ----------------
__device__ __forceinline__ float blockReduceSum256(float v, float* red) {
    int tid = threadIdx.x;
    red[tid] = v; __syncthreads();
    for (int s = 128; s > 0; s >>= 1) {
        if (tid < s) red[tid] += red[tid + s];
        __syncthreads();
    }
    float r = red[0]; __syncthreads();
    return r;
}

__device__ __forceinline__ uint32_t f2tf32(float f) {
    uint32_t u;
    asm("cvt.rna.tf32.f32 %0, %1;" : "=r"(u) : "f"(f));
    return u;
}

__device__ __forceinline__ void mma8(float* c, const uint4& a, const uint2& b) {
    asm volatile(
        "mma.sync.aligned.m16n8k8.row.col.f32.tf32.tf32.f32 "
        "{%0,%1,%2,%3}, {%4,%5,%6,%7}, {%8,%9}, {%0,%1,%2,%3};"
        : "+f"(c[0]), "+f"(c[1]), "+f"(c[2]), "+f"(c[3])
        : "r"(a.x), "r"(a.y), "r"(a.z), "r"(a.w), "r"(b.x), "r"(b.y));
}

// ---------------- embedding + norm + ve gather ----------------
__global__ __launch_bounds__(256)
void gpt_embed(const int* __restrict__ seq, const float* __restrict__ ew,
               const float* __restrict__ vew,
               float* __restrict__ x, float* __restrict__ x0, float* __restrict__ ve)
{
    __shared__ float red[256];
    int bt = blockIdx.x;
    int tid = threadIdx.x;
    int idx = seq[bt];
    const float* er = ew + (long)idx * D_;
    float a0 = er[tid], a1 = er[tid + 256], a2 = er[tid + 512];
    float ss = blockReduceSum256(a0*a0 + a1*a1 + a2*a2, red);
    float r = rsqrtf(ss / (float)D_ + EPSF);
    long o = (long)bt * D_;
    x0[o + tid]       = a0 * r;  x[o + tid]       = a0 * r;
    x0[o + tid + 256] = a1 * r;  x[o + tid + 256] = a1 * r;
    x0[o + tid + 512] = a2 * r;  x[o + tid + 512] = a2 * r;
    #pragma unroll
    for (int j = 0; j < 3; j++) {
        const float* vr = vew + ((long)j * 50257 + idx) * D_;
        float* vo = ve + ((long)j * (B_*T_) + bt) * D_;
        for (int d = tid; d < D_; d += 256) vo[d] = vr[d];
    }
}

// ---------------- rms norm (row = 768) ----------------
__global__ __launch_bounds__(256)
void gpt_rmsnorm(const float* __restrict__ x, float* __restrict__ y)
{
    __shared__ float red[256];
    int tid = threadIdx.x;
    const float* xr = x + (long)blockIdx.x * D_;
    float a0 = xr[tid], a1 = xr[tid + 256], a2 = xr[tid + 512];
    float ss = blockReduceSum256(a0*a0 + a1*a1 + a2*a2, red);
    float r = rsqrtf(ss / (float)D_ + EPSF);
    float* yr = y + (long)blockIdx.x * D_;
    yr[tid] = a0 * r; yr[tid + 256] = a1 * r; yr[tid + 512] = a2 * r;
}

// ---------------- residual combine: x = l0*(x + sw*skip) + l1*x0 ----------------
__global__ __launch_bounds__(256)
void gpt_residual(float* __restrict__ x, const float* __restrict__ x0,
                  const float* __restrict__ skip, const float* __restrict__ scalars, int layer)
{
    float l0 = scalars[L_ + 2*layer];
    float l1 = scalars[L_ + 2*layer + 1];
    float sw = skip ? scalars[layer - 6] : 0.f;
    long n = (long)BTD;
    for (long i = (long)blockIdx.x * 256 + threadIdx.x; i < n; i += (long)gridDim.x * 256) {
        float v = x[i];
        if (skip) v += sw * skip[i];
        x[i] = l0 * v + l1 * x0[i];
    }
}

__global__ __launch_bounds__(256)
void gpt_copy(float* __restrict__ dst, const float* __restrict__ src)
{
    long n = (long)BTD;
    for (long i = (long)blockIdx.x * 256 + threadIdx.x; i < n; i += (long)gridDim.x * 256)
        dst[i] = src[i];
}

// ---------------- qk norm + rope + v mix; repack to [b][h][t][hd] ----------------
__global__ __launch_bounds__(128)
void gpt_rope(const float* __restrict__ qkv, const float* __restrict__ ve,
              const float* __restrict__ scalars, int layer,
              float* __restrict__ q, float* __restrict__ k, float* __restrict__ v)
{
    __shared__ float rq[128], rk[128], sq[128], sk[128];
    int z = blockIdx.x;
    int hd = threadIdx.x;
    int h = z % H_;
    int t = (z / H_) % T_;
    int b = z / (H_ * T_);
    long bt = (long)b * T_ + t;
    const float* base = qkv + bt * (3*H_*HD_) + h * HD_;
    float qv = base[hd], kv = base[H_*HD_ + hd], vv = base[2*H_*HD_ + hd];

    rq[hd] = qv * qv; rk[hd] = kv * kv;
    __syncthreads();
    for (int s = 64; s > 0; s >>= 1) {
        if (hd < s) { rq[hd] += rq[hd + s]; rk[hd] += rk[hd + s]; }
        __syncthreads();
    }
    float rnq = rsqrtf(rq[0] / (float)HD_ + EPSF);
    float rnk = rsqrtf(rk[0] / (float)HD_ + EPSF);
    __syncthreads();
    sq[hd] = qv * rnq; sk[hd] = kv * rnk;
    __syncthreads();

    int j = hd & 63;
    float freq = (j < 32) ? exp2f(-10.0f * (float)j / 31.0f) : 0.0f;
    float sn, cs;
    sincosf((float)t * freq, &sn, &cs);
    float oq, ok;
    if (hd < 64) { oq =  sq[hd] * cs + sq[hd + 64] * sn;  ok =  sk[hd] * cs + sk[hd + 64] * sn; }
    else         { oq = -sq[hd - 64] * sn + sq[hd] * cs;  ok = -sk[hd - 64] * sn + sk[hd] * cs; }

    long o = (((long)b * H_ + h) * T_ + t) * HD_ + hd;
    q[o] = oq; k[o] = ok;

    float sa0 = scalars[3*L_ + 2*layer];
    float sa1 = scalars[3*L_ + 2*layer + 1];
    float vo = sa0 * vv;
    if (ve) vo += sa1 * ve[bt * D_ + h * HD_ + hd];
    v[o] = vo;
}

// ---------------- softmax over row of 1024 ----------------
__global__ __launch_bounds__(256)
void gpt_softmax(float* __restrict__ S)
{
    __shared__ float red[256];
    int tid = threadIdx.x;
    float* p = S + (long)blockIdx.x * T_;
    float v[4];
    float mx = -3.4e38f;
    #pragma unroll
    for (int j = 0; j < 4; j++) { v[j] = p[tid + j*256]; mx = fmaxf(mx, v[j]); }
    red[tid] = mx; __syncthreads();
    for (int s = 128; s > 0; s >>= 1) { if (tid < s) red[tid] = fmaxf(red[tid], red[tid+s]); __syncthreads(); }
    float m = red[0]; __syncthreads();
    float sum = 0.f;
    #pragma unroll
    for (int j = 0; j < 4; j++) { v[j] = expf(v[j] - m); sum += v[j]; }
    float tot = blockReduceSum256(sum, red);
    float inv = 1.0f / tot;
    #pragma unroll
    for (int j = 0; j < 4; j++) p[tid + j*256] = v[j] * inv;
}

// =================================================================================
// tf32 tensor-core GEMM: 128x128 block tile, BK=16, 8 warps, warp tile 64x32
// EPI: 0=store, 1=accumulate into C, 2=relu^2 store, 3=causal scores (alpha, -1e30)
// BT:  true -> C = A * B^T (B is [N][K]) ;  false -> C = A * B (B is [K][N])
// ktri: if 1, limit K to m0+128 (P upper triangle is zero)
// =================================================================================
#define BM 128
#define BN 128
#define BK 16

template<int EPI, bool BT>
__global__ __launch_bounds__(256)
void gpt_gemm(const float* __restrict__ A, const float* __restrict__ Bm, float* __restrict__ C,
              int K, int lda, int ldb, int ldc,
              long aZ, long bZ, int zdiv, long c1, long c2, float alpha, int ktri)
{
    int z = blockIdx.z;
    A  += (long)z * aZ;
    Bm += (long)z * bZ;
    C  += (long)(z / zdiv) * c1 + (long)(z % zdiv) * c2;

    const int m0 = blockIdx.y * BM, n0 = blockIdx.x * BN;
    const int tid  = threadIdx.x;
    const int lane = tid & 31, warp = tid >> 5;
    const int wm = warp >> 2, wn = warp & 3;         // 2 x 4 warp grid
    const int gid = lane >> 2, tig = lane & 3;

    if (EPI == 3 && n0 > m0) {
        // fully above diagonal: all masked
        float2 mi2 = make_float2(-1e30f, -1e30f);
        #pragma unroll
        for (int mi = 0; mi < 4; mi++) {
            int row = m0 + wm*64 + mi*16 + gid;
            #pragma unroll
            for (int ni = 0; ni < 4; ni++) {
                int col = n0 + wn*32 + ni*8 + tig*2;
                *(float2*)&C[(long)row * ldc + col]       = mi2;
                *(float2*)&C[(long)(row + 8) * ldc + col] = mi2;
            }
        }
        return;
    }

    // fragment-permuted smem: A frag = 1 x LDS.128, B frag = 1 x LDS.64
    __shared__ uint32_t As[2][2048];   // [mi(8) x ks(2)][lane(32)][slot(4)]
    __shared__ uint32_t Bs[2][2048];   // [ni(16) x ks(2)][lane(32)][slot(2)]

    int keff = K;
    if (ktri) { int kk = m0 + BM; keff = kk < K ? kk : K; }
    const int NT = keff / BK;

    float acc[4][4][4];
    #pragma unroll
    for (int a = 0; a < 4; a++)
        #pragma unroll
        for (int b = 0; b < 4; b++)
            #pragma unroll
            for (int c = 0; c < 4; c++) acc[a][b][c] = 0.f;

    float4 pa[2], pb[2];

    // ---- staging helpers ----
    auto loadA = [&](int k0) {
        #pragma unroll
        for (int t = 0; t < 2; t++) {
            int i = tid + t * 256;
            int r = i >> 2, c = (i & 3) << 2;
            pa[t] = *(const float4*)&A[(long)(m0 + r) * lda + k0 + c];
        }
    };
    auto loadB = [&](int k0) {
        #pragma unroll
        for (int t = 0; t < 2; t++) {
            int i = tid + t * 256;
            if (BT) {
                int n = i >> 2, c = (i & 3) << 2;
                pb[t] = *(const float4*)&Bm[(long)(n0 + n) * ldb + k0 + c];
            } else {
                int k = i >> 5, n = (i & 31) << 2;
                pb[t] = *(const float4*)&Bm[(long)(k0 + k) * ldb + n0 + n];
            }
        }
    };
    auto storeA = [&](int buf) {
        #pragma unroll
        for (int t = 0; t < 2; t++) {
            int i = tid + t * 256;
            int r = i >> 2, cb = (i & 3) << 2;
            float v[4] = {pa[t].x, pa[t].y, pa[t].z, pa[t].w};
            #pragma unroll
            for (int j = 0; j < 4; j++) {
                int c = cb + j;
                int mi = r >> 4, ks = c >> 3;
                int ln = ((r & 7) << 2) | (c & 3);
                int slot = ((r >> 3) & 1) | (((c >> 2) & 1) << 1);
                As[buf][(((mi << 1) | ks) << 7) + (ln << 2) + slot] = f2tf32(v[j]);
            }
        }
    };
    auto storeB = [&](int buf) {
        #pragma unroll
        for (int t = 0; t < 2; t++) {
            int i = tid + t * 256;
            float v[4] = {pb[t].x, pb[t].y, pb[t].z, pb[t].w};
            #pragma unroll
            for (int j = 0; j < 4; j++) {
                int n, k;
                if (BT) { n = i >> 2; k = ((i & 3) << 2) + j; }
                else    { k = i >> 5; n = ((i & 31) << 2) + j; }
                int ni = n >> 3, ks = k >> 3;
                int ln = ((n & 7) << 2) | (k & 3);
                int slot = (k >> 2) & 1;
                Bs[buf][(((ni << 1) | ks) << 6) + (ln << 1) + slot] = f2tf32(v[j]);
            }
        }
    };

    loadA(0); loadB(0);
    storeA(0); storeB(0);
    __syncthreads();

    for (int kt = 0; kt < NT; kt++) {
        int cur = kt & 1;
        if (kt + 1 < NT) { loadA((kt + 1) * BK); loadB((kt + 1) * BK); }

        const uint4* As4 = (const uint4*)As[cur];
        const uint2* Bs2 = (const uint2*)Bs[cur];
        #pragma unroll
        for (int ks = 0; ks < 2; ks++) {
            uint4 af[4]; uint2 bf[4];
            #pragma unroll
            for (int mi = 0; mi < 4; mi++)
                af[mi] = As4[(((wm*4 + mi) << 1) | ks) * 32 + lane];
            #pragma unroll
            for (int ni = 0; ni < 4; ni++)
                bf[ni] = Bs2[(((wn*4 + ni) << 1) | ks) * 32 + lane];
            #pragma unroll
            for (int mi = 0; mi < 4; mi++)
                #pragma unroll
                for (int ni = 0; ni < 4; ni++)
                    mma8(acc[mi][ni], af[mi], bf[ni]);
        }

        if (kt + 1 < NT) {
            storeA(1 - cur); storeB(1 - cur);
            __syncthreads();
        }
    }

    // ---- epilogue ----
    #pragma unroll
    for (int mi = 0; mi < 4; mi++) {
        int row = m0 + wm*64 + mi*16 + gid;
        #pragma unroll
        for (int ni = 0; ni < 4; ni++) {
            int col = n0 + wn*32 + ni*8 + tig*2;
            float* a4 = acc[mi][ni];
            #pragma unroll
            for (int half = 0; half < 2; half++) {
                int r = row + half * 8;
                float c0 = a4[half*2 + 0], c1 = a4[half*2 + 1];
                float* cp = &C[(long)r * ldc + col];
                float2 out;
                if (EPI == 0) {
                    out = make_float2(c0, c1);
                } else if (EPI == 1) {
                    float2 o = *(float2*)cp;
                    out = make_float2(o.x + c0, o.y + c1);
                } else if (EPI == 2) {
                    float r0 = fmaxf(c0, 0.f), r1 = fmaxf(c1, 0.f);
                    out = make_float2(r0*r0, r1*r1);
                } else {
                    out.x = (col + 0 <= r) ? alpha * c0 : -1e30f;
                    out.y = (col + 1 <= r) ? alpha * c1 : -1e30f;
                }
                *(float2*)cp = out;
            }
        }
    }
}

// ---------------- final norm -> output ----------------
__global__ __launch_bounds__(256)
void gpt_finalnorm(const float* __restrict__ x, float* __restrict__ out)
{
    __shared__ float red[256];
    int tid = threadIdx.x;
    const float* xr = x + (long)blockIdx.x * D_;
    float a0 = xr[tid], a1 = xr[tid + 256], a2 = xr[tid + 512];
    float ss = blockReduceSum256(a0*a0 + a1*a1 + a2*a2, red);
    float r = rsqrtf(ss / (float)D_ + EPSF);
    float* yr = out + (long)blockIdx.x * D_;
    yr[tid] = a0 * r; yr[tid + 256] = a1 * r; yr[tid + 512] = a2 * r;
}

// ---------------- host orchestration ----------------
extern "C" void kernel_launch(void* const* d_in, const int* in_sizes, int n_in,
                              void* d_out, int out_size)
{
    const int*   seq         = (const int*)  d_in[0];
    const float* embed_w     = (const float*)d_in[1];
    const float* ve_w        = (const float*)d_in[2];
    const float* qkv_w       = (const float*)d_in[3];
    const float* attn_proj_w = (const float*)d_in[4];
    const float* mlp_fc_w    = (const float*)d_in[5];
    const float* mlp_proj_w  = (const float*)d_in[6];
    const float* scalars     = (const float*)d_in[7];

    float *x, *x0, *xn, *skips, *ve, *qkv, *q, *k, *v, *scores, *att, *hbuf;
    cudaGetSymbolAddress((void**)&x,      g_x);
    cudaGetSymbolAddress((void**)&x0,     g_x0);
    cudaGetSymbolAddress((void**)&xn,     g_xn);
    cudaGetSymbolAddress((void**)&skips,  g_skips);
    cudaGetSymbolAddress((void**)&ve,     g_ve);
    cudaGetSymbolAddress((void**)&qkv,    g_qkv);
    cudaGetSymbolAddress((void**)&q,      g_q);
    cudaGetSymbolAddress((void**)&k,      g_k);
    cudaGetSymbolAddress((void**)&v,      g_v);
    cudaGetSymbolAddress((void**)&scores, g_scores);
    cudaGetSymbolAddress((void**)&att,    g_att);
    cudaGetSymbolAddress((void**)&hbuf,   g_hbuf);

    const int NTOK = B_ * T_;   // 4096

    gpt_embed<<<NTOK, 256>>>(seq, embed_w, ve_w, x, x0, ve);

    for (int i = 0; i < L_; i++) {
        const float* skip = (i >= 6) ? (skips + (long)(11 - i) * BTD) : nullptr;
        gpt_residual<<<4096, 256>>>(x, x0, skip, scalars, i);

        if (i != 7) {
            gpt_rmsnorm<<<NTOK, 256>>>(x, xn);
            // qkv = xn @ W_qkv^T : [4096,768] x [2304,768]^T
            gpt_gemm<0, true><<<dim3(18, 32, 1), 256>>>(
                xn, qkv_w + (long)i * 3 * H_ * HD_ * D_, qkv,
                D_, D_, D_, 3*H_*HD_, 0, 0, 1, 0, 0, 1.f, 0);

            const float* vep = nullptr;
            if (i < 3)       vep = ve + (long)i * BTD;
            else if (i >= 9) vep = ve + (long)(i - 9) * BTD;
            gpt_rope<<<B_*T_*H_, 128>>>(qkv, vep, scalars, i, q, k, v);

            // scores = 0.12 * Q K^T (causal): batched over 24 (b,h)
            gpt_gemm<3, true><<<dim3(8, 8, B_*H_), 256>>>(
                q, k, scores,
                HD_, HD_, HD_, T_,
                (long)T_*HD_, (long)T_*HD_, 1, (long)T_*T_, 0, 0.12f, 0);

            gpt_softmax<<<B_*H_*T_, 256>>>(scores);

            // att[b][t][h*128+hd] = P V : batched NN GEMM, triangular K limit
            gpt_gemm<0, false><<<dim3(1, 8, B_*H_), 256>>>(
                scores, v, att,
                T_, T_, HD_, D_,
                (long)T_*T_, (long)T_*HD_, H_, (long)T_*D_, (long)HD_, 1.f, 1);

            // x += att @ W_proj^T
            gpt_gemm<1, true><<<dim3(6, 32, 1), 256>>>(
                att, attn_proj_w + (long)i * D_ * H_ * HD_, x,
                H_*HD_, H_*HD_, H_*HD_, D_, 0, 0, 1, 0, 0, 1.f, 0);
        }

        gpt_rmsnorm<<<NTOK, 256>>>(x, xn);
        // h = relu(xn @ W_fc^T)^2 : [4096,768] x [3072,768]^T
        gpt_gemm<2, true><<<dim3(24, 32, 1), 256>>>(
            xn, mlp_fc_w + (long)i * 4 * D_ * D_, hbuf,
            D_, D_, D_, 4*D_, 0, 0, 1, 0, 0, 1.f, 0);
        // x += h @ W_proj^T : [4096,3072] x [768,3072]^T
        gpt_gemm<1, true><<<dim3(6, 32, 1), 256>>>(
            hbuf, mlp_proj_w + (long)i * D_ * 4 * D_, x,
            4*D_, 4*D_, 4*D_, D_, 0, 0, 1, 0, 0, 1.f, 0);

        if (i < 6) gpt_copy<<<4096, 256>>>(skips + (long)i * BTD, x);
    }

    gpt_finalnorm<<<NTOK, 256>>>(x, (float*)d_out);
}

// round 3
// speedup vs baseline: 2.5157x; 1.4416x over previous
#include <cuda_runtime.h>
#include <math.h>
#include <stdint.h>

#define B_  4
#define T_  1024
#define D_  768
#define H_  6
#define HD_ 128
#define L_  12
#define BTD (B_*T_*D_)          // 3145728
#define EPSF 1.1920929e-07f

// ---------------- scratch (device globals; no allocation allowed) ----------------
__device__ float g_x   [BTD];
__device__ float g_x0  [BTD];
__device__ float g_xn  [BTD];
__device__ float g_skips[6*BTD];
__device__ float g_ve  [3*BTD];
__device__ float g_qkv [B_*T_*3*H_*HD_];      // [bt][which*768 + h*128 + hd]
__device__ float g_q   [B_*H_*T_*HD_];        // [b][h][t][hd]
__device__ float g_k   [B_*H_*T_*HD_];
__device__ float g_vt  [B_*H_*HD_*T_];        // [b][h][hd][t]  (transposed V)
__device__ float g_scores[B_*H_*T_*T_];       // [b][h][t][s]
__device__ float g_att [BTD];                 // [b][t][h*128+hd]
__device__ float g_hbuf[B_*T_*4*D_];          // [bt][3072]

// ---------------- helpers ----------------
__device__ __forceinline__ float blockReduceSum256(float v, float* red) {
    int tid = threadIdx.x;
    red[tid] = v; __syncthreads();
    for (int s = 128; s > 0; s >>= 1) {
        if (tid < s) red[tid] += red[tid + s];
        __syncthreads();
    }
    float r = red[0]; __syncthreads();
    return r;
}

__device__ __forceinline__ uint32_t f2tf32(float f) {
    uint32_t u;
    asm("cvt.rna.tf32.f32 %0, %1;" : "=r"(u) : "f"(f));
    return u;
}

__device__ __forceinline__ void mma8(float* c, const uint32_t* a, const uint32_t* b) {
    asm volatile(
        "mma.sync.aligned.m16n8k8.row.col.f32.tf32.tf32.f32 "
        "{%0,%1,%2,%3}, {%4,%5,%6,%7}, {%8,%9}, {%0,%1,%2,%3};"
        : "+f"(c[0]), "+f"(c[1]), "+f"(c[2]), "+f"(c[3])
        : "r"(a[0]), "r"(a[1]), "r"(a[2]), "r"(a[3]), "r"(b[0]), "r"(b[1]));
}

// swizzle: column-group permutation within a 16-word row
__device__ __forceinline__ int swz(int r, int cg) { return cg ^ ((r >> 1) & 3); }

// ---------------- embedding + norm + ve gather ----------------
__global__ __launch_bounds__(256)
void gpt_embed(const int* __restrict__ seq, const float* __restrict__ ew,
               const float* __restrict__ vew,
               float* __restrict__ x, float* __restrict__ x0, float* __restrict__ ve)
{
    __shared__ float red[256];
    int bt = blockIdx.x;
    int tid = threadIdx.x;
    int idx = seq[bt];
    const float* er = ew + (long)idx * D_;
    float a0 = er[tid], a1 = er[tid + 256], a2 = er[tid + 512];
    float ss = blockReduceSum256(a0*a0 + a1*a1 + a2*a2, red);
    float r = rsqrtf(ss / (float)D_ + EPSF);
    long o = (long)bt * D_;
    x0[o + tid]       = a0 * r;  x[o + tid]       = a0 * r;
    x0[o + tid + 256] = a1 * r;  x[o + tid + 256] = a1 * r;
    x0[o + tid + 512] = a2 * r;  x[o + tid + 512] = a2 * r;
    #pragma unroll
    for (int j = 0; j < 3; j++) {
        const float* vr = vew + ((long)j * 50257 + idx) * D_;
        float* vo = ve + ((long)j * (B_*T_) + bt) * D_;
        for (int d = tid; d < D_; d += 256) vo[d] = vr[d];
    }
}

// ---------------- rms norm (row = 768) ----------------
__global__ __launch_bounds__(256)
void gpt_rmsnorm(const float* __restrict__ x, float* __restrict__ y)
{
    __shared__ float red[256];
    int tid = threadIdx.x;
    const float* xr = x + (long)blockIdx.x * D_;
    float a0 = xr[tid], a1 = xr[tid + 256], a2 = xr[tid + 512];
    float ss = blockReduceSum256(a0*a0 + a1*a1 + a2*a2, red);
    float r = rsqrtf(ss / (float)D_ + EPSF);
    float* yr = y + (long)blockIdx.x * D_;
    yr[tid] = a0 * r; yr[tid + 256] = a1 * r; yr[tid + 512] = a2 * r;
}

// ---------------- residual combine: x = l0*(x + sw*skip) + l1*x0 ----------------
__global__ __launch_bounds__(256)
void gpt_residual(float* __restrict__ x, const float* __restrict__ x0,
                  const float* __restrict__ skip, const float* __restrict__ scalars, int layer)
{
    float l0 = scalars[L_ + 2*layer];
    float l1 = scalars[L_ + 2*layer + 1];
    float sw = skip ? scalars[layer - 6] : 0.f;
    long n = (long)BTD;
    for (long i = (long)blockIdx.x * 256 + threadIdx.x; i < n; i += (long)gridDim.x * 256) {
        float v = x[i];
        if (skip) v += sw * skip[i];
        x[i] = l0 * v + l1 * x0[i];
    }
}

__global__ __launch_bounds__(256)
void gpt_copy(float* __restrict__ dst, const float* __restrict__ src)
{
    long n = (long)BTD;
    for (long i = (long)blockIdx.x * 256 + threadIdx.x; i < n; i += (long)gridDim.x * 256)
        dst[i] = src[i];
}

// ---------------- qk norm + rope + v mix; q,k -> [b][h][t][hd], v -> [b][h][hd][t]
__global__ __launch_bounds__(128)
void gpt_rope(const float* __restrict__ qkv, const float* __restrict__ ve,
              const float* __restrict__ scalars, int layer,
              float* __restrict__ q, float* __restrict__ k, float* __restrict__ vt)
{
    __shared__ float rq[128], rk[128], sq[128], sk[128];
    int z = blockIdx.x;
    int hd = threadIdx.x;
    int h = z % H_;
    int t = (z / H_) % T_;
    int b = z / (H_ * T_);
    long bt = (long)b * T_ + t;
    const float* base = qkv + bt * (3*H_*HD_) + h * HD_;
    float qv = base[hd], kv = base[H_*HD_ + hd], vv = base[2*H_*HD_ + hd];

    rq[hd] = qv * qv; rk[hd] = kv * kv;
    __syncthreads();
    for (int s = 64; s > 0; s >>= 1) {
        if (hd < s) { rq[hd] += rq[hd + s]; rk[hd] += rk[hd + s]; }
        __syncthreads();
    }
    float rnq = rsqrtf(rq[0] / (float)HD_ + EPSF);
    float rnk = rsqrtf(rk[0] / (float)HD_ + EPSF);
    __syncthreads();
    sq[hd] = qv * rnq; sk[hd] = kv * rnk;
    __syncthreads();

    int j = hd & 63;
    float freq = (j < 32) ? exp2f(-10.0f * (float)j / 31.0f) : 0.0f;
    float sn, cs;
    sincosf((float)t * freq, &sn, &cs);
    float oq, ok;
    if (hd < 64) { oq =  sq[hd] * cs + sq[hd + 64] * sn;  ok =  sk[hd] * cs + sk[hd + 64] * sn; }
    else         { oq = -sq[hd - 64] * sn + sq[hd] * cs;  ok = -sk[hd - 64] * sn + sk[hd] * cs; }

    long o = (((long)b * H_ + h) * T_ + t) * HD_ + hd;
    q[o] = oq; k[o] = ok;

    float sa0 = scalars[3*L_ + 2*layer];
    float sa1 = scalars[3*L_ + 2*layer + 1];
    float vo = sa0 * vv;
    if (ve) vo += sa1 * ve[bt * D_ + h * HD_ + hd];
    vt[(((long)b * H_ + h) * HD_ + hd) * T_ + t] = vo;
}

// ---------------- softmax over row of 1024 ----------------
__global__ __launch_bounds__(256)
void gpt_softmax(float* __restrict__ S)
{
    __shared__ float red[256];
    int tid = threadIdx.x;
    float* p = S + (long)blockIdx.x * T_;
    float v[4];
    float mx = -3.4e38f;
    #pragma unroll
    for (int j = 0; j < 4; j++) { v[j] = p[tid + j*256]; mx = fmaxf(mx, v[j]); }
    red[tid] = mx; __syncthreads();
    for (int s = 128; s > 0; s >>= 1) { if (tid < s) red[tid] = fmaxf(red[tid], red[tid+s]); __syncthreads(); }
    float m = red[0]; __syncthreads();
    float sum = 0.f;
    #pragma unroll
    for (int j = 0; j < 4; j++) { v[j] = expf(v[j] - m); sum += v[j]; }
    float tot = blockReduceSum256(sum, red);
    float inv = 1.0f / tot;
    #pragma unroll
    for (int j = 0; j < 4; j++) p[tid + j*256] = v[j] * inv;
}

// =================================================================================
// tf32 tensor-core GEMM: 256x128 block tile, BK=16, 8 warps, warp tile 64x64
// C[m][n] = sum_k A[m][k] * B[n][k]   (both operands k-major rows)
// EPI: 0=store, 1=accumulate into C, 2=relu^2 store, 3=causal scores (alpha, -1e30)
// ktri: if 1, limit K to m0+256 (P upper triangle is zero)
// =================================================================================
#define BM 256
#define BN 128
#define BK 16

template<int EPI>
__global__ __launch_bounds__(256)
void gpt_gemm(const float* __restrict__ A, const float* __restrict__ Bm, float* __restrict__ C,
              int K, int lda, int ldb, int ldc,
              long aZ, long bZ, int zdiv, long c1, long c2, float alpha, int ktri)
{
    int z = blockIdx.z;
    A  += (long)z * aZ;
    Bm += (long)z * bZ;
    C  += (long)(z / zdiv) * c1 + (long)(z % zdiv) * c2;

    const int m0 = blockIdx.y * BM, n0 = blockIdx.x * BN;
    const int tid  = threadIdx.x;
    const int lane = tid & 31, warp = tid >> 5;
    const int wm = warp >> 1, wn = warp & 1;        // 4 x 2 warp grid
    const int g = lane >> 2, t = lane & 3;

    if (EPI == 3 && n0 > m0 + (BM - 1)) {
        float2 mi2 = make_float2(-1e30f, -1e30f);
        #pragma unroll
        for (int mi = 0; mi < 4; mi++) {
            int row = m0 + wm*64 + mi*16 + g;
            #pragma unroll
            for (int ni = 0; ni < 8; ni++) {
                int col = n0 + wn*64 + ni*8 + t*2;
                *(float2*)&C[(long)row * ldc + col]       = mi2;
                *(float2*)&C[(long)(row + 8) * ldc + col] = mi2;
            }
        }
        return;
    }

    __shared__ uint32_t As[2][BM*16];   // 32 KB
    __shared__ uint32_t Bs[2][BN*16];   // 16 KB

    int keff = K;
    if (ktri) { int kk = m0 + BM; keff = kk < K ? kk : K; }
    const int NT = keff / BK;

    float acc[4][8][4];
    #pragma unroll
    for (int a = 0; a < 4; a++)
        #pragma unroll
        for (int b = 0; b < 8; b++)
            #pragma unroll
            for (int c = 0; c < 4; c++) acc[a][b][c] = 0.f;

    const int ar  = tid >> 2;       // 0..63
    const int acg = tid & 3;        // col-group 0..3

    float4 pa[4], pb[2];

    auto loadA = [&](int k0) {
        #pragma unroll
        for (int j = 0; j < 4; j++)
            pa[j] = *(const float4*)&A[(long)(m0 + ar + 64*j) * lda + k0 + acg*4];
    };
    auto loadB = [&](int k0) {
        #pragma unroll
        for (int j = 0; j < 2; j++)
            pb[j] = *(const float4*)&Bm[(long)(n0 + ar + 64*j) * ldb + k0 + acg*4];
    };
    auto storeA = [&](int buf) {
        #pragma unroll
        for (int j = 0; j < 4; j++) {
            int r = ar + 64*j;
            uint4 w;
            w.x = f2tf32(pa[j].x); w.y = f2tf32(pa[j].y);
            w.z = f2tf32(pa[j].z); w.w = f2tf32(pa[j].w);
            *(uint4*)&As[buf][r*16 + swz(r, acg)*4] = w;
        }
    };
    auto storeB = [&](int buf) {
        #pragma unroll
        for (int j = 0; j < 2; j++) {
            int r = ar + 64*j;
            uint4 w;
            w.x = f2tf32(pb[j].x); w.y = f2tf32(pb[j].y);
            w.z = f2tf32(pb[j].z); w.w = f2tf32(pb[j].w);
            *(uint4*)&Bs[buf][r*16 + swz(r, acg)*4] = w;
        }
    };

    loadA(0); loadB(0);
    storeA(0); storeB(0);
    __syncthreads();

    for (int kt = 0; kt < NT; kt++) {
        int cur = kt & 1;
        if (kt + 1 < NT) { loadA((kt + 1) * BK); loadB((kt + 1) * BK); }

        const uint32_t* Ab = As[cur];
        const uint32_t* Bb = Bs[cur];
        #pragma unroll
        for (int ks = 0; ks < 2; ks++) {
            uint32_t af[4][4];
            #pragma unroll
            for (int mi = 0; mi < 4; mi++) {
                int r0 = wm*64 + mi*16 + g;
                int s0 = swz(r0, ks*2)*4 + t;
                int s1 = swz(r0, ks*2 + 1)*4 + t;
                af[mi][0] = Ab[r0*16 + s0];
                af[mi][1] = Ab[(r0+8)*16 + s0];
                af[mi][2] = Ab[r0*16 + s1];
                af[mi][3] = Ab[(r0+8)*16 + s1];
            }
            uint32_t bf[8][2];
            #pragma unroll
            for (int ni = 0; ni < 8; ni++) {
                int nr = wn*64 + ni*8 + g;
                bf[ni][0] = Bb[nr*16 + swz(nr, ks*2)*4 + t];
                bf[ni][1] = Bb[nr*16 + swz(nr, ks*2 + 1)*4 + t];
            }
            #pragma unroll
            for (int mi = 0; mi < 4; mi++)
                #pragma unroll
                for (int ni = 0; ni < 8; ni++)
                    mma8(acc[mi][ni], af[mi], bf[ni]);
        }

        if (kt + 1 < NT) {
            storeA(1 - cur); storeB(1 - cur);
            __syncthreads();
        }
    }

    // ---- epilogue ----
    #pragma unroll
    for (int mi = 0; mi < 4; mi++) {
        int row = m0 + wm*64 + mi*16 + g;
        #pragma unroll
        for (int ni = 0; ni < 8; ni++) {
            int col = n0 + wn*64 + ni*8 + t*2;
            float* a4 = acc[mi][ni];
            #pragma unroll
            for (int half = 0; half < 2; half++) {
                int r = row + half * 8;
                float c0 = a4[half*2 + 0], c1 = a4[half*2 + 1];
                float* cp = &C[(long)r * ldc + col];
                float2 out;
                if (EPI == 0) {
                    out = make_float2(c0, c1);
                } else if (EPI == 1) {
                    float2 o = *(float2*)cp;
                    out = make_float2(o.x + c0, o.y + c1);
                } else if (EPI == 2) {
                    float r0 = fmaxf(c0, 0.f), r1 = fmaxf(c1, 0.f);
                    out = make_float2(r0*r0, r1*r1);
                } else {
                    out.x = (col + 0 <= r) ? alpha * c0 : -1e30f;
                    out.y = (col + 1 <= r) ? alpha * c1 : -1e30f;
                }
                *(float2*)cp = out;
            }
        }
    }
}

// ---------------- final norm -> output ----------------
__global__ __launch_bounds__(256)
void gpt_finalnorm(const float* __restrict__ x, float* __restrict__ out)
{
    __shared__ float red[256];
    int tid = threadIdx.x;
    const float* xr = x + (long)blockIdx.x * D_;
    float a0 = xr[tid], a1 = xr[tid + 256], a2 = xr[tid + 512];
    float ss = blockReduceSum256(a0*a0 + a1*a1 + a2*a2, red);
    float r = rsqrtf(ss / (float)D_ + EPSF);
    float* yr = out + (long)blockIdx.x * D_;
    yr[tid] = a0 * r; yr[tid + 256] = a1 * r; yr[tid + 512] = a2 * r;
}

// ---------------- host orchestration ----------------
extern "C" void kernel_launch(void* const* d_in, const int* in_sizes, int n_in,
                              void* d_out, int out_size)
{
    const int*   seq         = (const int*)  d_in[0];
    const float* embed_w     = (const float*)d_in[1];
    const float* ve_w        = (const float*)d_in[2];
    const float* qkv_w       = (const float*)d_in[3];
    const float* attn_proj_w = (const float*)d_in[4];
    const float* mlp_fc_w    = (const float*)d_in[5];
    const float* mlp_proj_w  = (const float*)d_in[6];
    const float* scalars     = (const float*)d_in[7];

    float *x, *x0, *xn, *skips, *ve, *qkv, *q, *k, *vt, *scores, *att, *hbuf;
    cudaGetSymbolAddress((void**)&x,      g_x);
    cudaGetSymbolAddress((void**)&x0,     g_x0);
    cudaGetSymbolAddress((void**)&xn,     g_xn);
    cudaGetSymbolAddress((void**)&skips,  g_skips);
    cudaGetSymbolAddress((void**)&ve,     g_ve);
    cudaGetSymbolAddress((void**)&qkv,    g_qkv);
    cudaGetSymbolAddress((void**)&q,      g_q);
    cudaGetSymbolAddress((void**)&k,      g_k);
    cudaGetSymbolAddress((void**)&vt,     g_vt);
    cudaGetSymbolAddress((void**)&scores, g_scores);
    cudaGetSymbolAddress((void**)&att,    g_att);
    cudaGetSymbolAddress((void**)&hbuf,   g_hbuf);

    const int NTOK = B_ * T_;   // 4096

    gpt_embed<<<NTOK, 256>>>(seq, embed_w, ve_w, x, x0, ve);

    for (int i = 0; i < L_; i++) {
        const float* skip = (i >= 6) ? (skips + (long)(11 - i) * BTD) : nullptr;
        gpt_residual<<<4096, 256>>>(x, x0, skip, scalars, i);

        if (i != 7) {
            gpt_rmsnorm<<<NTOK, 256>>>(x, xn);
            // qkv = xn @ W_qkv^T : [4096,768] x [2304,768]^T
            gpt_gemm<0><<<dim3(18, 16, 1), 256>>>(
                xn, qkv_w + (long)i * 3 * H_ * HD_ * D_, qkv,
                D_, D_, D_, 3*H_*HD_, 0, 0, 1, 0, 0, 1.f, 0);

            const float* vep = nullptr;
            if (i < 3)       vep = ve + (long)i * BTD;
            else if (i >= 9) vep = ve + (long)(i - 9) * BTD;
            gpt_rope<<<B_*T_*H_, 128>>>(qkv, vep, scalars, i, q, k, vt);

            // scores = 0.12 * Q K^T (causal): batched over 24 (b,h)
            gpt_gemm<3><<<dim3(8, 4, B_*H_), 256>>>(
                q, k, scores,
                HD_, HD_, HD_, T_,
                (long)T_*HD_, (long)T_*HD_, 1, (long)T_*T_, 0, 0.12f, 0);

            gpt_softmax<<<B_*H_*T_, 256>>>(scores);

            // att[b][t][h*128+hd] = P V : B = vT[b][h][hd][t], triangular K limit
            gpt_gemm<0><<<dim3(1, 4, B_*H_), 256>>>(
                scores, vt, att,
                T_, T_, T_, D_,
                (long)T_*T_, (long)HD_*T_, H_, (long)T_*D_, (long)HD_, 1.f, 1);

            // x += att @ W_proj^T
            gpt_gemm<1><<<dim3(6, 16, 1), 256>>>(
                att, attn_proj_w + (long)i * D_ * H_ * HD_, x,
                H_*HD_, H_*HD_, H_*HD_, D_, 0, 0, 1, 0, 0, 1.f, 0);
        }

        gpt_rmsnorm<<<NTOK, 256>>>(x, xn);
        // h = relu(xn @ W_fc^T)^2 : [4096,768] x [3072,768]^T
        gpt_gemm<2><<<dim3(24, 16, 1), 256>>>(
            xn, mlp_fc_w + (long)i * 4 * D_ * D_, hbuf,
            D_, D_, D_, 4*D_, 0, 0, 1, 0, 0, 1.f, 0);
        // x += h @ W_proj^T : [4096,3072] x [768,3072]^T
        gpt_gemm<1><<<dim3(6, 16, 1), 256>>>(
            hbuf, mlp_proj_w + (long)i * D_ * 4 * D_, x,
            4*D_, 4*D_, 4*D_, D_, 0, 0, 1, 0, 0, 1.f, 0);

        if (i < 6) gpt_copy<<<4096, 256>>>(skips + (long)i * BTD, x);
    }

    gpt_finalnorm<<<NTOK, 256>>>(x, (float*)d_out);
}

// round 5
// speedup vs baseline: 3.0089x; 1.1961x over previous
#include <cuda_runtime.h>
#include <math.h>
#include <stdint.h>

#define B_  4
#define T_  1024
#define D_  768
#define H_  6
#define HD_ 128
#define L_  12
#define BTD (B_*T_*D_)          // 3145728
#define EPSF 1.1920929e-07f
#define BK 16
#define NSTAGE 3

// ---------------- scratch (device globals; no allocation allowed) ----------------
__device__ float g_x   [BTD];
__device__ float g_x0  [BTD];
__device__ float g_xn  [BTD];
__device__ float g_skips[6*BTD];
__device__ float g_ve  [3*BTD];
__device__ float g_qkv [B_*T_*3*H_*HD_];      // [bt][which*768 + h*128 + hd]
__device__ float g_q   [B_*H_*T_*HD_];        // [b][h][t][hd]
__device__ float g_k   [B_*H_*T_*HD_];
__device__ float g_vt  [B_*H_*HD_*T_];        // [b][h][hd][t]  (transposed V)
__device__ float g_scores[B_*H_*T_*T_];       // [b][h][t][s]
__device__ float g_att [BTD];                 // [b][t][h*128+hd]
__device__ float g_hbuf[B_*T_*4*D_];          // [bt][3072]
// tf32-rounded weight mirrors
__device__ float g_qkvw [L_*3*H_*HD_*D_];     // 21.2M
__device__ float g_aprojw[L_*D_*H_*HD_];      // 7.1M
__device__ float g_fcw  [L_*4*D_*D_];         // 28.3M
__device__ float g_mprojw[L_*D_*4*D_];        // 28.3M

// ---------------- helpers ----------------
__device__ __forceinline__ float blockReduceSum256(float v, float* red) {
    int tid = threadIdx.x;
    red[tid] = v; __syncthreads();
    for (int s = 128; s > 0; s >>= 1) {
        if (tid < s) red[tid] += red[tid + s];
        __syncthreads();
    }
    float r = red[0]; __syncthreads();
    return r;
}

__device__ __forceinline__ float roundtf(float f) {
    uint32_t u;
    asm("cvt.rna.tf32.f32 %0, %1;" : "=r"(u) : "f"(f));
    return __uint_as_float(u);
}

__device__ __forceinline__ void mma8(float* c, const uint32_t* a, const uint32_t* b) {
    asm volatile(
        "mma.sync.aligned.m16n8k8.row.col.f32.tf32.tf32.f32 "
        "{%0,%1,%2,%3}, {%4,%5,%6,%7}, {%8,%9}, {%0,%1,%2,%3};"
        : "+f"(c[0]), "+f"(c[1]), "+f"(c[2]), "+f"(c[3])
        : "r"(a[0]), "r"(a[1]), "r"(a[2]), "r"(a[3]), "r"(b[0]), "r"(b[1]));
}

__device__ __forceinline__ void cp16(uint32_t saddr, const void* gptr) {
    asm volatile("cp.async.cg.shared.global [%0], [%1], 16;" :: "r"(saddr), "l"(gptr));
}

// swizzle: column-group permutation within a 16-word row
__device__ __forceinline__ int swz(int r, int cg) { return cg ^ ((r >> 1) & 3); }

// ---------------- weight pre-rounding (rna -> tf32-exact fp32) ----------------
__global__ __launch_bounds__(256)
void gpt_roundw(const float* __restrict__ src, float* __restrict__ dst, long n)
{
    long i = ((long)blockIdx.x * 256 + threadIdx.x) * 4;
    long stride = (long)gridDim.x * 1024;
    for (; i < n; i += stride) {
        float4 v = *(const float4*)&src[i];
        v.x = roundtf(v.x); v.y = roundtf(v.y);
        v.z = roundtf(v.z); v.w = roundtf(v.w);
        *(float4*)&dst[i] = v;
    }
}

// ---------------- embedding + norm + ve gather ----------------
__global__ __launch_bounds__(256)
void gpt_embed(const int* __restrict__ seq, const float* __restrict__ ew,
               const float* __restrict__ vew,
               float* __restrict__ x, float* __restrict__ x0, float* __restrict__ ve)
{
    __shared__ float red[256];
    int bt = blockIdx.x;
    int tid = threadIdx.x;
    int idx = seq[bt];
    const float* er = ew + (long)idx * D_;
    float a0 = er[tid], a1 = er[tid + 256], a2 = er[tid + 512];
    float ss = blockReduceSum256(a0*a0 + a1*a1 + a2*a2, red);
    float r = rsqrtf(ss / (float)D_ + EPSF);
    long o = (long)bt * D_;
    x0[o + tid]       = a0 * r;  x[o + tid]       = a0 * r;
    x0[o + tid + 256] = a1 * r;  x[o + tid + 256] = a1 * r;
    x0[o + tid + 512] = a2 * r;  x[o + tid + 512] = a2 * r;
    #pragma unroll
    for (int j = 0; j < 3; j++) {
        const float* vr = vew + ((long)j * 50257 + idx) * D_;
        float* vo = ve + ((long)j * (B_*T_) + bt) * D_;
        for (int d = tid; d < D_; d += 256) vo[d] = vr[d];
    }
}

// ---------------- rms norm (row = 768), output tf32-rounded ----------------
__global__ __launch_bounds__(256)
void gpt_rmsnorm(const float* __restrict__ x, float* __restrict__ y)
{
    __shared__ float red[256];
    int tid = threadIdx.x;
    const float* xr = x + (long)blockIdx.x * D_;
    float a0 = xr[tid], a1 = xr[tid + 256], a2 = xr[tid + 512];
    float ss = blockReduceSum256(a0*a0 + a1*a1 + a2*a2, red);
    float r = rsqrtf(ss / (float)D_ + EPSF);
    float* yr = y + (long)blockIdx.x * D_;
    yr[tid]       = roundtf(a0 * r);
    yr[tid + 256] = roundtf(a1 * r);
    yr[tid + 512] = roundtf(a2 * r);
}

// ---------------- residual combine: x = l0*(x + sw*skip) + l1*x0 ----------------
__global__ __launch_bounds__(256)
void gpt_residual(float* __restrict__ x, const float* __restrict__ x0,
                  const float* __restrict__ skip, const float* __restrict__ scalars, int layer)
{
    float l0 = scalars[L_ + 2*layer];
    float l1 = scalars[L_ + 2*layer + 1];
    float sw = skip ? scalars[layer - 6] : 0.f;
    long n = (long)BTD;
    for (long i = (long)blockIdx.x * 256 + threadIdx.x; i < n; i += (long)gridDim.x * 256) {
        float v = x[i];
        if (skip) v += sw * skip[i];
        x[i] = l0 * v + l1 * x0[i];
    }
}

__global__ __launch_bounds__(256)
void gpt_copy(float* __restrict__ dst, const float* __restrict__ src)
{
    long n = (long)BTD;
    for (long i = (long)blockIdx.x * 256 + threadIdx.x; i < n; i += (long)gridDim.x * 256)
        dst[i] = src[i];
}

// ---------------- qk norm + rope + v mix; q,k -> [b][h][t][hd], v -> [b][h][hd][t]
__global__ __launch_bounds__(128)
void gpt_rope(const float* __restrict__ qkv, const float* __restrict__ ve,
              const float* __restrict__ scalars, int layer,
              float* __restrict__ q, float* __restrict__ k, float* __restrict__ vt)
{
    __shared__ float rq[128], rk[128], sq[128], sk[128];
    int z = blockIdx.x;
    int hd = threadIdx.x;
    int h = z % H_;
    int t = (z / H_) % T_;
    int b = z / (H_ * T_);
    long bt = (long)b * T_ + t;
    const float* base = qkv + bt * (3*H_*HD_) + h * HD_;
    float qv = base[hd], kv = base[H_*HD_ + hd], vv = base[2*H_*HD_ + hd];

    rq[hd] = qv * qv; rk[hd] = kv * kv;
    __syncthreads();
    for (int s = 64; s > 0; s >>= 1) {
        if (hd < s) { rq[hd] += rq[hd + s]; rk[hd] += rk[hd + s]; }
        __syncthreads();
    }
    float rnq = rsqrtf(rq[0] / (float)HD_ + EPSF);
    float rnk = rsqrtf(rk[0] / (float)HD_ + EPSF);
    __syncthreads();
    sq[hd] = qv * rnq; sk[hd] = kv * rnk;
    __syncthreads();

    int j = hd & 63;
    float freq = (j < 32) ? exp2f(-10.0f * (float)j / 31.0f) : 0.0f;
    float sn, cs;
    sincosf((float)t * freq, &sn, &cs);
    float oq, ok;
    if (hd < 64) { oq =  sq[hd] * cs + sq[hd + 64] * sn;  ok =  sk[hd] * cs + sk[hd + 64] * sn; }
    else         { oq = -sq[hd - 64] * sn + sq[hd] * cs;  ok = -sk[hd - 64] * sn + sk[hd] * cs; }

    long o = (((long)b * H_ + h) * T_ + t) * HD_ + hd;
    q[o] = roundtf(oq); k[o] = roundtf(ok);

    float sa0 = scalars[3*L_ + 2*layer];
    float sa1 = scalars[3*L_ + 2*layer + 1];
    float vo = sa0 * vv;
    if (ve) vo += sa1 * ve[bt * D_ + h * HD_ + hd];
    vt[(((long)b * H_ + h) * HD_ + hd) * T_ + t] = roundtf(vo);
}

// ---------------- softmax over row of 1024, output tf32-rounded ----------------
__global__ __launch_bounds__(256)
void gpt_softmax(float* __restrict__ S)
{
    __shared__ float red[256];
    int tid = threadIdx.x;
    float* p = S + (long)blockIdx.x * T_;
    float v[4];
    float mx = -3.4e38f;
    #pragma unroll
    for (int j = 0; j < 4; j++) { v[j] = p[tid + j*256]; mx = fmaxf(mx, v[j]); }
    red[tid] = mx; __syncthreads();
    for (int s = 128; s > 0; s >>= 1) { if (tid < s) red[tid] = fmaxf(red[tid], red[tid+s]); __syncthreads(); }
    float m = red[0]; __syncthreads();
    float sum = 0.f;
    #pragma unroll
    for (int j = 0; j < 4; j++) { v[j] = expf(v[j] - m); sum += v[j]; }
    float tot = blockReduceSum256(sum, red);
    float inv = 1.0f / tot;
    #pragma unroll
    for (int j = 0; j < 4; j++) p[tid + j*256] = roundtf(v[j] * inv);
}

// =================================================================================
// tf32 tensor-core GEMM, cp.async 3-stage pipeline. Inputs must be tf32-exact fp32.
// MT=4: 256x128 block tile (warp grid 4x2, warp tile 64x64)
// MT=2: 128x128 block tile (warp grid 2x4, warp tile 64x32)
// C[m][n] = sum_k A[m][k] * B[n][k]   (both operands k-major rows)
// EPI: 0=store(rounded), 1=accumulate into C, 2=relu^2 store(rounded),
//      3=causal scores (alpha, -1e30)
// ktri: if 1, limit K to m0+BM (P upper triangle is zero)
// =================================================================================
template<int EPI, int MT>
__global__ __launch_bounds__(256)
void gpt_gemm(const float* __restrict__ A, const float* __restrict__ Bm, float* __restrict__ C,
              int K, int lda, int ldb, int ldc,
              long aZ, long bZ, int zdiv, long c1, long c2, float alpha, int ktri)
{
    constexpr int BM = MT * 64;
    constexpr int NI = (MT == 4) ? 8 : 4;      // n-fragments per warp
    constexpr int WNW = NI * 8;                // warp tile N width

    int z = blockIdx.z;
    A  += (long)z * aZ;
    Bm += (long)z * bZ;
    C  += (long)(z / zdiv) * c1 + (long)(z % zdiv) * c2;

    const int m0 = blockIdx.y * BM, n0 = blockIdx.x * 128;
    const int tid  = threadIdx.x;
    const int lane = tid & 31, warp = tid >> 5;
    const int wm = (MT == 4) ? (warp >> 1) : (warp >> 2);
    const int wn = (MT == 4) ? (warp & 1)  : (warp & 3);
    const int g = lane >> 2, t = lane & 3;

    if (EPI == 3 && n0 > m0 + (BM - 1)) {
        float2 mi2 = make_float2(-1e30f, -1e30f);
        #pragma unroll
        for (int mi = 0; mi < 4; mi++) {
            int row = m0 + wm*64 + mi*16 + g;
            #pragma unroll
            for (int ni = 0; ni < NI; ni++) {
                int col = n0 + wn*WNW + ni*8 + t*2;
                *(float2*)&C[(long)row * ldc + col]       = mi2;
                *(float2*)&C[(long)(row + 8) * ldc + col] = mi2;
            }
        }
        return;
    }

    extern __shared__ uint32_t smem[];
    uint32_t* As = smem;                         // NSTAGE * BM*16
    uint32_t* Bs = smem + NSTAGE * BM * 16;      // NSTAGE * 128*16
    uint32_t as0 = (uint32_t)__cvta_generic_to_shared(As);
    uint32_t bs0 = (uint32_t)__cvta_generic_to_shared(Bs);

    int keff = K;
    if (ktri) { int kk = m0 + BM; keff = kk < K ? kk : K; }
    const int NT = keff / BK;

    float acc[4][NI][4];
    #pragma unroll
    for (int a = 0; a < 4; a++)
        #pragma unroll
        for (int b = 0; b < NI; b++)
            #pragma unroll
            for (int c = 0; c < 4; c++) acc[a][b][c] = 0.f;

    const int ar  = tid >> 2;       // 0..63
    const int acg = tid & 3;        // col-group 0..3
    const float* apB = A  + (long)(m0 + ar) * lda + acg*4;
    const float* bpB = Bm + (long)(n0 + ar) * ldb + acg*4;

    auto issue = [&](int kt) {
        int s = kt % NSTAGE;
        const float* ap = apB + kt*BK;
        #pragma unroll
        for (int j = 0; j < MT; j++) {
            int r = ar + 64*j;
            cp16(as0 + 4u*(s*BM*16 + r*16 + swz(r, acg)*4), ap + (long)(64*j) * lda);
        }
        const float* bp = bpB + kt*BK;
        #pragma unroll
        for (int j = 0; j < 2; j++) {
            int r = ar + 64*j;
            cp16(bs0 + 4u*(s*128*16 + r*16 + swz(r, acg)*4), bp + (long)(64*j) * ldb);
        }
        asm volatile("cp.async.commit_group;" ::: "memory");
    };

    issue(0);
    issue(1);   // NT >= 8 always in this model

    for (int kt = 0; kt < NT; kt++) {
        if (kt == NT - 1) asm volatile("cp.async.wait_group 0;" ::: "memory");
        else              asm volatile("cp.async.wait_group 1;" ::: "memory");
        __syncthreads();
        if (kt + 2 < NT) issue(kt + 2);

        const uint32_t* Ab = As + (kt % NSTAGE) * BM * 16;
        const uint32_t* Bb = Bs + (kt % NSTAGE) * 128 * 16;
        #pragma unroll
        for (int ks = 0; ks < 2; ks++) {
            uint32_t af[4][4];
            #pragma unroll
            for (int mi = 0; mi < 4; mi++) {
                int r0 = wm*64 + mi*16 + g;
                int s0 = swz(r0, ks*2)*4 + t;
                int s1 = swz(r0, ks*2 + 1)*4 + t;
                af[mi][0] = Ab[r0*16 + s0];
                af[mi][1] = Ab[(r0+8)*16 + s0];
                af[mi][2] = Ab[r0*16 + s1];
                af[mi][3] = Ab[(r0+8)*16 + s1];
            }
            uint32_t bf[NI][2];
            #pragma unroll
            for (int ni = 0; ni < NI; ni++) {
                int nr = wn*WNW + ni*8 + g;
                bf[ni][0] = Bb[nr*16 + swz(nr, ks*2)*4 + t];
                bf[ni][1] = Bb[nr*16 + swz(nr, ks*2 + 1)*4 + t];
            }
            #pragma unroll
            for (int mi = 0; mi < 4; mi++)
                #pragma unroll
                for (int ni = 0; ni < NI; ni++)
                    mma8(acc[mi][ni], af[mi], bf[ni]);
        }
        __syncthreads();
    }

    // ---- epilogue ----
    #pragma unroll
    for (int mi = 0; mi < 4; mi++) {
        int row = m0 + wm*64 + mi*16 + g;
        #pragma unroll
        for (int ni = 0; ni < NI; ni++) {
            int col = n0 + wn*WNW + ni*8 + t*2;
            float* a4 = acc[mi][ni];
            #pragma unroll
            for (int half = 0; half < 2; half++) {
                int r = row + half * 8;
                float c0 = a4[half*2 + 0], c1 = a4[half*2 + 1];
                float* cp = &C[(long)r * ldc + col];
                float2 out;
                if (EPI == 0) {
                    out = make_float2(roundtf(c0), roundtf(c1));
                } else if (EPI == 1) {
                    float2 o = *(float2*)cp;
                    out = make_float2(o.x + c0, o.y + c1);
                } else if (EPI == 2) {
                    float r0 = fmaxf(c0, 0.f), r1 = fmaxf(c1, 0.f);
                    out = make_float2(roundtf(r0*r0), roundtf(r1*r1));
                } else {
                    out.x = (col + 0 <= r) ? alpha * c0 : -1e30f;
                    out.y = (col + 1 <= r) ? alpha * c1 : -1e30f;
                }
                *(float2*)cp = out;
            }
        }
    }
}

// ---------------- final norm -> output ----------------
__global__ __launch_bounds__(256)
void gpt_finalnorm(const float* __restrict__ x, float* __restrict__ out)
{
    __shared__ float red[256];
    int tid = threadIdx.x;
    const float* xr = x + (long)blockIdx.x * D_;
    float a0 = xr[tid], a1 = xr[tid + 256], a2 = xr[tid + 512];
    float ss = blockReduceSum256(a0*a0 + a1*a1 + a2*a2, red);
    float r = rsqrtf(ss / (float)D_ + EPSF);
    float* yr = out + (long)blockIdx.x * D_;
    yr[tid] = a0 * r; yr[tid + 256] = a1 * r; yr[tid + 512] = a2 * r;
}

// ---------------- host orchestration ----------------
#define SMEM4 (NSTAGE * (256 + 128) * 16 * 4)   // 73728
#define SMEM2 (NSTAGE * (128 + 128) * 16 * 4)   // 49152

extern "C" void kernel_launch(void* const* d_in, const int* in_sizes, int n_in,
                              void* d_out, int out_size)
{
    const int*   seq         = (const int*)  d_in[0];
    const float* embed_w     = (const float*)d_in[1];
    const float* ve_w        = (const float*)d_in[2];
    const float* qkv_w       = (const float*)d_in[3];
    const float* attn_proj_w = (const float*)d_in[4];
    const float* mlp_fc_w    = (const float*)d_in[5];
    const float* mlp_proj_w  = (const float*)d_in[6];
    const float* scalars     = (const float*)d_in[7];

    cudaFuncSetAttribute(gpt_gemm<0,4>, cudaFuncAttributeMaxDynamicSharedMemorySize, SMEM4);
    cudaFuncSetAttribute(gpt_gemm<2,4>, cudaFuncAttributeMaxDynamicSharedMemorySize, SMEM4);
    cudaFuncSetAttribute(gpt_gemm<3,4>, cudaFuncAttributeMaxDynamicSharedMemorySize, SMEM4);
    cudaFuncSetAttribute(gpt_gemm<0,2>, cudaFuncAttributeMaxDynamicSharedMemorySize, SMEM2);
    cudaFuncSetAttribute(gpt_gemm<1,2>, cudaFuncAttributeMaxDynamicSharedMemorySize, SMEM2);

    float *x, *x0, *xn, *skips, *ve, *qkv, *q, *k, *vt, *scores, *att, *hbuf;
    float *qkvw, *aprojw, *fcw, *mprojw;
    cudaGetSymbolAddress((void**)&x,      g_x);
    cudaGetSymbolAddress((void**)&x0,     g_x0);
    cudaGetSymbolAddress((void**)&xn,     g_xn);
    cudaGetSymbolAddress((void**)&skips,  g_skips);
    cudaGetSymbolAddress((void**)&ve,     g_ve);
    cudaGetSymbolAddress((void**)&qkv,    g_qkv);
    cudaGetSymbolAddress((void**)&q,      g_q);
    cudaGetSymbolAddress((void**)&k,      g_k);
    cudaGetSymbolAddress((void**)&vt,     g_vt);
    cudaGetSymbolAddress((void**)&scores, g_scores);
    cudaGetSymbolAddress((void**)&att,    g_att);
    cudaGetSymbolAddress((void**)&hbuf,   g_hbuf);
    cudaGetSymbolAddress((void**)&qkvw,   g_qkvw);
    cudaGetSymbolAddress((void**)&aprojw, g_aprojw);
    cudaGetSymbolAddress((void**)&fcw,    g_fcw);
    cudaGetSymbolAddress((void**)&mprojw, g_mprojw);

    const int NTOK = B_ * T_;   // 4096

    // pre-round all weights to tf32-exact fp32
    gpt_roundw<<<2048, 256>>>(qkv_w,       qkvw,   (long)L_*3*H_*HD_*D_);
    gpt_roundw<<<2048, 256>>>(attn_proj_w, aprojw, (long)L_*D_*H_*HD_);
    gpt_roundw<<<2048, 256>>>(mlp_fc_w,    fcw,    (long)L_*4*D_*D_);
    gpt_roundw<<<2048, 256>>>(mlp_proj_w,  mprojw, (long)L_*D_*4*D_);

    gpt_embed<<<NTOK, 256>>>(seq, embed_w, ve_w, x, x0, ve);

    for (int i = 0; i < L_; i++) {
        const float* skip = (i >= 6) ? (skips + (long)(11 - i) * BTD) : nullptr;
        gpt_residual<<<4096, 256>>>(x, x0, skip, scalars, i);

        if (i != 7) {
            gpt_rmsnorm<<<NTOK, 256>>>(x, xn);
            // qkv = xn @ W_qkv^T : [4096,768] x [2304,768]^T
            gpt_gemm<0,4><<<dim3(18, 16, 1), 256, SMEM4>>>(
                xn, qkvw + (long)i * 3 * H_ * HD_ * D_, qkv,
                D_, D_, D_, 3*H_*HD_, 0, 0, 1, 0, 0, 1.f, 0);

            const float* vep = nullptr;
            if (i < 3)       vep = ve + (long)i * BTD;
            else if (i >= 9) vep = ve + (long)(i - 9) * BTD;
            gpt_rope<<<B_*T_*H_, 128>>>(qkv, vep, scalars, i, q, k, vt);

            // scores = 0.12 * Q K^T (causal): batched over 24 (b,h)
            gpt_gemm<3,4><<<dim3(8, 4, B_*H_), 256, SMEM4>>>(
                q, k, scores,
                HD_, HD_, HD_, T_,
                (long)T_*HD_, (long)T_*HD_, 1, (long)T_*T_, 0, 0.12f, 0);

            gpt_softmax<<<B_*H_*T_, 256>>>(scores);

            // att[b][t][h*128+hd] = P V : B = vT[b][h][hd][t], triangular K limit
            gpt_gemm<0,2><<<dim3(1, 8, B_*H_), 256, SMEM2>>>(
                scores, vt, att,
                T_, T_, T_, D_,
                (long)T_*T_, (long)HD_*T_, H_, (long)T_*D_, (long)HD_, 1.f, 1);

            // x += att @ W_proj^T
            gpt_gemm<1,2><<<dim3(6, 32, 1), 256, SMEM2>>>(
                att, aprojw + (long)i * D_ * H_ * HD_, x,
                H_*HD_, H_*HD_, H_*HD_, D_, 0, 0, 1, 0, 0, 1.f, 0);
        }

        gpt_rmsnorm<<<NTOK, 256>>>(x, xn);
        // h = relu(xn @ W_fc^T)^2 : [4096,768] x [3072,768]^T
        gpt_gemm<2,4><<<dim3(24, 16, 1), 256, SMEM4>>>(
            xn, fcw + (long)i * 4 * D_ * D_, hbuf,
            D_, D_, D_, 4*D_, 0, 0, 1, 0, 0, 1.f, 0);
        // x += h @ W_proj^T : [4096,3072] x [768,3072]^T
        gpt_gemm<1,2><<<dim3(6, 32, 1), 256, SMEM2>>>(
            hbuf, mprojw + (long)i * D_ * 4 * D_, x,
            4*D_, 4*D_, 4*D_, D_, 0, 0, 1, 0, 0, 1.f, 0);

        if (i < 6) gpt_copy<<<4096, 256>>>(skips + (long)i * BTD, x);
    }

    gpt_finalnorm<<<NTOK, 256>>>(x, (float*)d_out);
}

// round 6
// speedup vs baseline: 3.1883x; 1.0596x over previous
#include <cuda_runtime.h>
#include <math.h>
#include <stdint.h>

#define B_  4
#define T_  1024
#define D_  768
#define H_  6
#define HD_ 128
#define L_  12
#define BTD (B_*T_*D_)          // 3145728
#define EPSF 1.1920929e-07f
#define BK 16
#define NSTAGE 3

// ---------------- scratch (device globals; no allocation allowed) ----------------
__device__ float g_x   [BTD];
__device__ float g_x0  [BTD];
__device__ float g_xn  [BTD];
__device__ float g_skips[6*BTD];
__device__ float g_ve  [3*BTD];
__device__ float g_qkv [B_*T_*3*H_*HD_];      // [bt][which*768 + h*128 + hd]
__device__ float g_q   [B_*H_*T_*HD_];        // [b][h][t][hd]
__device__ float g_k   [B_*H_*T_*HD_];
__device__ float g_vt  [B_*H_*HD_*T_];        // [b][h][hd][t]  (transposed V)
__device__ float g_scores[B_*H_*T_*T_];       // [b][h][t][s]
__device__ float g_att [BTD];                 // [b][t][h*128+hd]
__device__ float g_hbuf[B_*T_*4*D_];          // [bt][3072]
// tf32-rounded weight mirrors
__device__ float g_qkvw [L_*3*H_*HD_*D_];
__device__ float g_aprojw[L_*D_*H_*HD_];
__device__ float g_fcw  [L_*4*D_*D_];
__device__ float g_mprojw[L_*D_*4*D_];

// ---------------- helpers ----------------
__device__ __forceinline__ float blockReduceSum256(float v, float* red) {
    int tid = threadIdx.x;
    red[tid] = v; __syncthreads();
    for (int s = 128; s > 0; s >>= 1) {
        if (tid < s) red[tid] += red[tid + s];
        __syncthreads();
    }
    float r = red[0]; __syncthreads();
    return r;
}

__device__ __forceinline__ float roundtf(float f) {
    uint32_t u;
    asm("cvt.rna.tf32.f32 %0, %1;" : "=r"(u) : "f"(f));
    return __uint_as_float(u);
}

__device__ __forceinline__ void mma8(float* c, const uint32_t* a, const uint32_t* b) {
    asm volatile(
        "mma.sync.aligned.m16n8k8.row.col.f32.tf32.tf32.f32 "
        "{%0,%1,%2,%3}, {%4,%5,%6,%7}, {%8,%9}, {%0,%1,%2,%3};"
        : "+f"(c[0]), "+f"(c[1]), "+f"(c[2]), "+f"(c[3])
        : "r"(a[0]), "r"(a[1]), "r"(a[2]), "r"(a[3]), "r"(b[0]), "r"(b[1]));
}

__device__ __forceinline__ void cp16(uint32_t saddr, const void* gptr) {
    asm volatile("cp.async.cg.shared.global [%0], [%1], 16;" :: "r"(saddr), "l"(gptr));
}

// swizzle: column-group permutation within a 16-word row
__device__ __forceinline__ int swz(int r, int cg) { return cg ^ ((r >> 1) & 3); }

// ---------------- weight pre-rounding (rna -> tf32-exact fp32) ----------------
__global__ __launch_bounds__(256)
void gpt_roundw(const float* __restrict__ src, float* __restrict__ dst, long n)
{
    long i = ((long)blockIdx.x * 256 + threadIdx.x) * 4;
    long stride = (long)gridDim.x * 1024;
    for (; i < n; i += stride) {
        float4 v = *(const float4*)&src[i];
        v.x = roundtf(v.x); v.y = roundtf(v.y);
        v.z = roundtf(v.z); v.w = roundtf(v.w);
        *(float4*)&dst[i] = v;
    }
}

// ---------------- embedding + norm + ve gather ----------------
__global__ __launch_bounds__(256)
void gpt_embed(const int* __restrict__ seq, const float* __restrict__ ew,
               const float* __restrict__ vew,
               float* __restrict__ x, float* __restrict__ x0, float* __restrict__ ve)
{
    __shared__ float red[256];
    int bt = blockIdx.x;
    int tid = threadIdx.x;
    int idx = seq[bt];
    const float* er = ew + (long)idx * D_;
    float a0 = er[tid], a1 = er[tid + 256], a2 = er[tid + 512];
    float ss = blockReduceSum256(a0*a0 + a1*a1 + a2*a2, red);
    float r = rsqrtf(ss / (float)D_ + EPSF);
    long o = (long)bt * D_;
    x0[o + tid]       = a0 * r;  x[o + tid]       = a0 * r;
    x0[o + tid + 256] = a1 * r;  x[o + tid + 256] = a1 * r;
    x0[o + tid + 512] = a2 * r;  x[o + tid + 512] = a2 * r;
    #pragma unroll
    for (int j = 0; j < 3; j++) {
        const float* vr = vew + ((long)j * 50257 + idx) * D_;
        float* vo = ve + ((long)j * (B_*T_) + bt) * D_;
        for (int d = tid; d < D_; d += 256) vo[d] = vr[d];
    }
}

// ------- fused residual + rms norm: x = l0*(x + sw*skip) + l1*x0 ; xn = tf(norm(x))
__global__ __launch_bounds__(256)
void gpt_resnorm(float* __restrict__ x, const float* __restrict__ x0,
                 const float* __restrict__ skip, const float* __restrict__ scalars,
                 int layer, float* __restrict__ xn)
{
    __shared__ float red[256];
    float l0 = scalars[L_ + 2*layer];
    float l1 = scalars[L_ + 2*layer + 1];
    float sw = skip ? scalars[layer - 6] : 0.f;
    int tid = threadIdx.x;
    long o = (long)blockIdx.x * D_;
    float a[3];
    #pragma unroll
    for (int j = 0; j < 3; j++) {
        long i = o + tid + j*256;
        float v = x[i];
        if (skip) v += sw * skip[i];
        v = l0 * v + l1 * x0[i];
        x[i] = v;
        a[j] = v;
    }
    float ss = blockReduceSum256(a[0]*a[0] + a[1]*a[1] + a[2]*a[2], red);
    float r = rsqrtf(ss / (float)D_ + EPSF);
    #pragma unroll
    for (int j = 0; j < 3; j++)
        xn[o + tid + j*256] = roundtf(a[j] * r);
}

// ---------------- rms norm (row = 768), output tf32-rounded ----------------
__global__ __launch_bounds__(256)
void gpt_rmsnorm(const float* __restrict__ x, float* __restrict__ y)
{
    __shared__ float red[256];
    int tid = threadIdx.x;
    const float* xr = x + (long)blockIdx.x * D_;
    float a0 = xr[tid], a1 = xr[tid + 256], a2 = xr[tid + 512];
    float ss = blockReduceSum256(a0*a0 + a1*a1 + a2*a2, red);
    float r = rsqrtf(ss / (float)D_ + EPSF);
    float* yr = y + (long)blockIdx.x * D_;
    yr[tid]       = roundtf(a0 * r);
    yr[tid + 256] = roundtf(a1 * r);
    yr[tid + 512] = roundtf(a2 * r);
}

// ---------------- qk norm + rope + v mix; q,k -> [b][h][t][hd], v -> [b][h][hd][t]
__global__ __launch_bounds__(128)
void gpt_rope(const float* __restrict__ qkv, const float* __restrict__ ve,
              const float* __restrict__ scalars, int layer,
              float* __restrict__ q, float* __restrict__ k, float* __restrict__ vt)
{
    __shared__ float rq[128], rk[128], sq[128], sk[128];
    int z = blockIdx.x;
    int hd = threadIdx.x;
    int h = z % H_;
    int t = (z / H_) % T_;
    int b = z / (H_ * T_);
    long bt = (long)b * T_ + t;
    const float* base = qkv + bt * (3*H_*HD_) + h * HD_;
    float qv = base[hd], kv = base[H_*HD_ + hd], vv = base[2*H_*HD_ + hd];

    rq[hd] = qv * qv; rk[hd] = kv * kv;
    __syncthreads();
    for (int s = 64; s > 0; s >>= 1) {
        if (hd < s) { rq[hd] += rq[hd + s]; rk[hd] += rk[hd + s]; }
        __syncthreads();
    }
    float rnq = rsqrtf(rq[0] / (float)HD_ + EPSF);
    float rnk = rsqrtf(rk[0] / (float)HD_ + EPSF);
    __syncthreads();
    sq[hd] = qv * rnq; sk[hd] = kv * rnk;
    __syncthreads();

    int j = hd & 63;
    float freq = (j < 32) ? exp2f(-10.0f * (float)j / 31.0f) : 0.0f;
    float sn, cs;
    sincosf((float)t * freq, &sn, &cs);
    float oq, ok;
    if (hd < 64) { oq =  sq[hd] * cs + sq[hd + 64] * sn;  ok =  sk[hd] * cs + sk[hd + 64] * sn; }
    else         { oq = -sq[hd - 64] * sn + sq[hd] * cs;  ok = -sk[hd - 64] * sn + sk[hd] * cs; }

    long o = (((long)b * H_ + h) * T_ + t) * HD_ + hd;
    q[o] = roundtf(oq); k[o] = roundtf(ok);

    float sa0 = scalars[3*L_ + 2*layer];
    float sa1 = scalars[3*L_ + 2*layer + 1];
    float vo = sa0 * vv;
    if (ve) vo += sa1 * ve[bt * D_ + h * HD_ + hd];
    vt[(((long)b * H_ + h) * HD_ + hd) * T_ + t] = roundtf(vo);
}

// ---------------- softmax over row of 1024, output tf32-rounded ----------------
__global__ __launch_bounds__(256)
void gpt_softmax(float* __restrict__ S)
{
    __shared__ float red[256];
    int tid = threadIdx.x;
    float* p = S + (long)blockIdx.x * T_;
    float v[4];
    float mx = -3.4e38f;
    #pragma unroll
    for (int j = 0; j < 4; j++) { v[j] = p[tid + j*256]; mx = fmaxf(mx, v[j]); }
    red[tid] = mx; __syncthreads();
    for (int s = 128; s > 0; s >>= 1) { if (tid < s) red[tid] = fmaxf(red[tid], red[tid+s]); __syncthreads(); }
    float m = red[0]; __syncthreads();
    float sum = 0.f;
    #pragma unroll
    for (int j = 0; j < 4; j++) { v[j] = expf(v[j] - m); sum += v[j]; }
    float tot = blockReduceSum256(sum, red);
    float inv = 1.0f / tot;
    #pragma unroll
    for (int j = 0; j < 4; j++) p[tid + j*256] = roundtf(v[j] * inv);
}

// =================================================================================
// tf32 tensor-core GEMM, cp.async 3-stage pipeline. Inputs must be tf32-exact fp32.
// MT=4: 256x128 block tile, 512 threads (warp grid 4x4, warp tile 64x32)
// MT=2: 128x128 block tile, 256 threads (warp grid 2x4, warp tile 64x32), 2 CTA/SM
// C[m][n] = sum_k A[m][k] * B[n][k]   (both operands k-major rows)
// EPI: 0=store(rounded), 1=accumulate into C, 2=relu^2 store(rounded),
//      3=causal scores (alpha, -1e30), 4=accumulate + copy result to C2
// ktri: if 1, limit K to m0+BM (P upper triangle is zero)
// =================================================================================
template<int EPI, int MT>
__global__ void
__launch_bounds__(MT == 4 ? 512 : 256, MT == 4 ? 1 : 2)
gpt_gemm(const float* __restrict__ A, const float* __restrict__ Bm, float* __restrict__ C,
         float* __restrict__ C2,
         int K, int lda, int ldb, int ldc,
         long aZ, long bZ, int zdiv, long c1, long c2, float alpha, int ktri)
{
    constexpr int THREADS = (MT == 4) ? 512 : 256;
    constexpr int BM = MT * 64;
    constexpr int AROWS = THREADS / 4;     // rows staged per pass
    constexpr int APASS = BM / AROWS;      // 2
    constexpr int BPASS = 128 / AROWS;     // 1 (MT4) or 2 (MT2)

    int z = blockIdx.z;
    A  += (long)z * aZ;
    Bm += (long)z * bZ;
    long coff = (long)(z / zdiv) * c1 + (long)(z % zdiv) * c2;
    C  += coff;
    if (EPI == 4) C2 += coff;

    const int m0 = blockIdx.y * BM, n0 = blockIdx.x * 128;
    const int tid  = threadIdx.x;
    const int lane = tid & 31, warp = tid >> 5;
    const int wm = warp >> 2, wn = warp & 3;
    const int g = lane >> 2, t = lane & 3;

    if (EPI == 3 && n0 > m0 + (BM - 1)) {
        float2 mi2 = make_float2(-1e30f, -1e30f);
        #pragma unroll
        for (int mi = 0; mi < 4; mi++) {
            int row = m0 + wm*64 + mi*16 + g;
            #pragma unroll
            for (int ni = 0; ni < 4; ni++) {
                int col = n0 + wn*32 + ni*8 + t*2;
                *(float2*)&C[(long)row * ldc + col]       = mi2;
                *(float2*)&C[(long)(row + 8) * ldc + col] = mi2;
            }
        }
        return;
    }

    extern __shared__ uint32_t smem[];
    uint32_t* As = smem;                         // NSTAGE * BM*16
    uint32_t* Bs = smem + NSTAGE * BM * 16;      // NSTAGE * 128*16
    uint32_t as0 = (uint32_t)__cvta_generic_to_shared(As);
    uint32_t bs0 = (uint32_t)__cvta_generic_to_shared(Bs);

    int keff = K;
    if (ktri) { int kk = m0 + BM; keff = kk < K ? kk : K; }
    const int NT = keff / BK;

    float acc[4][4][4];
    #pragma unroll
    for (int a = 0; a < 4; a++)
        #pragma unroll
        for (int b = 0; b < 4; b++)
            #pragma unroll
            for (int c = 0; c < 4; c++) acc[a][b][c] = 0.f;

    const int ar  = tid >> 2;
    const int acg = tid & 3;
    const float* apB = A  + (long)(m0 + ar) * lda + acg*4;
    const float* bpB = Bm + (long)(n0 + ar) * ldb + acg*4;

    auto issue = [&](int kt) {
        int s = kt % NSTAGE;
        const float* ap = apB + kt*BK;
        #pragma unroll
        for (int j = 0; j < APASS; j++) {
            int r = ar + AROWS*j;
            cp16(as0 + 4u*(s*BM*16 + r*16 + swz(r, acg)*4), ap + (long)(AROWS*j) * lda);
        }
        const float* bp = bpB + kt*BK;
        #pragma unroll
        for (int j = 0; j < BPASS; j++) {
            int r = ar + AROWS*j;
            cp16(bs0 + 4u*(s*128*16 + r*16 + swz(r, acg)*4), bp + (long)(AROWS*j) * ldb);
        }
        asm volatile("cp.async.commit_group;" ::: "memory");
    };

    issue(0);
    issue(1);   // NT >= 8 always in this model

    for (int kt = 0; kt < NT; kt++) {
        if (kt == NT - 1) asm volatile("cp.async.wait_group 0;" ::: "memory");
        else              asm volatile("cp.async.wait_group 1;" ::: "memory");
        __syncthreads();

        const uint32_t* Ab = As + (kt % NSTAGE) * BM * 16;
        const uint32_t* Bb = Bs + (kt % NSTAGE) * 128 * 16;
        #pragma unroll
        for (int ks = 0; ks < 2; ks++) {
            uint32_t af[4][4];
            #pragma unroll
            for (int mi = 0; mi < 4; mi++) {
                int r0 = wm*64 + mi*16 + g;
                int s0 = swz(r0, ks*2)*4 + t;
                int s1 = swz(r0, ks*2 + 1)*4 + t;
                af[mi][0] = Ab[r0*16 + s0];
                af[mi][1] = Ab[(r0+8)*16 + s0];
                af[mi][2] = Ab[r0*16 + s1];
                af[mi][3] = Ab[(r0+8)*16 + s1];
            }
            uint32_t bf[4][2];
            #pragma unroll
            for (int ni = 0; ni < 4; ni++) {
                int nr = wn*32 + ni*8 + g;
                bf[ni][0] = Bb[nr*16 + swz(nr, ks*2)*4 + t];
                bf[ni][1] = Bb[nr*16 + swz(nr, ks*2 + 1)*4 + t];
            }
            #pragma unroll
            for (int mi = 0; mi < 4; mi++)
                #pragma unroll
                for (int ni = 0; ni < 4; ni++)
                    mma8(acc[mi][ni], af[mi], bf[ni]);
        }

        if (kt + 2 < NT) issue(kt + 2);
    }

    // ---- epilogue ----
    #pragma unroll
    for (int mi = 0; mi < 4; mi++) {
        int row = m0 + wm*64 + mi*16 + g;
        #pragma unroll
        for (int ni = 0; ni < 4; ni++) {
            int col = n0 + wn*32 + ni*8 + t*2;
            float* a4 = acc[mi][ni];
            #pragma unroll
            for (int half = 0; half < 2; half++) {
                int r = row + half * 8;
                float c0 = a4[half*2 + 0], c1 = a4[half*2 + 1];
                float* cp = &C[(long)r * ldc + col];
                float2 out;
                if (EPI == 0) {
                    out = make_float2(roundtf(c0), roundtf(c1));
                } else if (EPI == 1 || EPI == 4) {
                    float2 o = *(float2*)cp;
                    out = make_float2(o.x + c0, o.y + c1);
                } else if (EPI == 2) {
                    float r0 = fmaxf(c0, 0.f), r1 = fmaxf(c1, 0.f);
                    out = make_float2(roundtf(r0*r0), roundtf(r1*r1));
                } else {
                    out.x = (col + 0 <= r) ? alpha * c0 : -1e30f;
                    out.y = (col + 1 <= r) ? alpha * c1 : -1e30f;
                }
                *(float2*)cp = out;
                if (EPI == 4) *(float2*)&C2[(long)r * ldc + col] = out;
            }
        }
    }
}

// ---------------- final norm -> output ----------------
__global__ __launch_bounds__(256)
void gpt_finalnorm(const float* __restrict__ x, float* __restrict__ out)
{
    __shared__ float red[256];
    int tid = threadIdx.x;
    const float* xr = x + (long)blockIdx.x * D_;
    float a0 = xr[tid], a1 = xr[tid + 256], a2 = xr[tid + 512];
    float ss = blockReduceSum256(a0*a0 + a1*a1 + a2*a2, red);
    float r = rsqrtf(ss / (float)D_ + EPSF);
    float* yr = out + (long)blockIdx.x * D_;
    yr[tid] = a0 * r; yr[tid + 256] = a1 * r; yr[tid + 512] = a2 * r;
}

// ---------------- host orchestration ----------------
#define SMEM4 (NSTAGE * (256 + 128) * 16 * 4)   // 73728
#define SMEM2 (NSTAGE * (128 + 128) * 16 * 4)   // 49152

extern "C" void kernel_launch(void* const* d_in, const int* in_sizes, int n_in,
                              void* d_out, int out_size)
{
    const int*   seq         = (const int*)  d_in[0];
    const float* embed_w     = (const float*)d_in[1];
    const float* ve_w        = (const float*)d_in[2];
    const float* qkv_w       = (const float*)d_in[3];
    const float* attn_proj_w = (const float*)d_in[4];
    const float* mlp_fc_w    = (const float*)d_in[5];
    const float* mlp_proj_w  = (const float*)d_in[6];
    const float* scalars     = (const float*)d_in[7];

    cudaFuncSetAttribute(gpt_gemm<0,4>, cudaFuncAttributeMaxDynamicSharedMemorySize, SMEM4);
    cudaFuncSetAttribute(gpt_gemm<2,4>, cudaFuncAttributeMaxDynamicSharedMemorySize, SMEM4);
    cudaFuncSetAttribute(gpt_gemm<3,4>, cudaFuncAttributeMaxDynamicSharedMemorySize, SMEM4);
    cudaFuncSetAttribute(gpt_gemm<0,2>, cudaFuncAttributeMaxDynamicSharedMemorySize, SMEM2);
    cudaFuncSetAttribute(gpt_gemm<1,2>, cudaFuncAttributeMaxDynamicSharedMemorySize, SMEM2);
    cudaFuncSetAttribute(gpt_gemm<4,2>, cudaFuncAttributeMaxDynamicSharedMemorySize, SMEM2);

    float *x, *x0, *xn, *skips, *ve, *qkv, *q, *k, *vt, *scores, *att, *hbuf;
    float *qkvw, *aprojw, *fcw, *mprojw;
    cudaGetSymbolAddress((void**)&x,      g_x);
    cudaGetSymbolAddress((void**)&x0,     g_x0);
    cudaGetSymbolAddress((void**)&xn,     g_xn);
    cudaGetSymbolAddress((void**)&skips,  g_skips);
    cudaGetSymbolAddress((void**)&ve,     g_ve);
    cudaGetSymbolAddress((void**)&qkv,    g_qkv);
    cudaGetSymbolAddress((void**)&q,      g_q);
    cudaGetSymbolAddress((void**)&k,      g_k);
    cudaGetSymbolAddress((void**)&vt,     g_vt);
    cudaGetSymbolAddress((void**)&scores, g_scores);
    cudaGetSymbolAddress((void**)&att,    g_att);
    cudaGetSymbolAddress((void**)&hbuf,   g_hbuf);
    cudaGetSymbolAddress((void**)&qkvw,   g_qkvw);
    cudaGetSymbolAddress((void**)&aprojw, g_aprojw);
    cudaGetSymbolAddress((void**)&fcw,    g_fcw);
    cudaGetSymbolAddress((void**)&mprojw, g_mprojw);

    const int NTOK = B_ * T_;   // 4096

    // pre-round all weights to tf32-exact fp32
    gpt_roundw<<<2048, 256>>>(qkv_w,       qkvw,   (long)L_*3*H_*HD_*D_);
    gpt_roundw<<<2048, 256>>>(attn_proj_w, aprojw, (long)L_*D_*H_*HD_);
    gpt_roundw<<<2048, 256>>>(mlp_fc_w,    fcw,    (long)L_*4*D_*D_);
    gpt_roundw<<<2048, 256>>>(mlp_proj_w,  mprojw, (long)L_*D_*4*D_);

    gpt_embed<<<NTOK, 256>>>(seq, embed_w, ve_w, x, x0, ve);

    for (int i = 0; i < L_; i++) {
        const float* skip = (i >= 6) ? (skips + (long)(11 - i) * BTD) : nullptr;
        gpt_resnorm<<<NTOK, 256>>>(x, x0, skip, scalars, i, xn);

        if (i != 7) {
            // qkv = xn @ W_qkv^T : [4096,768] x [2304,768]^T
            gpt_gemm<0,4><<<dim3(18, 16, 1), 512, SMEM4>>>(
                xn, qkvw + (long)i * 3 * H_ * HD_ * D_, qkv, nullptr,
                D_, D_, D_, 3*H_*HD_, 0, 0, 1, 0, 0, 1.f, 0);

            const float* vep = nullptr;
            if (i < 3)       vep = ve + (long)i * BTD;
            else if (i >= 9) vep = ve + (long)(i - 9) * BTD;
            gpt_rope<<<B_*T_*H_, 128>>>(qkv, vep, scalars, i, q, k, vt);

            // scores = 0.12 * Q K^T (causal): batched over 24 (b,h)
            gpt_gemm<3,4><<<dim3(8, 4, B_*H_), 512, SMEM4>>>(
                q, k, scores, nullptr,
                HD_, HD_, HD_, T_,
                (long)T_*HD_, (long)T_*HD_, 1, (long)T_*T_, 0, 0.12f, 0);

            gpt_softmax<<<B_*H_*T_, 256>>>(scores);

            // att[b][t][h*128+hd] = P V : B = vT[b][h][hd][t], triangular K limit
            gpt_gemm<0,2><<<dim3(1, 8, B_*H_), 256, SMEM2>>>(
                scores, vt, att, nullptr,
                T_, T_, T_, D_,
                (long)T_*T_, (long)HD_*T_, H_, (long)T_*D_, (long)HD_, 1.f, 1);

            // x += att @ W_proj^T
            gpt_gemm<1,2><<<dim3(6, 32, 1), 256, SMEM2>>>(
                att, aprojw + (long)i * D_ * H_ * HD_, x, nullptr,
                H_*HD_, H_*HD_, H_*HD_, D_, 0, 0, 1, 0, 0, 1.f, 0);

            gpt_rmsnorm<<<NTOK, 256>>>(x, xn);
        }

        // h = relu(xn @ W_fc^T)^2 : [4096,768] x [3072,768]^T
        gpt_gemm<2,4><<<dim3(24, 16, 1), 512, SMEM4>>>(
            xn, fcw + (long)i * 4 * D_ * D_, hbuf, nullptr,
            D_, D_, D_, 4*D_, 0, 0, 1, 0, 0, 1.f, 0);
        // x += h @ W_proj^T ; for i<6 also copy x into skip buffer
        if (i < 6) {
            gpt_gemm<4,2><<<dim3(6, 32, 1), 256, SMEM2>>>(
                hbuf, mprojw + (long)i * D_ * 4 * D_, x, skips + (long)i * BTD,
                4*D_, 4*D_, 4*D_, D_, 0, 0, 1, 0, 0, 1.f, 0);
        } else {
            gpt_gemm<1,2><<<dim3(6, 32, 1), 256, SMEM2>>>(
                hbuf, mprojw + (long)i * D_ * 4 * D_, x, nullptr,
                4*D_, 4*D_, 4*D_, D_, 0, 0, 1, 0, 0, 1.f, 0);
        }
    }

    gpt_finalnorm<<<NTOK, 256>>>(x, (float*)d_out);
}

// round 8
// speedup vs baseline: 5.0305x; 1.5778x over previous
#include <cuda_runtime.h>
#include <cuda_fp16.h>
#include <math.h>
#include <stdint.h>

#define B_  4
#define T_  1024
#define D_  768
#define H_  6
#define HD_ 128
#define L_  12
#define BTD (B_*T_*D_)          // 3145728
#define EPSF 1.1920929e-07f
#define BKH 32                  // k-halfs per tile (16 uint32 words)
#define NSTAGE 3

// ---------------- scratch (device globals; no allocation allowed) ----------------
__device__ float  g_x   [BTD];
__device__ float  g_x0  [BTD];
__device__ __half g_xn  [BTD];
__device__ float  g_skips[6*BTD];
__device__ float  g_ve  [3*BTD];
__device__ __half g_qkv [B_*T_*3*H_*HD_];      // [bt][which*768 + h*128 + hd]
__device__ __half g_q   [B_*H_*T_*HD_];        // [b][h][t][hd]
__device__ __half g_k   [B_*H_*T_*HD_];
__device__ __half g_vt  [B_*H_*HD_*T_];        // [b][h][hd][t]  (transposed V)
__device__ float  g_scores[B_*H_*T_*T_];       // [b][h][t][s]  fp32 scores
__device__ __half g_p   [B_*H_*T_*T_];         // softmax probs (half)
__device__ __half g_att [BTD];                 // [b][t][h*128+hd]
__device__ __half g_hbuf[B_*T_*4*D_];          // [bt][3072]
// fp16 weight mirrors
__device__ __half g_qkvw [L_*3*H_*HD_*D_];
__device__ __half g_aprojw[L_*D_*H_*HD_];
__device__ __half g_fcw  [L_*4*D_*D_];
__device__ __half g_mprojw[L_*D_*4*D_];

// ---------------- helpers ----------------
__device__ __forceinline__ float blockReduceSum256(float v, float* red) {
    int tid = threadIdx.x;
    red[tid] = v; __syncthreads();
    for (int s = 128; s > 0; s >>= 1) {
        if (tid < s) red[tid] += red[tid + s];
        __syncthreads();
    }
    float r = red[0]; __syncthreads();
    return r;
}

__device__ __forceinline__ void mma16(float* c, const uint32_t* a, const uint32_t* b) {
    asm volatile(
        "mma.sync.aligned.m16n8k16.row.col.f32.f16.f16.f32 "
        "{%0,%1,%2,%3}, {%4,%5,%6,%7}, {%8,%9}, {%0,%1,%2,%3};"
        : "+f"(c[0]), "+f"(c[1]), "+f"(c[2]), "+f"(c[3])
        : "r"(a[0]), "r"(a[1]), "r"(a[2]), "r"(a[3]), "r"(b[0]), "r"(b[1]));
}

__device__ __forceinline__ void cp16(uint32_t saddr, const void* gptr) {
    asm volatile("cp.async.cg.shared.global [%0], [%1], 16;" :: "r"(saddr), "l"(gptr));
}

// swizzle: column-group permutation within a 16-word row
__device__ __forceinline__ int swz(int r, int cg) { return cg ^ ((r >> 1) & 3); }

// ---------------- weight conversion fp32 -> fp16 (rne) ----------------
__global__ __launch_bounds__(256)
void gpt_cvtw(const float* __restrict__ src, __half* __restrict__ dst, long n)
{
    long i = ((long)blockIdx.x * 256 + threadIdx.x) * 4;
    long stride = (long)gridDim.x * 1024;
    for (; i < n; i += stride) {
        float4 v = *(const float4*)&src[i];
        __half2* d = (__half2*)&dst[i];
        d[0] = __floats2half2_rn(v.x, v.y);
        d[1] = __floats2half2_rn(v.z, v.w);
    }
}

// ---------------- embedding + norm + ve gather ----------------
__global__ __launch_bounds__(256)
void gpt_embed(const int* __restrict__ seq, const float* __restrict__ ew,
               const float* __restrict__ vew,
               float* __restrict__ x, float* __restrict__ x0, float* __restrict__ ve)
{
    __shared__ float red[256];
    int bt = blockIdx.x;
    int tid = threadIdx.x;
    int idx = seq[bt];
    const float* er = ew + (long)idx * D_;
    float a0 = er[tid], a1 = er[tid + 256], a2 = er[tid + 512];
    float ss = blockReduceSum256(a0*a0 + a1*a1 + a2*a2, red);
    float r = rsqrtf(ss / (float)D_ + EPSF);
    long o = (long)bt * D_;
    x0[o + tid]       = a0 * r;  x[o + tid]       = a0 * r;
    x0[o + tid + 256] = a1 * r;  x[o + tid + 256] = a1 * r;
    x0[o + tid + 512] = a2 * r;  x[o + tid + 512] = a2 * r;
    #pragma unroll
    for (int j = 0; j < 3; j++) {
        const float* vr = vew + ((long)j * 50257 + idx) * D_;
        float* vo = ve + ((long)j * (B_*T_) + bt) * D_;
        for (int d = tid; d < D_; d += 256) vo[d] = vr[d];
    }
}

// ------- fused residual + rms norm: x = l0*(x + sw*skip) + l1*x0 ; xn = h(norm(x))
__global__ __launch_bounds__(256)
void gpt_resnorm(float* __restrict__ x, const float* __restrict__ x0,
                 const float* __restrict__ skip, const float* __restrict__ scalars,
                 int layer, __half* __restrict__ xn)
{
    __shared__ float red[256];
    float l0 = scalars[L_ + 2*layer];
    float l1 = scalars[L_ + 2*layer + 1];
    float sw = skip ? scalars[layer - 6] : 0.f;
    int tid = threadIdx.x;
    long o = (long)blockIdx.x * D_;
    float a[3];
    #pragma unroll
    for (int j = 0; j < 3; j++) {
        long i = o + tid + j*256;
        float v = x[i];
        if (skip) v += sw * skip[i];
        v = l0 * v + l1 * x0[i];
        x[i] = v;
        a[j] = v;
    }
    float ss = blockReduceSum256(a[0]*a[0] + a[1]*a[1] + a[2]*a[2], red);
    float r = rsqrtf(ss / (float)D_ + EPSF);
    #pragma unroll
    for (int j = 0; j < 3; j++)
        xn[o + tid + j*256] = __float2half_rn(a[j] * r);
}

// ---------------- rms norm (row = 768), output fp16 ----------------
__global__ __launch_bounds__(256)
void gpt_rmsnorm(const float* __restrict__ x, __half* __restrict__ y)
{
    __shared__ float red[256];
    int tid = threadIdx.x;
    const float* xr = x + (long)blockIdx.x * D_;
    float a0 = xr[tid], a1 = xr[tid + 256], a2 = xr[tid + 512];
    float ss = blockReduceSum256(a0*a0 + a1*a1 + a2*a2, red);
    float r = rsqrtf(ss / (float)D_ + EPSF);
    __half* yr = y + (long)blockIdx.x * D_;
    yr[tid]       = __float2half_rn(a0 * r);
    yr[tid + 256] = __float2half_rn(a1 * r);
    yr[tid + 512] = __float2half_rn(a2 * r);
}

// ---------------- qk norm + rope + v mix; q,k -> [b][h][t][hd], v -> [b][h][hd][t]
__global__ __launch_bounds__(128)
void gpt_rope(const __half* __restrict__ qkv, const float* __restrict__ ve,
              const float* __restrict__ scalars, int layer,
              __half* __restrict__ q, __half* __restrict__ k, __half* __restrict__ vt)
{
    __shared__ float rq[128], rk[128], sq[128], sk[128];
    int z = blockIdx.x;
    int hd = threadIdx.x;
    int h = z % H_;
    int t = (z / H_) % T_;
    int b = z / (H_ * T_);
    long bt = (long)b * T_ + t;
    const __half* base = qkv + bt * (3*H_*HD_) + h * HD_;
    float qv = __half2float(base[hd]);
    float kv = __half2float(base[H_*HD_ + hd]);
    float vv = __half2float(base[2*H_*HD_ + hd]);

    rq[hd] = qv * qv; rk[hd] = kv * kv;
    __syncthreads();
    for (int s = 64; s > 0; s >>= 1) {
        if (hd < s) { rq[hd] += rq[hd + s]; rk[hd] += rk[hd + s]; }
        __syncthreads();
    }
    float rnq = rsqrtf(rq[0] / (float)HD_ + EPSF);
    float rnk = rsqrtf(rk[0] / (float)HD_ + EPSF);
    __syncthreads();
    sq[hd] = qv * rnq; sk[hd] = kv * rnk;
    __syncthreads();

    int j = hd & 63;
    float freq = (j < 32) ? exp2f(-10.0f * (float)j / 31.0f) : 0.0f;
    float sn, cs;
    sincosf((float)t * freq, &sn, &cs);
    float oq, ok;
    if (hd < 64) { oq =  sq[hd] * cs + sq[hd + 64] * sn;  ok =  sk[hd] * cs + sk[hd + 64] * sn; }
    else         { oq = -sq[hd - 64] * sn + sq[hd] * cs;  ok = -sk[hd - 64] * sn + sk[hd] * cs; }

    long o = (((long)b * H_ + h) * T_ + t) * HD_ + hd;
    q[o] = __float2half_rn(oq); k[o] = __float2half_rn(ok);

    float sa0 = scalars[3*L_ + 2*layer];
    float sa1 = scalars[3*L_ + 2*layer + 1];
    float vo = sa0 * vv;
    if (ve) vo += sa1 * ve[bt * D_ + h * HD_ + hd];
    vt[(((long)b * H_ + h) * HD_ + hd) * T_ + t] = __float2half_rn(vo);
}

// ---------------- softmax over row of 1024: fp32 scores in, fp16 probs out ------
__global__ __launch_bounds__(256)
void gpt_softmax(const float* __restrict__ S, __half* __restrict__ P)
{
    __shared__ float red[256];
    int tid = threadIdx.x;
    const float* p = S + (long)blockIdx.x * T_;
    __half* po = P + (long)blockIdx.x * T_;
    float v[4];
    float mx = -3.4e38f;
    #pragma unroll
    for (int j = 0; j < 4; j++) { v[j] = p[tid + j*256]; mx = fmaxf(mx, v[j]); }
    red[tid] = mx; __syncthreads();
    for (int s = 128; s > 0; s >>= 1) { if (tid < s) red[tid] = fmaxf(red[tid], red[tid+s]); __syncthreads(); }
    float m = red[0]; __syncthreads();
    float sum = 0.f;
    #pragma unroll
    for (int j = 0; j < 4; j++) { v[j] = expf(v[j] - m); sum += v[j]; }
    float tot = blockReduceSum256(sum, red);
    float inv = 1.0f / tot;
    #pragma unroll
    for (int j = 0; j < 4; j++) po[tid + j*256] = __float2half_rn(v[j] * inv);
}

// =================================================================================
// fp16 tensor-core GEMM (m16n8k16, fp32 accum), cp.async 3-stage pipeline.
// MT=4: 256x128 block tile, 512 threads (warp grid 4x4, warp tile 64x32)
// MT=2: 128x128 block tile, 256 threads (warp grid 2x4, warp tile 64x32), 2 CTA/SM
// C[m][n] = sum_k A[m][k] * B[n][k]   (both operands k-major half rows)
// EPI: 0=store half, 1=accumulate into float C, 2=relu^2 store half,
//      3=causal scores (alpha, -1e30) float, 4=accumulate + copy to float C2
// ktri: if 1, limit K to m0+BM (P upper triangle is zero)
// =================================================================================
template<int EPI, int MT>
__global__ void
__launch_bounds__(MT == 4 ? 512 : 256, MT == 4 ? 1 : 2)
gpt_gemm(const __half* __restrict__ A, const __half* __restrict__ Bm, void* __restrict__ Cv,
         float* __restrict__ C2,
         int K, int lda, int ldb, int ldc,
         long aZ, long bZ, int zdiv, long c1, long c2, float alpha, int ktri)
{
    constexpr int THREADS = (MT == 4) ? 512 : 256;
    constexpr int BM = MT * 64;
    constexpr int AROWS = THREADS / 4;     // rows staged per pass
    constexpr int APASS = BM / AROWS;      // 2
    constexpr int BPASS = 128 / AROWS;     // 1 (MT4) or 2 (MT2)

    int z = blockIdx.z;
    A  += (long)z * aZ;
    Bm += (long)z * bZ;
    long coff = (long)(z / zdiv) * c1 + (long)(z % zdiv) * c2;
    float*  Cf = (float*)Cv + coff;
    __half* Ch = (__half*)Cv + coff;
    if (EPI == 4) C2 += coff;

    const int m0 = blockIdx.y * BM, n0 = blockIdx.x * 128;
    const int tid  = threadIdx.x;
    const int lane = tid & 31, warp = tid >> 5;
    const int wm = warp >> 2, wn = warp & 3;
    const int g = lane >> 2, t = lane & 3;

    if (EPI == 3 && n0 > m0 + (BM - 1)) {
        float2 mi2 = make_float2(-1e30f, -1e30f);
        #pragma unroll
        for (int mi = 0; mi < 4; mi++) {
            int row = m0 + wm*64 + mi*16 + g;
            #pragma unroll
            for (int ni = 0; ni < 4; ni++) {
                int col = n0 + wn*32 + ni*8 + t*2;
                *(float2*)&Cf[(long)row * ldc + col]       = mi2;
                *(float2*)&Cf[(long)(row + 8) * ldc + col] = mi2;
            }
        }
        return;
    }

    extern __shared__ uint32_t smem[];
    uint32_t* As = smem;                         // NSTAGE * BM*16 words
    uint32_t* Bs = smem + NSTAGE * BM * 16;      // NSTAGE * 128*16 words
    uint32_t as0 = (uint32_t)__cvta_generic_to_shared(As);
    uint32_t bs0 = (uint32_t)__cvta_generic_to_shared(Bs);

    int keff = K;
    if (ktri) { int kk = m0 + BM; keff = kk < K ? kk : K; }
    const int NT = keff / BKH;

    float acc[4][4][4];
    #pragma unroll
    for (int a = 0; a < 4; a++)
        #pragma unroll
        for (int b = 0; b < 4; b++)
            #pragma unroll
            for (int c = 0; c < 4; c++) acc[a][b][c] = 0.f;

    const int ar  = tid >> 2;
    const int acg = tid & 3;
    const __half* apB = A  + (long)(m0 + ar) * lda + acg*8;
    const __half* bpB = Bm + (long)(n0 + ar) * ldb + acg*8;

    auto issue = [&](int kt) {
        int s = kt % NSTAGE;
        const __half* ap = apB + kt*BKH;
        #pragma unroll
        for (int j = 0; j < APASS; j++) {
            int r = ar + AROWS*j;
            cp16(as0 + 4u*(s*BM*16 + r*16 + swz(r, acg)*4), ap + (long)(AROWS*j) * lda);
        }
        const __half* bp = bpB + kt*BKH;
        #pragma unroll
        for (int j = 0; j < BPASS; j++) {
            int r = ar + AROWS*j;
            cp16(bs0 + 4u*(s*128*16 + r*16 + swz(r, acg)*4), bp + (long)(AROWS*j) * ldb);
        }
        asm volatile("cp.async.commit_group;" ::: "memory");
    };

    issue(0);
    issue(1);   // NT >= 2 always in this model

    for (int kt = 0; kt < NT; kt++) {
        if (kt == NT - 1) asm volatile("cp.async.wait_group 0;" ::: "memory");
        else              asm volatile("cp.async.wait_group 1;" ::: "memory");
        __syncthreads();

        const uint32_t* Ab = As + (kt % NSTAGE) * BM * 16;
        const uint32_t* Bb = Bs + (kt % NSTAGE) * 128 * 16;
        #pragma unroll
        for (int ks = 0; ks < 2; ks++) {
            uint32_t af[4][4];
            #pragma unroll
            for (int mi = 0; mi < 4; mi++) {
                int r0 = wm*64 + mi*16 + g;
                int s0 = swz(r0, ks*2)*4 + t;
                int s1 = swz(r0, ks*2 + 1)*4 + t;
                af[mi][0] = Ab[r0*16 + s0];
                af[mi][1] = Ab[(r0+8)*16 + s0];
                af[mi][2] = Ab[r0*16 + s1];
                af[mi][3] = Ab[(r0+8)*16 + s1];
            }
            uint32_t bf[4][2];
            #pragma unroll
            for (int ni = 0; ni < 4; ni++) {
                int nr = wn*32 + ni*8 + g;
                bf[ni][0] = Bb[nr*16 + swz(nr, ks*2)*4 + t];
                bf[ni][1] = Bb[nr*16 + swz(nr, ks*2 + 1)*4 + t];
            }
            #pragma unroll
            for (int mi = 0; mi < 4; mi++)
                #pragma unroll
                for (int ni = 0; ni < 4; ni++)
                    mma16(acc[mi][ni], af[mi], bf[ni]);
        }

        if (kt + 2 < NT) issue(kt + 2);
    }

    // ---- epilogue ----
    #pragma unroll
    for (int mi = 0; mi < 4; mi++) {
        int row = m0 + wm*64 + mi*16 + g;
        #pragma unroll
        for (int ni = 0; ni < 4; ni++) {
            int col = n0 + wn*32 + ni*8 + t*2;
            float* a4 = acc[mi][ni];
            #pragma unroll
            for (int half_ = 0; half_ < 2; half_++) {
                int r = row + half_ * 8;
                float c0 = a4[half_*2 + 0], c1 = a4[half_*2 + 1];
                if (EPI == 0) {
                    *(__half2*)&Ch[(long)r * ldc + col] = __floats2half2_rn(c0, c1);
                } else if (EPI == 2) {
                    float r0 = fmaxf(c0, 0.f), r1 = fmaxf(c1, 0.f);
                    *(__half2*)&Ch[(long)r * ldc + col] = __floats2half2_rn(r0*r0, r1*r1);
                } else if (EPI == 1 || EPI == 4) {
                    float* cp = &Cf[(long)r * ldc + col];
                    float2 o = *(float2*)cp;
                    float2 out = make_float2(o.x + c0, o.y + c1);
                    *(float2*)cp = out;
                    if (EPI == 4) *(float2*)&C2[(long)r * ldc + col] = out;
                } else {  // EPI == 3
                    float2 out;
                    out.x = (col + 0 <= r) ? alpha * c0 : -1e30f;
                    out.y = (col + 1 <= r) ? alpha * c1 : -1e30f;
                    *(float2*)&Cf[(long)r * ldc + col] = out;
                }
            }
        }
    }
}

// ---------------- final norm -> output ----------------
__global__ __launch_bounds__(256)
void gpt_finalnorm(const float* __restrict__ x, float* __restrict__ out)
{
    __shared__ float red[256];
    int tid = threadIdx.x;
    const float* xr = x + (long)blockIdx.x * D_;
    float a0 = xr[tid], a1 = xr[tid + 256], a2 = xr[tid + 512];
    float ss = blockReduceSum256(a0*a0 + a1*a1 + a2*a2, red);
    float r = rsqrtf(ss / (float)D_ + EPSF);
    float* yr = out + (long)blockIdx.x * D_;
    yr[tid] = a0 * r; yr[tid + 256] = a1 * r; yr[tid + 512] = a2 * r;
}

// ---------------- host orchestration ----------------
// smem: words are uint32 (half2); sizes unchanged from R6
#define SMEM4 (NSTAGE * (256 + 128) * 16 * 4)   // 73728
#define SMEM2 (NSTAGE * (128 + 128) * 16 * 4)   // 49152

extern "C" void kernel_launch(void* const* d_in, const int* in_sizes, int n_in,
                              void* d_out, int out_size)
{
    const int*   seq         = (const int*)  d_in[0];
    const float* embed_w     = (const float*)d_in[1];
    const float* ve_w        = (const float*)d_in[2];
    const float* qkv_w       = (const float*)d_in[3];
    const float* attn_proj_w = (const float*)d_in[4];
    const float* mlp_fc_w    = (const float*)d_in[5];
    const float* mlp_proj_w  = (const float*)d_in[6];
    const float* scalars     = (const float*)d_in[7];

    cudaFuncSetAttribute(gpt_gemm<0,4>, cudaFuncAttributeMaxDynamicSharedMemorySize, SMEM4);
    cudaFuncSetAttribute(gpt_gemm<2,4>, cudaFuncAttributeMaxDynamicSharedMemorySize, SMEM4);
    cudaFuncSetAttribute(gpt_gemm<3,4>, cudaFuncAttributeMaxDynamicSharedMemorySize, SMEM4);
    cudaFuncSetAttribute(gpt_gemm<0,2>, cudaFuncAttributeMaxDynamicSharedMemorySize, SMEM2);
    cudaFuncSetAttribute(gpt_gemm<1,2>, cudaFuncAttributeMaxDynamicSharedMemorySize, SMEM2);
    cudaFuncSetAttribute(gpt_gemm<4,2>, cudaFuncAttributeMaxDynamicSharedMemorySize, SMEM2);

    float *x, *x0, *skips, *ve, *scores;
    __half *xn, *qkv, *q, *k, *vt, *p, *att, *hbuf;
    __half *qkvw, *aprojw, *fcw, *mprojw;
    cudaGetSymbolAddress((void**)&x,      g_x);
    cudaGetSymbolAddress((void**)&x0,     g_x0);
    cudaGetSymbolAddress((void**)&xn,     g_xn);
    cudaGetSymbolAddress((void**)&skips,  g_skips);
    cudaGetSymbolAddress((void**)&ve,     g_ve);
    cudaGetSymbolAddress((void**)&qkv,    g_qkv);
    cudaGetSymbolAddress((void**)&q,      g_q);
    cudaGetSymbolAddress((void**)&k,      g_k);
    cudaGetSymbolAddress((void**)&vt,     g_vt);
    cudaGetSymbolAddress((void**)&scores, g_scores);
    cudaGetSymbolAddress((void**)&p,      g_p);
    cudaGetSymbolAddress((void**)&att,    g_att);
    cudaGetSymbolAddress((void**)&hbuf,   g_hbuf);
    cudaGetSymbolAddress((void**)&qkvw,   g_qkvw);
    cudaGetSymbolAddress((void**)&aprojw, g_aprojw);
    cudaGetSymbolAddress((void**)&fcw,    g_fcw);
    cudaGetSymbolAddress((void**)&mprojw, g_mprojw);

    const int NTOK = B_ * T_;   // 4096

    // convert all weights to fp16 mirrors
    gpt_cvtw<<<2048, 256>>>(qkv_w,       qkvw,   (long)L_*3*H_*HD_*D_);
    gpt_cvtw<<<2048, 256>>>(attn_proj_w, aprojw, (long)L_*D_*H_*HD_);
    gpt_cvtw<<<2048, 256>>>(mlp_fc_w,    fcw,    (long)L_*4*D_*D_);
    gpt_cvtw<<<2048, 256>>>(mlp_proj_w,  mprojw, (long)L_*D_*4*D_);

    gpt_embed<<<NTOK, 256>>>(seq, embed_w, ve_w, x, x0, ve);

    for (int i = 0; i < L_; i++) {
        const float* skip = (i >= 6) ? (skips + (long)(11 - i) * BTD) : nullptr;
        gpt_resnorm<<<NTOK, 256>>>(x, x0, skip, scalars, i, xn);

        if (i != 7) {
            // qkv = xn @ W_qkv^T : [4096,768] x [2304,768]^T  -> half
            gpt_gemm<0,4><<<dim3(18, 16, 1), 512, SMEM4>>>(
                xn, qkvw + (long)i * 3 * H_ * HD_ * D_, qkv, nullptr,
                D_, D_, D_, 3*H_*HD_, 0, 0, 1, 0, 0, 1.f, 0);

            const float* vep = nullptr;
            if (i < 3)       vep = ve + (long)i * BTD;
            else if (i >= 9) vep = ve + (long)(i - 9) * BTD;
            gpt_rope<<<B_*T_*H_, 128>>>(qkv, vep, scalars, i, q, k, vt);

            // scores = 0.12 * Q K^T (causal): batched over 24 (b,h) -> fp32
            gpt_gemm<3,4><<<dim3(8, 4, B_*H_), 512, SMEM4>>>(
                q, k, scores, nullptr,
                HD_, HD_, HD_, T_,
                (long)T_*HD_, (long)T_*HD_, 1, (long)T_*T_, 0, 0.12f, 0);

            gpt_softmax<<<B_*H_*T_, 256>>>(scores, p);

            // att[b][t][h*128+hd] = P V : B = vT[b][h][hd][t], triangular K limit -> half
            gpt_gemm<0,2><<<dim3(1, 8, B_*H_), 256, SMEM2>>>(
                p, vt, att, nullptr,
                T_, T_, T_, D_,
                (long)T_*T_, (long)HD_*T_, H_, (long)T_*D_, (long)HD_, 1.f, 1);

            // x += att @ W_proj^T   (float accumulate)
            gpt_gemm<1,2><<<dim3(6, 32, 1), 256, SMEM2>>>(
                att, aprojw + (long)i * D_ * H_ * HD_, x, nullptr,
                H_*HD_, H_*HD_, H_*HD_, D_, 0, 0, 1, 0, 0, 1.f, 0);

            gpt_rmsnorm<<<NTOK, 256>>>(x, xn);
        }

        // h = relu(xn @ W_fc^T)^2 : [4096,768] x [3072,768]^T -> half
        gpt_gemm<2,4><<<dim3(24, 16, 1), 512, SMEM4>>>(
            xn, fcw + (long)i * 4 * D_ * D_, hbuf, nullptr,
            D_, D_, D_, 4*D_, 0, 0, 1, 0, 0, 1.f, 0);
        // x += h @ W_proj^T ; for i<6 also copy x into skip buffer
        if (i < 6) {
            gpt_gemm<4,2><<<dim3(6, 32, 1), 256, SMEM2>>>(
                hbuf, mprojw + (long)i * D_ * 4 * D_, x, skips + (long)i * BTD,
                4*D_, 4*D_, 4*D_, D_, 0, 0, 1, 0, 0, 1.f, 0);
        } else {
            gpt_gemm<1,2><<<dim3(6, 32, 1), 256, SMEM2>>>(
                hbuf, mprojw + (long)i * D_ * 4 * D_, x, nullptr,
                4*D_, 4*D_, 4*D_, D_, 0, 0, 1, 0, 0, 1.f, 0);
        }
    }

    gpt_finalnorm<<<NTOK, 256>>>(x, (float*)d_out);
}

// round 9
// speedup vs baseline: 5.0969x; 1.0132x over previous
#include <cuda_runtime.h>
#include <cuda_fp16.h>
#include <math.h>
#include <stdint.h>

#define B_  4
#define T_  1024
#define D_  768
#define H_  6
#define HD_ 128
#define L_  12
#define BTD (B_*T_*D_)          // 3145728
#define EPSF 1.1920929e-07f
#define BKH 32                  // k-halfs per tile (16 uint32 words)
#define NSTAGE 4

// ---------------- scratch (device globals; no allocation allowed) ----------------
__device__ float  g_x   [BTD];
__device__ float  g_x0  [BTD];
__device__ __half g_xn  [BTD];
__device__ float  g_skips[6*BTD];
__device__ float  g_ve  [3*BTD];
__device__ __half g_qkv [B_*T_*3*H_*HD_];      // [bt][which*768 + h*128 + hd]
__device__ __half g_q   [B_*H_*T_*HD_];        // [b][h][t][hd]
__device__ __half g_k   [B_*H_*T_*HD_];
__device__ __half g_vt  [B_*H_*HD_*T_];        // [b][h][hd][t]  (transposed V)
__device__ float  g_scores[B_*H_*T_*T_];       // [b][h][t][s]  fp32 scores
__device__ __half g_p   [B_*H_*T_*T_];         // softmax probs (half)
__device__ __half g_att [BTD];                 // [b][t][h*128+hd]
__device__ __half g_hbuf[B_*T_*4*D_];          // [bt][3072]
// fp16 weight mirrors
__device__ __half g_qkvw [L_*3*H_*HD_*D_];
__device__ __half g_aprojw[L_*D_*H_*HD_];
__device__ __half g_fcw  [L_*4*D_*D_];
__device__ __half g_mprojw[L_*D_*4*D_];

// ---------------- helpers ----------------
__device__ __forceinline__ float blockReduceSum256(float v, float* red) {
    int tid = threadIdx.x;
    red[tid] = v; __syncthreads();
    for (int s = 128; s > 0; s >>= 1) {
        if (tid < s) red[tid] += red[tid + s];
        __syncthreads();
    }
    float r = red[0]; __syncthreads();
    return r;
}

__device__ __forceinline__ void mma16(float* c, const uint32_t* a, const uint32_t* b) {
    asm volatile(
        "mma.sync.aligned.m16n8k16.row.col.f32.f16.f16.f32 "
        "{%0,%1,%2,%3}, {%4,%5,%6,%7}, {%8,%9}, {%0,%1,%2,%3};"
        : "+f"(c[0]), "+f"(c[1]), "+f"(c[2]), "+f"(c[3])
        : "r"(a[0]), "r"(a[1]), "r"(a[2]), "r"(a[3]), "r"(b[0]), "r"(b[1]));
}

__device__ __forceinline__ void cp16(uint32_t saddr, const void* gptr) {
    asm volatile("cp.async.cg.shared.global [%0], [%1], 16;" :: "r"(saddr), "l"(gptr));
}

// swizzle: column-group permutation within a 16-word row
__device__ __forceinline__ int swz(int r, int cg) { return cg ^ ((r >> 1) & 3); }

// ---------------- weight conversion fp32 -> fp16 (rne) ----------------
__global__ __launch_bounds__(256)
void gpt_cvtw(const float* __restrict__ src, __half* __restrict__ dst, long n)
{
    long i = ((long)blockIdx.x * 256 + threadIdx.x) * 4;
    long stride = (long)gridDim.x * 1024;
    for (; i < n; i += stride) {
        float4 v = *(const float4*)&src[i];
        __half2* d = (__half2*)&dst[i];
        d[0] = __floats2half2_rn(v.x, v.y);
        d[1] = __floats2half2_rn(v.z, v.w);
    }
}

// ---------------- embedding + norm + ve gather ----------------
__global__ __launch_bounds__(256)
void gpt_embed(const int* __restrict__ seq, const float* __restrict__ ew,
               const float* __restrict__ vew,
               float* __restrict__ x, float* __restrict__ x0, float* __restrict__ ve)
{
    __shared__ float red[256];
    int bt = blockIdx.x;
    int tid = threadIdx.x;
    int idx = seq[bt];
    const float* er = ew + (long)idx * D_;
    float a0 = er[tid], a1 = er[tid + 256], a2 = er[tid + 512];
    float ss = blockReduceSum256(a0*a0 + a1*a1 + a2*a2, red);
    float r = rsqrtf(ss / (float)D_ + EPSF);
    long o = (long)bt * D_;
    x0[o + tid]       = a0 * r;  x[o + tid]       = a0 * r;
    x0[o + tid + 256] = a1 * r;  x[o + tid + 256] = a1 * r;
    x0[o + tid + 512] = a2 * r;  x[o + tid + 512] = a2 * r;
    #pragma unroll
    for (int j = 0; j < 3; j++) {
        const float* vr = vew + ((long)j * 50257 + idx) * D_;
        float* vo = ve + ((long)j * (B_*T_) + bt) * D_;
        for (int d = tid; d < D_; d += 256) vo[d] = vr[d];
    }
}

// ------- fused residual + rms norm: x = l0*(x + sw*skip) + l1*x0 ; xn = h(norm(x))
__global__ __launch_bounds__(256)
void gpt_resnorm(float* __restrict__ x, const float* __restrict__ x0,
                 const float* __restrict__ skip, const float* __restrict__ scalars,
                 int layer, __half* __restrict__ xn)
{
    __shared__ float red[256];
    float l0 = scalars[L_ + 2*layer];
    float l1 = scalars[L_ + 2*layer + 1];
    float sw = skip ? scalars[layer - 6] : 0.f;
    int tid = threadIdx.x;
    long o = (long)blockIdx.x * D_;
    float a[3];
    #pragma unroll
    for (int j = 0; j < 3; j++) {
        long i = o + tid + j*256;
        float v = x[i];
        if (skip) v += sw * skip[i];
        v = l0 * v + l1 * x0[i];
        x[i] = v;
        a[j] = v;
    }
    float ss = blockReduceSum256(a[0]*a[0] + a[1]*a[1] + a[2]*a[2], red);
    float r = rsqrtf(ss / (float)D_ + EPSF);
    #pragma unroll
    for (int j = 0; j < 3; j++)
        xn[o + tid + j*256] = __float2half_rn(a[j] * r);
}

// ---------------- rms norm (row = 768), output fp16 ----------------
__global__ __launch_bounds__(256)
void gpt_rmsnorm(const float* __restrict__ x, __half* __restrict__ y)
{
    __shared__ float red[256];
    int tid = threadIdx.x;
    const float* xr = x + (long)blockIdx.x * D_;
    float a0 = xr[tid], a1 = xr[tid + 256], a2 = xr[tid + 512];
    float ss = blockReduceSum256(a0*a0 + a1*a1 + a2*a2, red);
    float r = rsqrtf(ss / (float)D_ + EPSF);
    __half* yr = y + (long)blockIdx.x * D_;
    yr[tid]       = __float2half_rn(a0 * r);
    yr[tid + 256] = __float2half_rn(a1 * r);
    yr[tid + 512] = __float2half_rn(a2 * r);
}

// ---------------- qk norm + rope + v mix; q,k -> [b][h][t][hd], v -> [b][h][hd][t]
__global__ __launch_bounds__(128)
void gpt_rope(const __half* __restrict__ qkv, const float* __restrict__ ve,
              const float* __restrict__ scalars, int layer,
              __half* __restrict__ q, __half* __restrict__ k, __half* __restrict__ vt)
{
    __shared__ float rq[128], rk[128], sq[128], sk[128];
    int z = blockIdx.x;
    int hd = threadIdx.x;
    int h = z % H_;
    int t = (z / H_) % T_;
    int b = z / (H_ * T_);
    long bt = (long)b * T_ + t;
    const __half* base = qkv + bt * (3*H_*HD_) + h * HD_;
    float qv = __half2float(base[hd]);
    float kv = __half2float(base[H_*HD_ + hd]);
    float vv = __half2float(base[2*H_*HD_ + hd]);

    rq[hd] = qv * qv; rk[hd] = kv * kv;
    __syncthreads();
    for (int s = 64; s > 0; s >>= 1) {
        if (hd < s) { rq[hd] += rq[hd + s]; rk[hd] += rk[hd + s]; }
        __syncthreads();
    }
    float rnq = rsqrtf(rq[0] / (float)HD_ + EPSF);
    float rnk = rsqrtf(rk[0] / (float)HD_ + EPSF);
    __syncthreads();
    sq[hd] = qv * rnq; sk[hd] = kv * rnk;
    __syncthreads();

    int j = hd & 63;
    float freq = (j < 32) ? exp2f(-10.0f * (float)j / 31.0f) : 0.0f;
    float sn, cs;
    sincosf((float)t * freq, &sn, &cs);
    float oq, ok;
    if (hd < 64) { oq =  sq[hd] * cs + sq[hd + 64] * sn;  ok =  sk[hd] * cs + sk[hd + 64] * sn; }
    else         { oq = -sq[hd - 64] * sn + sq[hd] * cs;  ok = -sk[hd - 64] * sn + sk[hd] * cs; }

    long o = (((long)b * H_ + h) * T_ + t) * HD_ + hd;
    q[o] = __float2half_rn(oq); k[o] = __float2half_rn(ok);

    float sa0 = scalars[3*L_ + 2*layer];
    float sa1 = scalars[3*L_ + 2*layer + 1];
    float vo = sa0 * vv;
    if (ve) vo += sa1 * ve[bt * D_ + h * HD_ + hd];
    vt[(((long)b * H_ + h) * HD_ + hd) * T_ + t] = __float2half_rn(vo);
}

// -------- causal softmax over row: only [0, r] is valid; zero-fill to 128-bdry ----
__global__ __launch_bounds__(256)
void gpt_softmax(const float* __restrict__ S, __half* __restrict__ P)
{
    __shared__ float red[256];
    int tid = threadIdx.x;
    int r = blockIdx.x % T_;        // row within (b,h)
    int valid = r + 1;
    int kend = ((r >> 7) + 1) << 7; // PV reads this row up to kend
    const float* p = S + (long)blockIdx.x * T_;
    __half* po = P + (long)blockIdx.x * T_;

    float v[4];
    float mx = -3.4e38f;
    #pragma unroll
    for (int j = 0; j < 4; j++) {
        int idx = tid + j*256;
        v[j] = (idx < valid) ? p[idx] : -3.4e38f;
        mx = fmaxf(mx, v[j]);
    }
    red[tid] = mx; __syncthreads();
    for (int s = 128; s > 0; s >>= 1) { if (tid < s) red[tid] = fmaxf(red[tid], red[tid+s]); __syncthreads(); }
    float m = red[0]; __syncthreads();
    float sum = 0.f;
    #pragma unroll
    for (int j = 0; j < 4; j++) {
        int idx = tid + j*256;
        v[j] = (idx < valid) ? __expf(v[j] - m) : 0.f;
        sum += v[j];
    }
    float tot = blockReduceSum256(sum, red);
    float inv = 1.0f / tot;
    #pragma unroll
    for (int j = 0; j < 4; j++) {
        int idx = tid + j*256;
        if (idx < valid) po[idx] = __float2half_rn(v[j] * inv);
    }
    // zero-fill (valid, kend) so triangular PV reads zeros
    for (int idx = valid + tid; idx < kend; idx += 256) po[idx] = __float2half(0.f);
}

// =================================================================================
// fp16 tensor-core GEMM (m16n8k16, fp32 accum), cp.async 4-stage pipeline.
// MT=4: 256x128 block tile, 512 threads (warp grid 4x4, warp tile 64x32)
// MT=2: 128x128 block tile, 256 threads (warp grid 2x4, warp tile 64x32), 2 CTA/SM
// C[m][n] = sum_k A[m][k] * B[n][k]   (both operands k-major half rows)
// EPI: 0=store half, 1=accumulate into float C, 2=relu^2 store half,
//      3=causal scores (alpha) float — masked blocks are NOT written,
//      4=accumulate + copy to float C2
// ktri: if 1, limit K to m0+BM (P upper triangle is zero)
// =================================================================================
template<int EPI, int MT>
__global__ void
__launch_bounds__(MT == 4 ? 512 : 256, MT == 4 ? 1 : 2)
gpt_gemm(const __half* __restrict__ A, const __half* __restrict__ Bm, void* __restrict__ Cv,
         float* __restrict__ C2,
         int K, int lda, int ldb, int ldc,
         long aZ, long bZ, int zdiv, long c1, long c2, float alpha, int ktri)
{
    constexpr int THREADS = (MT == 4) ? 512 : 256;
    constexpr int BM = MT * 64;
    constexpr int AROWS = THREADS / 4;     // rows staged per pass
    constexpr int APASS = BM / AROWS;      // 2
    constexpr int BPASS = 128 / AROWS;     // 1 (MT4) or 2 (MT2)

    const int m0 = blockIdx.y * BM, n0 = blockIdx.x * 128;
    if (EPI == 3 && n0 > m0 + (BM - 1)) return;   // fully masked: softmax never reads it

    int z = blockIdx.z;
    A  += (long)z * aZ;
    Bm += (long)z * bZ;
    long coff = (long)(z / zdiv) * c1 + (long)(z % zdiv) * c2;
    float*  Cf = (float*)Cv + coff;
    __half* Ch = (__half*)Cv + coff;
    if (EPI == 4) C2 += coff;

    const int tid  = threadIdx.x;
    const int lane = tid & 31, warp = tid >> 5;
    const int wm = warp >> 2, wn = warp & 3;
    const int g = lane >> 2, t = lane & 3;

    extern __shared__ uint32_t smem[];
    uint32_t* As = smem;                         // NSTAGE * BM*16 words
    uint32_t* Bs = smem + NSTAGE * BM * 16;      // NSTAGE * 128*16 words
    uint32_t as0 = (uint32_t)__cvta_generic_to_shared(As);
    uint32_t bs0 = (uint32_t)__cvta_generic_to_shared(Bs);

    int keff = K;
    if (ktri) { int kk = m0 + BM; keff = kk < K ? kk : K; }
    const int NT = keff / BKH;

    float acc[4][4][4];
    #pragma unroll
    for (int a = 0; a < 4; a++)
        #pragma unroll
        for (int b = 0; b < 4; b++)
            #pragma unroll
            for (int c = 0; c < 4; c++) acc[a][b][c] = 0.f;

    const int ar  = tid >> 2;
    const int acg = tid & 3;
    const __half* apB = A  + (long)(m0 + ar) * lda + acg*8;
    const __half* bpB = Bm + (long)(n0 + ar) * ldb + acg*8;

    auto issue = [&](int kt) {
        int s = kt % NSTAGE;
        const __half* ap = apB + kt*BKH;
        #pragma unroll
        for (int j = 0; j < APASS; j++) {
            int r = ar + AROWS*j;
            cp16(as0 + 4u*(s*BM*16 + r*16 + swz(r, acg)*4), ap + (long)(AROWS*j) * lda);
        }
        const __half* bp = bpB + kt*BKH;
        #pragma unroll
        for (int j = 0; j < BPASS; j++) {
            int r = ar + AROWS*j;
            cp16(bs0 + 4u*(s*128*16 + r*16 + swz(r, acg)*4), bp + (long)(AROWS*j) * ldb);
        }
        asm volatile("cp.async.commit_group;" ::: "memory");
    };

    issue(0); issue(1); issue(2);   // NT >= 4 always in this model

    for (int kt = 0; kt < NT; kt++) {
        if (kt + 1 >= NT)      asm volatile("cp.async.wait_group 0;" ::: "memory");
        else if (kt + 2 >= NT) asm volatile("cp.async.wait_group 1;" ::: "memory");
        else                   asm volatile("cp.async.wait_group 2;" ::: "memory");
        __syncthreads();

        const uint32_t* Ab = As + (kt % NSTAGE) * BM * 16;
        const uint32_t* Bb = Bs + (kt % NSTAGE) * 128 * 16;
        #pragma unroll
        for (int ks = 0; ks < 2; ks++) {
            uint32_t af[4][4];
            #pragma unroll
            for (int mi = 0; mi < 4; mi++) {
                int r0 = wm*64 + mi*16 + g;
                int s0 = swz(r0, ks*2)*4 + t;
                int s1 = swz(r0, ks*2 + 1)*4 + t;
                af[mi][0] = Ab[r0*16 + s0];
                af[mi][1] = Ab[(r0+8)*16 + s0];
                af[mi][2] = Ab[r0*16 + s1];
                af[mi][3] = Ab[(r0+8)*16 + s1];
            }
            uint32_t bf[4][2];
            #pragma unroll
            for (int ni = 0; ni < 4; ni++) {
                int nr = wn*32 + ni*8 + g;
                bf[ni][0] = Bb[nr*16 + swz(nr, ks*2)*4 + t];
                bf[ni][1] = Bb[nr*16 + swz(nr, ks*2 + 1)*4 + t];
            }
            #pragma unroll
            for (int mi = 0; mi < 4; mi++)
                #pragma unroll
                for (int ni = 0; ni < 4; ni++)
                    mma16(acc[mi][ni], af[mi], bf[ni]);
        }

        if (kt + NSTAGE - 1 < NT) issue(kt + NSTAGE - 1);
    }

    // ---- epilogue ----
    #pragma unroll
    for (int mi = 0; mi < 4; mi++) {
        int row = m0 + wm*64 + mi*16 + g;
        #pragma unroll
        for (int ni = 0; ni < 4; ni++) {
            int col = n0 + wn*32 + ni*8 + t*2;
            float* a4 = acc[mi][ni];
            #pragma unroll
            for (int half_ = 0; half_ < 2; half_++) {
                int r = row + half_ * 8;
                float c0 = a4[half_*2 + 0], c1 = a4[half_*2 + 1];
                if (EPI == 0) {
                    *(__half2*)&Ch[(long)r * ldc + col] = __floats2half2_rn(c0, c1);
                } else if (EPI == 2) {
                    float r0 = fmaxf(c0, 0.f), r1 = fmaxf(c1, 0.f);
                    *(__half2*)&Ch[(long)r * ldc + col] = __floats2half2_rn(r0*r0, r1*r1);
                } else if (EPI == 1 || EPI == 4) {
                    float* cp = &Cf[(long)r * ldc + col];
                    float2 o = *(float2*)cp;
                    float2 out = make_float2(o.x + c0, o.y + c1);
                    *(float2*)cp = out;
                    if (EPI == 4) *(float2*)&C2[(long)r * ldc + col] = out;
                } else {  // EPI == 3
                    float2 out;
                    out.x = (col + 0 <= r) ? alpha * c0 : -1e30f;
                    out.y = (col + 1 <= r) ? alpha * c1 : -1e30f;
                    *(float2*)&Cf[(long)r * ldc + col] = out;
                }
            }
        }
    }
}

// ---------------- final norm -> output ----------------
__global__ __launch_bounds__(256)
void gpt_finalnorm(const float* __restrict__ x, float* __restrict__ out)
{
    __shared__ float red[256];
    int tid = threadIdx.x;
    const float* xr = x + (long)blockIdx.x * D_;
    float a0 = xr[tid], a1 = xr[tid + 256], a2 = xr[tid + 512];
    float ss = blockReduceSum256(a0*a0 + a1*a1 + a2*a2, red);
    float r = rsqrtf(ss / (float)D_ + EPSF);
    float* yr = out + (long)blockIdx.x * D_;
    yr[tid] = a0 * r; yr[tid + 256] = a1 * r; yr[tid + 512] = a2 * r;
}

// ---------------- host orchestration ----------------
#define SMEM4 (NSTAGE * (256 + 128) * 16 * 4)   // 98304
#define SMEM2 (NSTAGE * (128 + 128) * 16 * 4)   // 65536

extern "C" void kernel_launch(void* const* d_in, const int* in_sizes, int n_in,
                              void* d_out, int out_size)
{
    const int*   seq         = (const int*)  d_in[0];
    const float* embed_w     = (const float*)d_in[1];
    const float* ve_w        = (const float*)d_in[2];
    const float* qkv_w       = (const float*)d_in[3];
    const float* attn_proj_w = (const float*)d_in[4];
    const float* mlp_fc_w    = (const float*)d_in[5];
    const float* mlp_proj_w  = (const float*)d_in[6];
    const float* scalars     = (const float*)d_in[7];

    cudaFuncSetAttribute(gpt_gemm<0,4>, cudaFuncAttributeMaxDynamicSharedMemorySize, SMEM4);
    cudaFuncSetAttribute(gpt_gemm<2,4>, cudaFuncAttributeMaxDynamicSharedMemorySize, SMEM4);
    cudaFuncSetAttribute(gpt_gemm<3,4>, cudaFuncAttributeMaxDynamicSharedMemorySize, SMEM4);
    cudaFuncSetAttribute(gpt_gemm<0,2>, cudaFuncAttributeMaxDynamicSharedMemorySize, SMEM2);
    cudaFuncSetAttribute(gpt_gemm<1,2>, cudaFuncAttributeMaxDynamicSharedMemorySize, SMEM2);
    cudaFuncSetAttribute(gpt_gemm<4,2>, cudaFuncAttributeMaxDynamicSharedMemorySize, SMEM2);

    float *x, *x0, *skips, *ve, *scores;
    __half *xn, *qkv, *q, *k, *vt, *p, *att, *hbuf;
    __half *qkvw, *aprojw, *fcw, *mprojw;
    cudaGetSymbolAddress((void**)&x,      g_x);
    cudaGetSymbolAddress((void**)&x0,     g_x0);
    cudaGetSymbolAddress((void**)&xn,     g_xn);
    cudaGetSymbolAddress((void**)&skips,  g_skips);
    cudaGetSymbolAddress((void**)&ve,     g_ve);
    cudaGetSymbolAddress((void**)&qkv,    g_qkv);
    cudaGetSymbolAddress((void**)&q,      g_q);
    cudaGetSymbolAddress((void**)&k,      g_k);
    cudaGetSymbolAddress((void**)&vt,     g_vt);
    cudaGetSymbolAddress((void**)&scores, g_scores);
    cudaGetSymbolAddress((void**)&p,      g_p);
    cudaGetSymbolAddress((void**)&att,    g_att);
    cudaGetSymbolAddress((void**)&hbuf,   g_hbuf);
    cudaGetSymbolAddress((void**)&qkvw,   g_qkvw);
    cudaGetSymbolAddress((void**)&aprojw, g_aprojw);
    cudaGetSymbolAddress((void**)&fcw,    g_fcw);
    cudaGetSymbolAddress((void**)&mprojw, g_mprojw);

    const int NTOK = B_ * T_;   // 4096

    // convert all weights to fp16 mirrors
    gpt_cvtw<<<2048, 256>>>(qkv_w,       qkvw,   (long)L_*3*H_*HD_*D_);
    gpt_cvtw<<<2048, 256>>>(attn_proj_w, aprojw, (long)L_*D_*H_*HD_);
    gpt_cvtw<<<2048, 256>>>(mlp_fc_w,    fcw,    (long)L_*4*D_*D_);
    gpt_cvtw<<<2048, 256>>>(mlp_proj_w,  mprojw, (long)L_*D_*4*D_);

    gpt_embed<<<NTOK, 256>>>(seq, embed_w, ve_w, x, x0, ve);

    for (int i = 0; i < L_; i++) {
        const float* skip = (i >= 6) ? (skips + (long)(11 - i) * BTD) : nullptr;
        gpt_resnorm<<<NTOK, 256>>>(x, x0, skip, scalars, i, xn);

        if (i != 7) {
            // qkv = xn @ W_qkv^T : [4096,768] x [2304,768]^T  -> half
            gpt_gemm<0,4><<<dim3(18, 16, 1), 512, SMEM4>>>(
                xn, qkvw + (long)i * 3 * H_ * HD_ * D_, qkv, nullptr,
                D_, D_, D_, 3*H_*HD_, 0, 0, 1, 0, 0, 1.f, 0);

            const float* vep = nullptr;
            if (i < 3)       vep = ve + (long)i * BTD;
            else if (i >= 9) vep = ve + (long)(i - 9) * BTD;
            gpt_rope<<<B_*T_*H_, 128>>>(qkv, vep, scalars, i, q, k, vt);

            // scores = 0.12 * Q K^T (causal): batched over 24 (b,h) -> fp32
            gpt_gemm<3,4><<<dim3(8, 4, B_*H_), 512, SMEM4>>>(
                q, k, scores, nullptr,
                HD_, HD_, HD_, T_,
                (long)T_*HD_, (long)T_*HD_, 1, (long)T_*T_, 0, 0.12f, 0);

            gpt_softmax<<<B_*H_*T_, 256>>>(scores, p);

            // att[b][t][h*128+hd] = P V : B = vT[b][h][hd][t], triangular K limit -> half
            gpt_gemm<0,2><<<dim3(1, 8, B_*H_), 256, SMEM2>>>(
                p, vt, att, nullptr,
                T_, T_, T_, D_,
                (long)T_*T_, (long)HD_*T_, H_, (long)T_*D_, (long)HD_, 1.f, 1);

            // x += att @ W_proj^T   (float accumulate)
            gpt_gemm<1,2><<<dim3(6, 32, 1), 256, SMEM2>>>(
                att, aprojw + (long)i * D_ * H_ * HD_, x, nullptr,
                H_*HD_, H_*HD_, H_*HD_, D_, 0, 0, 1, 0, 0, 1.f, 0);

            gpt_rmsnorm<<<NTOK, 256>>>(x, xn);
        }

        // h = relu(xn @ W_fc^T)^2 : [4096,768] x [3072,768]^T -> half
        gpt_gemm<2,4><<<dim3(24, 16, 1), 512, SMEM4>>>(
            xn, fcw + (long)i * 4 * D_ * D_, hbuf, nullptr,
            D_, D_, D_, 4*D_, 0, 0, 1, 0, 0, 1.f, 0);
        // x += h @ W_proj^T ; for i<6 also copy x into skip buffer
        if (i < 6) {
            gpt_gemm<4,2><<<dim3(6, 32, 1), 256, SMEM2>>>(
                hbuf, mprojw + (long)i * D_ * 4 * D_, x, skips + (long)i * BTD,
                4*D_, 4*D_, 4*D_, D_, 0, 0, 1, 0, 0, 1.f, 0);
        } else {
            gpt_gemm<1,2><<<dim3(6, 32, 1), 256, SMEM2>>>(
                hbuf, mprojw + (long)i * D_ * 4 * D_, x, nullptr,
                4*D_, 4*D_, 4*D_, D_, 0, 0, 1, 0, 0, 1.f, 0);
        }
    }

    gpt_finalnorm<<<NTOK, 256>>>(x, (float*)d_out);
}

// round 10
// speedup vs baseline: 6.0699x; 1.1909x over previous
#include <cuda_runtime.h>
#include <cuda_fp16.h>
#include <math.h>
#include <stdint.h>

#define B_  4
#define T_  1024
#define D_  768
#define H_  6
#define HD_ 128
#define L_  12
#define BTD (B_*T_*D_)          // 3145728
#define EPSF 1.1920929e-07f
#define BKH 32                  // k-halfs per tile (16 uint32 words)
#define NSTAGE 4

// ---------------- scratch (device globals; no allocation allowed) ----------------
__device__ float  g_x   [BTD];
__device__ float  g_x0  [BTD];
__device__ __half g_xn  [BTD];
__device__ float  g_skips[6*BTD];
__device__ float  g_ve  [3*BTD];
__device__ __half g_qkv [B_*T_*3*H_*HD_];      // [bt][which*768 + h*128 + hd]
__device__ __half g_q   [B_*H_*T_*HD_];        // [b][h][t][hd]
__device__ __half g_k   [B_*H_*T_*HD_];
__device__ __half g_vt  [B_*H_*HD_*T_];        // [b][h][hd][t]  (transposed V)
__device__ __half g_att [BTD];                 // [b][t][h*128+hd]
__device__ __half g_hbuf[B_*T_*4*D_];          // [bt][3072]
// fp16 weight mirrors
__device__ __half g_qkvw [L_*3*H_*HD_*D_];
__device__ __half g_aprojw[L_*D_*H_*HD_];
__device__ __half g_fcw  [L_*4*D_*D_];
__device__ __half g_mprojw[L_*D_*4*D_];

// ---------------- helpers ----------------
__device__ __forceinline__ float blockReduceSum256(float v, float* red) {
    int tid = threadIdx.x;
    red[tid] = v; __syncthreads();
    for (int s = 128; s > 0; s >>= 1) {
        if (tid < s) red[tid] += red[tid + s];
        __syncthreads();
    }
    float r = red[0]; __syncthreads();
    return r;
}

__device__ __forceinline__ void mma16(float* c, const uint32_t* a, const uint32_t* b) {
    asm volatile(
        "mma.sync.aligned.m16n8k16.row.col.f32.f16.f16.f32 "
        "{%0,%1,%2,%3}, {%4,%5,%6,%7}, {%8,%9}, {%0,%1,%2,%3};"
        : "+f"(c[0]), "+f"(c[1]), "+f"(c[2]), "+f"(c[3])
        : "r"(a[0]), "r"(a[1]), "r"(a[2]), "r"(a[3]), "r"(b[0]), "r"(b[1]));
}

__device__ __forceinline__ void cp16(uint32_t saddr, const void* gptr) {
    asm volatile("cp.async.cg.shared.global [%0], [%1], 16;" :: "r"(saddr), "l"(gptr));
}

// swizzle: column-group permutation within a 16-word row
__device__ __forceinline__ int swz(int r, int cg) { return cg ^ ((r >> 1) & 3); }

__device__ __forceinline__ uint32_t packh2(float a, float b) {
    __half2 h = __floats2half2_rn(a, b);
    return *(uint32_t*)&h;
}

// ---------------- weight conversion fp32 -> fp16 (rne) ----------------
__global__ __launch_bounds__(256)
void gpt_cvtw(const float* __restrict__ src, __half* __restrict__ dst, long n)
{
    long i = ((long)blockIdx.x * 256 + threadIdx.x) * 4;
    long stride = (long)gridDim.x * 1024;
    for (; i < n; i += stride) {
        float4 v = *(const float4*)&src[i];
        __half2* d = (__half2*)&dst[i];
        d[0] = __floats2half2_rn(v.x, v.y);
        d[1] = __floats2half2_rn(v.z, v.w);
    }
}

// ---------------- embedding + norm + ve gather ----------------
__global__ __launch_bounds__(256)
void gpt_embed(const int* __restrict__ seq, const float* __restrict__ ew,
               const float* __restrict__ vew,
               float* __restrict__ x, float* __restrict__ x0, float* __restrict__ ve)
{
    __shared__ float red[256];
    int bt = blockIdx.x;
    int tid = threadIdx.x;
    int idx = seq[bt];
    const float* er = ew + (long)idx * D_;
    float a0 = er[tid], a1 = er[tid + 256], a2 = er[tid + 512];
    float ss = blockReduceSum256(a0*a0 + a1*a1 + a2*a2, red);
    float r = rsqrtf(ss / (float)D_ + EPSF);
    long o = (long)bt * D_;
    x0[o + tid]       = a0 * r;  x[o + tid]       = a0 * r;
    x0[o + tid + 256] = a1 * r;  x[o + tid + 256] = a1 * r;
    x0[o + tid + 512] = a2 * r;  x[o + tid + 512] = a2 * r;
    #pragma unroll
    for (int j = 0; j < 3; j++) {
        const float* vr = vew + ((long)j * 50257 + idx) * D_;
        float* vo = ve + ((long)j * (B_*T_) + bt) * D_;
        for (int d = tid; d < D_; d += 256) vo[d] = vr[d];
    }
}

// ------- fused residual + rms norm: x = l0*(x + sw*skip) + l1*x0 ; xn = h(norm(x))
__global__ __launch_bounds__(256)
void gpt_resnorm(float* __restrict__ x, const float* __restrict__ x0,
                 const float* __restrict__ skip, const float* __restrict__ scalars,
                 int layer, __half* __restrict__ xn)
{
    __shared__ float red[256];
    float l0 = scalars[L_ + 2*layer];
    float l1 = scalars[L_ + 2*layer + 1];
    float sw = skip ? scalars[layer - 6] : 0.f;
    int tid = threadIdx.x;
    long o = (long)blockIdx.x * D_;
    float a[3];
    #pragma unroll
    for (int j = 0; j < 3; j++) {
        long i = o + tid + j*256;
        float v = x[i];
        if (skip) v += sw * skip[i];
        v = l0 * v + l1 * x0[i];
        x[i] = v;
        a[j] = v;
    }
    float ss = blockReduceSum256(a[0]*a[0] + a[1]*a[1] + a[2]*a[2], red);
    float r = rsqrtf(ss / (float)D_ + EPSF);
    #pragma unroll
    for (int j = 0; j < 3; j++)
        xn[o + tid + j*256] = __float2half_rn(a[j] * r);
}

// ---------------- rms norm (row = 768), output fp16 ----------------
__global__ __launch_bounds__(256)
void gpt_rmsnorm(const float* __restrict__ x, __half* __restrict__ y)
{
    __shared__ float red[256];
    int tid = threadIdx.x;
    const float* xr = x + (long)blockIdx.x * D_;
    float a0 = xr[tid], a1 = xr[tid + 256], a2 = xr[tid + 512];
    float ss = blockReduceSum256(a0*a0 + a1*a1 + a2*a2, red);
    float r = rsqrtf(ss / (float)D_ + EPSF);
    __half* yr = y + (long)blockIdx.x * D_;
    yr[tid]       = __float2half_rn(a0 * r);
    yr[tid + 256] = __float2half_rn(a1 * r);
    yr[tid + 512] = __float2half_rn(a2 * r);
}

// ---------------- qk norm + rope + v mix; q,k -> [b][h][t][hd], v -> [b][h][hd][t]
__global__ __launch_bounds__(128)
void gpt_rope(const __half* __restrict__ qkv, const float* __restrict__ ve,
              const float* __restrict__ scalars, int layer,
              __half* __restrict__ q, __half* __restrict__ k, __half* __restrict__ vt)
{
    __shared__ float rq[128], rk[128], sq[128], sk[128];
    int z = blockIdx.x;
    int hd = threadIdx.x;
    int h = z % H_;
    int t = (z / H_) % T_;
    int b = z / (H_ * T_);
    long bt = (long)b * T_ + t;
    const __half* base = qkv + bt * (3*H_*HD_) + h * HD_;
    float qv = __half2float(base[hd]);
    float kv = __half2float(base[H_*HD_ + hd]);
    float vv = __half2float(base[2*H_*HD_ + hd]);

    rq[hd] = qv * qv; rk[hd] = kv * kv;
    __syncthreads();
    for (int s = 64; s > 0; s >>= 1) {
        if (hd < s) { rq[hd] += rq[hd + s]; rk[hd] += rk[hd + s]; }
        __syncthreads();
    }
    float rnq = rsqrtf(rq[0] / (float)HD_ + EPSF);
    float rnk = rsqrtf(rk[0] / (float)HD_ + EPSF);
    __syncthreads();
    sq[hd] = qv * rnq; sk[hd] = kv * rnk;
    __syncthreads();

    int j = hd & 63;
    float freq = (j < 32) ? exp2f(-10.0f * (float)j / 31.0f) : 0.0f;
    float sn, cs;
    sincosf((float)t * freq, &sn, &cs);
    float oq, ok;
    if (hd < 64) { oq =  sq[hd] * cs + sq[hd + 64] * sn;  ok =  sk[hd] * cs + sk[hd + 64] * sn; }
    else         { oq = -sq[hd - 64] * sn + sq[hd] * cs;  ok = -sk[hd - 64] * sn + sk[hd] * cs; }

    long o = (((long)b * H_ + h) * T_ + t) * HD_ + hd;
    q[o] = __float2half_rn(oq); k[o] = __float2half_rn(ok);

    float sa0 = scalars[3*L_ + 2*layer];
    float sa1 = scalars[3*L_ + 2*layer + 1];
    float vo = sa0 * vv;
    if (ve) vo += sa1 * ve[bt * D_ + h * HD_ + hd];
    vt[(((long)b * H_ + h) * HD_ + hd) * T_ + t] = __float2half_rn(vo);
}

// =================================================================================
// Fused flash attention: 64 q-rows per CTA (4 warps), K/V tiles of 64, online
// softmax, double-buffered cp.async K/V. Q/K: [b][h][t][hd]; V: [b][h][hd][t].
// Output att[b][t][h*128+hd] (half), already softmax-normalized.
// =================================================================================
__global__ void __launch_bounds__(128, 1)
gpt_flash(const __half* __restrict__ Q, const __half* __restrict__ K,
          const __half* __restrict__ Vt, __half* __restrict__ att)
{
    const int qt = 15 - blockIdx.x;           // heavy tiles first
    const int bh = blockIdx.y;
    const int b = bh / H_, h = bh % H_;
    const int tid = threadIdx.x;
    const int w = tid >> 5, lane = tid & 31;
    const int g = lane >> 2, t = lane & 3;

    const __half* Qb = Q  + (((long)bh * T_) + qt*64) * HD_;
    const __half* Kb = K  + (long)bh * T_ * HD_;
    const __half* Vb = Vt + (long)bh * HD_ * T_;

    extern __shared__ uint32_t sm[];
    // words: Qs [4 kc][64 rows][16]  = 4096  @ 0
    //        KV buf s (s=0,1): K [4 kc][64][16] = 4096 @ 4096+s*8192
    //                          V [2 kc][128][16] = 4096 @ 8192+s*8192
    uint32_t sbase = (uint32_t)__cvta_generic_to_shared(sm);

    // ---- load Q (64 rows x 256B = 1024 x 16B), one group ----
    #pragma unroll
    for (int j = 0; j < 8; j++) {
        int i = tid + j*128;                  // 0..1023
        int row = i >> 4, c16 = i & 15;
        int kc = c16 >> 2, wg = c16 & 3;
        uint32_t word = (kc*64 + row)*16 + swz(row, wg)*4;
        cp16(sbase + 4u*word, Qb + row*HD_ + c16*8);
    }
    asm volatile("cp.async.commit_group;" ::: "memory");

    const int NT = qt + 1;

    auto issueKV = [&](int kt) {
        int s = kt & 1;
        uint32_t kw0 = 4096 + s*8192;
        #pragma unroll
        for (int j = 0; j < 8; j++) {
            int i = tid + j*128;
            int row = i >> 4, c16 = i & 15;
            int kc = c16 >> 2, wg = c16 & 3;
            uint32_t word = kw0 + (kc*64 + row)*16 + swz(row, wg)*4;
            cp16(sbase + 4u*word, Kb + (long)(kt*64 + row)*HD_ + c16*8);
        }
        uint32_t vw0 = 8192 + s*8192;
        #pragma unroll
        for (int j = 0; j < 8; j++) {
            int i = tid + j*128;
            int row = i >> 3, c16 = i & 7;
            int kc = c16 >> 2, wg = c16 & 3;
            uint32_t word = vw0 + (kc*128 + row)*16 + swz(row, wg)*4;
            cp16(sbase + 4u*word, Vb + (long)row*T_ + kt*64 + c16*8);
        }
        asm volatile("cp.async.commit_group;" ::: "memory");
    };

    issueKV(0);
    if (NT > 1) issueKV(1);

    float m0 = -1e30f, m1 = -1e30f, l0 = 0.f, l1 = 0.f;
    float oacc[16][4];
    #pragma unroll
    for (int a = 0; a < 16; a++)
        #pragma unroll
        for (int c = 0; c < 4; c++) oacc[a][c] = 0.f;

    const int r0 = w*16 + g;                  // warp-local q row (and +8)
    const int grow = qt*64 + r0;

    for (int kt = 0; kt < NT; kt++) {
        if (kt + 1 < NT) asm volatile("cp.async.wait_group 1;" ::: "memory");
        else             asm volatile("cp.async.wait_group 0;" ::: "memory");
        __syncthreads();

        const uint32_t* Kc = sm + 4096 + (kt & 1)*8192;
        const uint32_t* Vc = sm + 8192 + (kt & 1)*8192;

        // ---- S = Q K^T (warp: 16 rows x 64 cols) ----
        float sacc[8][4];
        #pragma unroll
        for (int a = 0; a < 8; a++)
            #pragma unroll
            for (int c = 0; c < 4; c++) sacc[a][c] = 0.f;

        #pragma unroll
        for (int kc = 0; kc < 4; kc++) {
            const uint32_t* Qc = sm + kc*1024;
            const uint32_t* Kk = Kc + kc*1024;
            #pragma unroll
            for (int ks = 0; ks < 2; ks++) {
                int s0 = swz(r0, ks*2)*4 + t;
                int s1 = swz(r0, ks*2 + 1)*4 + t;
                uint32_t af[4];
                af[0] = Qc[r0*16 + s0];
                af[1] = Qc[(r0+8)*16 + s0];
                af[2] = Qc[r0*16 + s1];
                af[3] = Qc[(r0+8)*16 + s1];
                #pragma unroll
                for (int ni = 0; ni < 8; ni++) {
                    int nr = ni*8 + g;
                    uint32_t bf[2];
                    bf[0] = Kk[nr*16 + swz(nr, ks*2)*4 + t];
                    bf[1] = Kk[nr*16 + swz(nr, ks*2 + 1)*4 + t];
                    mma16(sacc[ni], af, bf);
                }
            }
        }

        // ---- scale + causal mask (diag tile only) ----
        bool diag = (kt == qt);
        #pragma unroll
        for (int ni = 0; ni < 8; ni++) {
            int col = kt*64 + ni*8 + t*2;
            float v0 = 0.12f * sacc[ni][0];
            float v1 = 0.12f * sacc[ni][1];
            float v2 = 0.12f * sacc[ni][2];
            float v3 = 0.12f * sacc[ni][3];
            if (diag) {
                if (col     > grow)     v0 = -1e30f;
                if (col + 1 > grow)     v1 = -1e30f;
                if (col     > grow + 8) v2 = -1e30f;
                if (col + 1 > grow + 8) v3 = -1e30f;
            }
            sacc[ni][0] = v0; sacc[ni][1] = v1; sacc[ni][2] = v2; sacc[ni][3] = v3;
        }

        // ---- online softmax (rows g and g+8) ----
        float rm0 = -1e30f, rm1 = -1e30f;
        #pragma unroll
        for (int ni = 0; ni < 8; ni++) {
            rm0 = fmaxf(rm0, fmaxf(sacc[ni][0], sacc[ni][1]));
            rm1 = fmaxf(rm1, fmaxf(sacc[ni][2], sacc[ni][3]));
        }
        rm0 = fmaxf(rm0, __shfl_xor_sync(0xffffffff, rm0, 1));
        rm0 = fmaxf(rm0, __shfl_xor_sync(0xffffffff, rm0, 2));
        rm1 = fmaxf(rm1, __shfl_xor_sync(0xffffffff, rm1, 1));
        rm1 = fmaxf(rm1, __shfl_xor_sync(0xffffffff, rm1, 2));

        float mn0 = fmaxf(m0, rm0), mn1 = fmaxf(m1, rm1);
        float sc0 = __expf(m0 - mn0), sc1 = __expf(m1 - mn1);
        m0 = mn0; m1 = mn1;

        float ls0 = 0.f, ls1 = 0.f;
        uint32_t phg[8], phg8[8];
        #pragma unroll
        for (int ni = 0; ni < 8; ni++) {
            float p0 = __expf(sacc[ni][0] - mn0);
            float p1 = __expf(sacc[ni][1] - mn0);
            float p2 = __expf(sacc[ni][2] - mn1);
            float p3 = __expf(sacc[ni][3] - mn1);
            ls0 += p0 + p1; ls1 += p2 + p3;
            phg[ni]  = packh2(p0, p1);
            phg8[ni] = packh2(p2, p3);
        }
        ls0 += __shfl_xor_sync(0xffffffff, ls0, 1);
        ls0 += __shfl_xor_sync(0xffffffff, ls0, 2);
        ls1 += __shfl_xor_sync(0xffffffff, ls1, 1);
        ls1 += __shfl_xor_sync(0xffffffff, ls1, 2);
        l0 = l0*sc0 + ls0;
        l1 = l1*sc1 + ls1;

        #pragma unroll
        for (int ni = 0; ni < 16; ni++) {
            oacc[ni][0] *= sc0; oacc[ni][1] *= sc0;
            oacc[ni][2] *= sc1; oacc[ni][3] *= sc1;
        }

        // ---- O += P V  (P A-fragments from registers; V n=128, k=64) ----
        #pragma unroll
        for (int kk = 0; kk < 4; kk++) {
            uint32_t af[4] = { phg[2*kk], phg8[2*kk], phg[2*kk+1], phg8[2*kk+1] };
            const uint32_t* Vk = Vc + (kk >> 1)*2048;
            int ks = kk & 1;
            #pragma unroll
            for (int ni = 0; ni < 16; ni++) {
                int nr = ni*8 + g;
                uint32_t bf[2];
                bf[0] = Vk[nr*16 + swz(nr, ks*2)*4 + t];
                bf[1] = Vk[nr*16 + swz(nr, ks*2 + 1)*4 + t];
                mma16(oacc[ni], af, bf);
            }
        }

        __syncthreads();
        if (kt + 2 < NT) issueKV(kt + 2);
    }

    // ---- epilogue: att[b][q][h*128+col] = O / l ----
    float inv0 = 1.f / l0, inv1 = 1.f / l1;
    long base0 = ((long)b*T_ + grow) * D_ + h*HD_;
    long base1 = base0 + 8L*D_;
    #pragma unroll
    for (int ni = 0; ni < 16; ni++) {
        int col = ni*8 + t*2;
        *(uint32_t*)&att[base0 + col] = packh2(oacc[ni][0]*inv0, oacc[ni][1]*inv0);
        *(uint32_t*)&att[base1 + col] = packh2(oacc[ni][2]*inv1, oacc[ni][3]*inv1);
    }
}

// =================================================================================
// fp16 tensor-core GEMM (m16n8k16, fp32 accum), cp.async 4-stage pipeline.
// MT=4: 256x128 block tile, 512 threads; MT=2: 128x128 block tile, 256 threads.
// C[m][n] = sum_k A[m][k] * B[n][k]
// EPI: 0=store half, 1=accumulate into float C, 2=relu^2 store half,
//      4=accumulate + copy to float C2
// =================================================================================
template<int EPI, int MT>
__global__ void
__launch_bounds__(MT == 4 ? 512 : 256, MT == 4 ? 1 : 2)
gpt_gemm(const __half* __restrict__ A, const __half* __restrict__ Bm, void* __restrict__ Cv,
         float* __restrict__ C2,
         int K, int lda, int ldb, int ldc,
         long aZ, long bZ, int zdiv, long c1, long c2, float alpha, int ktri)
{
    constexpr int THREADS = (MT == 4) ? 512 : 256;
    constexpr int BM = MT * 64;
    constexpr int AROWS = THREADS / 4;
    constexpr int APASS = BM / AROWS;
    constexpr int BPASS = 128 / AROWS;

    const int m0 = blockIdx.y * BM, n0 = blockIdx.x * 128;

    int z = blockIdx.z;
    A  += (long)z * aZ;
    Bm += (long)z * bZ;
    long coff = (long)(z / zdiv) * c1 + (long)(z % zdiv) * c2;
    float*  Cf = (float*)Cv + coff;
    __half* Ch = (__half*)Cv + coff;
    if (EPI == 4) C2 += coff;

    const int tid  = threadIdx.x;
    const int lane = tid & 31, warp = tid >> 5;
    const int wm = warp >> 2, wn = warp & 3;
    const int g = lane >> 2, t = lane & 3;

    extern __shared__ uint32_t smem[];
    uint32_t* As = smem;
    uint32_t* Bs = smem + NSTAGE * BM * 16;
    uint32_t as0 = (uint32_t)__cvta_generic_to_shared(As);
    uint32_t bs0 = (uint32_t)__cvta_generic_to_shared(Bs);

    int keff = K;
    if (ktri) { int kk = m0 + BM; keff = kk < K ? kk : K; }
    const int NT = keff / BKH;

    float acc[4][4][4];
    #pragma unroll
    for (int a = 0; a < 4; a++)
        #pragma unroll
        for (int b = 0; b < 4; b++)
            #pragma unroll
            for (int c = 0; c < 4; c++) acc[a][b][c] = 0.f;

    const int ar  = tid >> 2;
    const int acg = tid & 3;
    const __half* apB = A  + (long)(m0 + ar) * lda + acg*8;
    const __half* bpB = Bm + (long)(n0 + ar) * ldb + acg*8;

    auto issue = [&](int kt) {
        int s = kt % NSTAGE;
        const __half* ap = apB + kt*BKH;
        #pragma unroll
        for (int j = 0; j < APASS; j++) {
            int r = ar + AROWS*j;
            cp16(as0 + 4u*(s*BM*16 + r*16 + swz(r, acg)*4), ap + (long)(AROWS*j) * lda);
        }
        const __half* bp = bpB + kt*BKH;
        #pragma unroll
        for (int j = 0; j < BPASS; j++) {
            int r = ar + AROWS*j;
            cp16(bs0 + 4u*(s*128*16 + r*16 + swz(r, acg)*4), bp + (long)(AROWS*j) * ldb);
        }
        asm volatile("cp.async.commit_group;" ::: "memory");
    };

    issue(0); issue(1); issue(2);

    for (int kt = 0; kt < NT; kt++) {
        if (kt + 1 >= NT)      asm volatile("cp.async.wait_group 0;" ::: "memory");
        else if (kt + 2 >= NT) asm volatile("cp.async.wait_group 1;" ::: "memory");
        else                   asm volatile("cp.async.wait_group 2;" ::: "memory");
        __syncthreads();

        const uint32_t* Ab = As + (kt % NSTAGE) * BM * 16;
        const uint32_t* Bb = Bs + (kt % NSTAGE) * 128 * 16;
        #pragma unroll
        for (int ks = 0; ks < 2; ks++) {
            uint32_t af[4][4];
            #pragma unroll
            for (int mi = 0; mi < 4; mi++) {
                int r0 = wm*64 + mi*16 + g;
                int s0 = swz(r0, ks*2)*4 + t;
                int s1 = swz(r0, ks*2 + 1)*4 + t;
                af[mi][0] = Ab[r0*16 + s0];
                af[mi][1] = Ab[(r0+8)*16 + s0];
                af[mi][2] = Ab[r0*16 + s1];
                af[mi][3] = Ab[(r0+8)*16 + s1];
            }
            uint32_t bf[4][2];
            #pragma unroll
            for (int ni = 0; ni < 4; ni++) {
                int nr = wn*32 + ni*8 + g;
                bf[ni][0] = Bb[nr*16 + swz(nr, ks*2)*4 + t];
                bf[ni][1] = Bb[nr*16 + swz(nr, ks*2 + 1)*4 + t];
            }
            #pragma unroll
            for (int mi = 0; mi < 4; mi++)
                #pragma unroll
                for (int ni = 0; ni < 4; ni++)
                    mma16(acc[mi][ni], af[mi], bf[ni]);
        }

        if (kt + NSTAGE - 1 < NT) issue(kt + NSTAGE - 1);
    }

    // ---- epilogue ----
    #pragma unroll
    for (int mi = 0; mi < 4; mi++) {
        int row = m0 + wm*64 + mi*16 + g;
        #pragma unroll
        for (int ni = 0; ni < 4; ni++) {
            int col = n0 + wn*32 + ni*8 + t*2;
            float* a4 = acc[mi][ni];
            #pragma unroll
            for (int half_ = 0; half_ < 2; half_++) {
                int r = row + half_ * 8;
                float c0 = a4[half_*2 + 0], c1 = a4[half_*2 + 1];
                if (EPI == 0) {
                    *(__half2*)&Ch[(long)r * ldc + col] = __floats2half2_rn(c0, c1);
                } else if (EPI == 2) {
                    float r0 = fmaxf(c0, 0.f), r1 = fmaxf(c1, 0.f);
                    *(__half2*)&Ch[(long)r * ldc + col] = __floats2half2_rn(r0*r0, r1*r1);
                } else {
                    float* cp = &Cf[(long)r * ldc + col];
                    float2 o = *(float2*)cp;
                    float2 out = make_float2(o.x + c0, o.y + c1);
                    *(float2*)cp = out;
                    if (EPI == 4) *(float2*)&C2[(long)r * ldc + col] = out;
                }
            }
        }
    }
}

// ---------------- final norm -> output ----------------
__global__ __launch_bounds__(256)
void gpt_finalnorm(const float* __restrict__ x, float* __restrict__ out)
{
    __shared__ float red[256];
    int tid = threadIdx.x;
    const float* xr = x + (long)blockIdx.x * D_;
    float a0 = xr[tid], a1 = xr[tid + 256], a2 = xr[tid + 512];
    float ss = blockReduceSum256(a0*a0 + a1*a1 + a2*a2, red);
    float r = rsqrtf(ss / (float)D_ + EPSF);
    float* yr = out + (long)blockIdx.x * D_;
    yr[tid] = a0 * r; yr[tid + 256] = a1 * r; yr[tid + 512] = a2 * r;
}

// ---------------- host orchestration ----------------
#define SMEM4 (NSTAGE * (256 + 128) * 16 * 4)   // 98304
#define SMEM2 (NSTAGE * (128 + 128) * 16 * 4)   // 65536
#define SMEMF ((4096 + 2*8192) * 4)             // 81920 (flash)

extern "C" void kernel_launch(void* const* d_in, const int* in_sizes, int n_in,
                              void* d_out, int out_size)
{
    const int*   seq         = (const int*)  d_in[0];
    const float* embed_w     = (const float*)d_in[1];
    const float* ve_w        = (const float*)d_in[2];
    const float* qkv_w       = (const float*)d_in[3];
    const float* attn_proj_w = (const float*)d_in[4];
    const float* mlp_fc_w    = (const float*)d_in[5];
    const float* mlp_proj_w  = (const float*)d_in[6];
    const float* scalars     = (const float*)d_in[7];

    cudaFuncSetAttribute(gpt_gemm<0,4>, cudaFuncAttributeMaxDynamicSharedMemorySize, SMEM4);
    cudaFuncSetAttribute(gpt_gemm<2,4>, cudaFuncAttributeMaxDynamicSharedMemorySize, SMEM4);
    cudaFuncSetAttribute(gpt_gemm<1,2>, cudaFuncAttributeMaxDynamicSharedMemorySize, SMEM2);
    cudaFuncSetAttribute(gpt_gemm<4,2>, cudaFuncAttributeMaxDynamicSharedMemorySize, SMEM2);
    cudaFuncSetAttribute(gpt_flash,     cudaFuncAttributeMaxDynamicSharedMemorySize, SMEMF);

    float *x, *x0, *skips, *ve;
    __half *xn, *qkv, *q, *k, *vt, *att, *hbuf;
    __half *qkvw, *aprojw, *fcw, *mprojw;
    cudaGetSymbolAddress((void**)&x,      g_x);
    cudaGetSymbolAddress((void**)&x0,     g_x0);
    cudaGetSymbolAddress((void**)&xn,     g_xn);
    cudaGetSymbolAddress((void**)&skips,  g_skips);
    cudaGetSymbolAddress((void**)&ve,     g_ve);
    cudaGetSymbolAddress((void**)&qkv,    g_qkv);
    cudaGetSymbolAddress((void**)&q,      g_q);
    cudaGetSymbolAddress((void**)&k,      g_k);
    cudaGetSymbolAddress((void**)&vt,     g_vt);
    cudaGetSymbolAddress((void**)&att,    g_att);
    cudaGetSymbolAddress((void**)&hbuf,   g_hbuf);
    cudaGetSymbolAddress((void**)&qkvw,   g_qkvw);
    cudaGetSymbolAddress((void**)&aprojw, g_aprojw);
    cudaGetSymbolAddress((void**)&fcw,    g_fcw);
    cudaGetSymbolAddress((void**)&mprojw, g_mprojw);

    const int NTOK = B_ * T_;   // 4096

    // convert all weights to fp16 mirrors
    gpt_cvtw<<<2048, 256>>>(qkv_w,       qkvw,   (long)L_*3*H_*HD_*D_);
    gpt_cvtw<<<2048, 256>>>(attn_proj_w, aprojw, (long)L_*D_*H_*HD_);
    gpt_cvtw<<<2048, 256>>>(mlp_fc_w,    fcw,    (long)L_*4*D_*D_);
    gpt_cvtw<<<2048, 256>>>(mlp_proj_w,  mprojw, (long)L_*D_*4*D_);

    gpt_embed<<<NTOK, 256>>>(seq, embed_w, ve_w, x, x0, ve);

    for (int i = 0; i < L_; i++) {
        const float* skip = (i >= 6) ? (skips + (long)(11 - i) * BTD) : nullptr;
        gpt_resnorm<<<NTOK, 256>>>(x, x0, skip, scalars, i, xn);

        if (i != 7) {
            // qkv = xn @ W_qkv^T : [4096,768] x [2304,768]^T  -> half
            gpt_gemm<0,4><<<dim3(18, 16, 1), 512, SMEM4>>>(
                xn, qkvw + (long)i * 3 * H_ * HD_ * D_, qkv, nullptr,
                D_, D_, D_, 3*H_*HD_, 0, 0, 1, 0, 0, 1.f, 0);

            const float* vep = nullptr;
            if (i < 3)       vep = ve + (long)i * BTD;
            else if (i >= 9) vep = ve + (long)(i - 9) * BTD;
            gpt_rope<<<B_*T_*H_, 128>>>(qkv, vep, scalars, i, q, k, vt);

            // fused flash attention -> att (half)
            gpt_flash<<<dim3(16, B_*H_), 128, SMEMF>>>(q, k, vt, att);

            // x += att @ W_proj^T   (float accumulate)
            gpt_gemm<1,2><<<dim3(6, 32, 1), 256, SMEM2>>>(
                att, aprojw + (long)i * D_ * H_ * HD_, x, nullptr,
                H_*HD_, H_*HD_, H_*HD_, D_, 0, 0, 1, 0, 0, 1.f, 0);

            gpt_rmsnorm<<<NTOK, 256>>>(x, xn);
        }

        // h = relu(xn @ W_fc^T)^2 : [4096,768] x [3072,768]^T -> half
        gpt_gemm<2,4><<<dim3(24, 16, 1), 512, SMEM4>>>(
            xn, fcw + (long)i * 4 * D_ * D_, hbuf, nullptr,
            D_, D_, D_, 4*D_, 0, 0, 1, 0, 0, 1.f, 0);
        // x += h @ W_proj^T ; for i<6 also copy x into skip buffer
        if (i < 6) {
            gpt_gemm<4,2><<<dim3(6, 32, 1), 256, SMEM2>>>(
                hbuf, mprojw + (long)i * D_ * 4 * D_, x, skips + (long)i * BTD,
                4*D_, 4*D_, 4*D_, D_, 0, 0, 1, 0, 0, 1.f, 0);
        } else {
            gpt_gemm<1,2><<<dim3(6, 32, 1), 256, SMEM2>>>(
                hbuf, mprojw + (long)i * D_ * 4 * D_, x, nullptr,
                4*D_, 4*D_, 4*D_, D_, 0, 0, 1, 0, 0, 1.f, 0);
        }
    }

    gpt_finalnorm<<<NTOK, 256>>>(x, (float*)d_out);
}

// round 11
// speedup vs baseline: 6.1581x; 1.0145x over previous
#include <cuda_runtime.h>
#include <cuda_fp16.h>
#include <math.h>
#include <stdint.h>

#define B_  4
#define T_  1024
#define D_  768
#define H_  6
#define HD_ 128
#define L_  12
#define BTD (B_*T_*D_)          // 3145728
#define EPSF 1.1920929e-07f
#define BKH 32                  // k-halfs per tile (16 uint32 words)
#define NSTAGE 4

// ---------------- scratch (device globals; no allocation allowed) ----------------
__device__ float  g_x   [BTD];
__device__ float  g_x0  [BTD];
__device__ __half g_xn  [BTD];
__device__ float  g_skips[6*BTD];
__device__ float  g_ve  [3*BTD];
__device__ __half g_qkv [B_*T_*3*H_*HD_];      // [bt][which*768 + h*128 + hd]
__device__ __half g_q   [B_*H_*T_*HD_];        // [b][h][t][hd]
__device__ __half g_k   [B_*H_*T_*HD_];
__device__ __half g_vt  [B_*H_*HD_*T_];        // [b][h][hd][t]  (transposed V)
__device__ __half g_att [BTD];                 // [b][t][h*128+hd]
__device__ __half g_hbuf[B_*T_*4*D_];          // [bt][3072]
__device__ float2 g_rtab[T_*32];               // rope cos/sin table
// fp16 weight mirrors
__device__ __half g_qkvw [L_*3*H_*HD_*D_];
__device__ __half g_aprojw[L_*D_*H_*HD_];
__device__ __half g_fcw  [L_*4*D_*D_];
__device__ __half g_mprojw[L_*D_*4*D_];

// ---------------- helpers ----------------
__device__ __forceinline__ float blockReduceSum256(float v, float* red) {
    int tid = threadIdx.x;
    red[tid] = v; __syncthreads();
    for (int s = 128; s > 0; s >>= 1) {
        if (tid < s) red[tid] += red[tid + s];
        __syncthreads();
    }
    float r = red[0]; __syncthreads();
    return r;
}

__device__ __forceinline__ void mma16(float* c, const uint32_t* a, const uint32_t* b) {
    asm volatile(
        "mma.sync.aligned.m16n8k16.row.col.f32.f16.f16.f32 "
        "{%0,%1,%2,%3}, {%4,%5,%6,%7}, {%8,%9}, {%0,%1,%2,%3};"
        : "+f"(c[0]), "+f"(c[1]), "+f"(c[2]), "+f"(c[3])
        : "r"(a[0]), "r"(a[1]), "r"(a[2]), "r"(a[3]), "r"(b[0]), "r"(b[1]));
}

__device__ __forceinline__ void cp16(uint32_t saddr, const void* gptr) {
    asm volatile("cp.async.cg.shared.global [%0], [%1], 16;" :: "r"(saddr), "l"(gptr));
}

// swizzle: column-group permutation within a 16-word row
__device__ __forceinline__ int swz(int r, int cg) { return cg ^ ((r >> 1) & 3); }

__device__ __forceinline__ uint32_t packh2(float a, float b) {
    __half2 h = __floats2half2_rn(a, b);
    return *(uint32_t*)&h;
}

// ---------------- weight conversion fp32 -> fp16 (rne) ----------------
__global__ __launch_bounds__(256)
void gpt_cvtw(const float* __restrict__ src, __half* __restrict__ dst, long n)
{
    long i = ((long)blockIdx.x * 256 + threadIdx.x) * 4;
    long stride = (long)gridDim.x * 1024;
    for (; i < n; i += stride) {
        float4 v = *(const float4*)&src[i];
        __half2* d = (__half2*)&dst[i];
        d[0] = __floats2half2_rn(v.x, v.y);
        d[1] = __floats2half2_rn(v.z, v.w);
    }
}

// ---------------- rope table: cos/sin(t * freq_j), layer-invariant ----------------
__global__ __launch_bounds__(256)
void gpt_ropetab(float2* __restrict__ rtab)
{
    int i = blockIdx.x * 256 + threadIdx.x;   // t*32 + j, 32768 entries
    int t = i >> 5, j = i & 31;
    float freq = exp2f(-10.0f * (float)j / 31.0f);
    float sn, cs;
    sincosf((float)t * freq, &sn, &cs);
    rtab[i] = make_float2(cs, sn);
}

// ---------------- embedding + norm + ve gather ----------------
__global__ __launch_bounds__(256)
void gpt_embed(const int* __restrict__ seq, const float* __restrict__ ew,
               const float* __restrict__ vew,
               float* __restrict__ x, float* __restrict__ x0, float* __restrict__ ve)
{
    __shared__ float red[256];
    int bt = blockIdx.x;
    int tid = threadIdx.x;
    int idx = seq[bt];
    const float* er = ew + (long)idx * D_;
    float a0 = er[tid], a1 = er[tid + 256], a2 = er[tid + 512];
    float ss = blockReduceSum256(a0*a0 + a1*a1 + a2*a2, red);
    float r = rsqrtf(ss / (float)D_ + EPSF);
    long o = (long)bt * D_;
    x0[o + tid]       = a0 * r;  x[o + tid]       = a0 * r;
    x0[o + tid + 256] = a1 * r;  x[o + tid + 256] = a1 * r;
    x0[o + tid + 512] = a2 * r;  x[o + tid + 512] = a2 * r;
    #pragma unroll
    for (int j = 0; j < 3; j++) {
        const float* vr = vew + ((long)j * 50257 + idx) * D_;
        float* vo = ve + ((long)j * (B_*T_) + bt) * D_;
        for (int d = tid; d < D_; d += 256) vo[d] = vr[d];
    }
}

// ------- fused residual + rms norm: x = l0*(x + sw*skip) + l1*x0 ; xn = h(norm(x))
__global__ __launch_bounds__(256)
void gpt_resnorm(float* __restrict__ x, const float* __restrict__ x0,
                 const float* __restrict__ skip, const float* __restrict__ scalars,
                 int layer, __half* __restrict__ xn)
{
    __shared__ float red[256];
    float l0 = scalars[L_ + 2*layer];
    float l1 = scalars[L_ + 2*layer + 1];
    float sw = skip ? scalars[layer - 6] : 0.f;
    int tid = threadIdx.x;
    long o = (long)blockIdx.x * D_;
    float a[3];
    #pragma unroll
    for (int j = 0; j < 3; j++) {
        long i = o + tid + j*256;
        float v = x[i];
        if (skip) v += sw * skip[i];
        v = l0 * v + l1 * x0[i];
        x[i] = v;
        a[j] = v;
    }
    float ss = blockReduceSum256(a[0]*a[0] + a[1]*a[1] + a[2]*a[2], red);
    float r = rsqrtf(ss / (float)D_ + EPSF);
    #pragma unroll
    for (int j = 0; j < 3; j++)
        xn[o + tid + j*256] = __float2half_rn(a[j] * r);
}

// ---------------- rms norm (row = 768), output fp16 ----------------
__global__ __launch_bounds__(256)
void gpt_rmsnorm(const float* __restrict__ x, __half* __restrict__ y)
{
    __shared__ float red[256];
    int tid = threadIdx.x;
    const float* xr = x + (long)blockIdx.x * D_;
    float a0 = xr[tid], a1 = xr[tid + 256], a2 = xr[tid + 512];
    float ss = blockReduceSum256(a0*a0 + a1*a1 + a2*a2, red);
    float r = rsqrtf(ss / (float)D_ + EPSF);
    __half* yr = y + (long)blockIdx.x * D_;
    yr[tid]       = __float2half_rn(a0 * r);
    yr[tid + 256] = __float2half_rn(a1 * r);
    yr[tid + 512] = __float2half_rn(a2 * r);
}

// ------- warp-level rope: one warp per (b,t,h); lane owns hd = lane + 32*j -------
// pairs (lane, lane+64) rotate with table[t][lane]; (lane+32, lane+96) pass through
__global__ __launch_bounds__(256)
void gpt_rope(const __half* __restrict__ qkv, const float* __restrict__ ve,
              const float* __restrict__ scalars, int layer,
              __half* __restrict__ q, __half* __restrict__ k, __half* __restrict__ vt,
              const float2* __restrict__ rtab)
{
    int z = blockIdx.x * 8 + (threadIdx.x >> 5);
    int lane = threadIdx.x & 31;
    int h = z % H_;
    int t = (z / H_) % T_;
    int b = z / (H_ * T_);
    long bt = (long)b * T_ + t;
    const __half* base = qkv + bt * (3*H_*HD_) + h * HD_;

    float qv[4], kv[4], vv[4];
    #pragma unroll
    for (int j = 0; j < 4; j++) {
        qv[j] = __half2float(base[lane + 32*j]);
        kv[j] = __half2float(base[H_*HD_ + lane + 32*j]);
        vv[j] = __half2float(base[2*H_*HD_ + lane + 32*j]);
    }
    float sq = qv[0]*qv[0] + qv[1]*qv[1] + qv[2]*qv[2] + qv[3]*qv[3];
    float sk = kv[0]*kv[0] + kv[1]*kv[1] + kv[2]*kv[2] + kv[3]*kv[3];
    #pragma unroll
    for (int s = 16; s > 0; s >>= 1) {
        sq += __shfl_xor_sync(0xffffffff, sq, s);
        sk += __shfl_xor_sync(0xffffffff, sk, s);
    }
    float rnq = rsqrtf(sq / (float)HD_ + EPSF);
    float rnk = rsqrtf(sk / (float)HD_ + EPSF);
    #pragma unroll
    for (int j = 0; j < 4; j++) { qv[j] *= rnq; kv[j] *= rnk; }

    float2 cs = rtab[t*32 + lane];
    float oq0 =  qv[0]*cs.x + qv[2]*cs.y;
    float oq2 = -qv[0]*cs.y + qv[2]*cs.x;
    float ok0 =  kv[0]*cs.x + kv[2]*cs.y;
    float ok2 = -kv[0]*cs.y + kv[2]*cs.x;

    long o = (((long)b * H_ + h) * T_ + t) * HD_;
    q[o + lane]      = __float2half_rn(oq0);
    q[o + lane + 32] = __float2half_rn(qv[1]);
    q[o + lane + 64] = __float2half_rn(oq2);
    q[o + lane + 96] = __float2half_rn(qv[3]);
    k[o + lane]      = __float2half_rn(ok0);
    k[o + lane + 32] = __float2half_rn(kv[1]);
    k[o + lane + 64] = __float2half_rn(ok2);
    k[o + lane + 96] = __float2half_rn(kv[3]);

    float sa0 = scalars[3*L_ + 2*layer];
    float sa1 = scalars[3*L_ + 2*layer + 1];
    long vbase = ((long)b * H_ + h) * HD_;
    #pragma unroll
    for (int j = 0; j < 4; j++) {
        float vo = sa0 * vv[j];
        if (ve) vo += sa1 * ve[bt * D_ + h * HD_ + lane + 32*j];
        vt[(vbase + lane + 32*j) * T_ + t] = __float2half_rn(vo);
    }
}

// =================================================================================
// Fused flash attention: 128 q-rows per CTA (8 warps), K/V tiles of 64, online
// softmax, double-buffered cp.async K/V. Q/K: [b][h][t][hd]; V: [b][h][hd][t].
// Output att[b][t][h*128+hd] (half), already softmax-normalized.
// =================================================================================
__global__ void __launch_bounds__(256, 1)
gpt_flash(const __half* __restrict__ Q, const __half* __restrict__ K,
          const __half* __restrict__ Vt, __half* __restrict__ att)
{
    const int qt = 7 - blockIdx.x;            // heavy tiles first
    const int bh = blockIdx.y;
    const int b = bh / H_, h = bh % H_;
    const int tid = threadIdx.x;
    const int w = tid >> 5, lane = tid & 31;
    const int g = lane >> 2, t = lane & 3;

    const __half* Qb = Q  + (((long)bh * T_) + qt*128) * HD_;
    const __half* Kb = K  + (long)bh * T_ * HD_;
    const __half* Vb = Vt + (long)bh * HD_ * T_;

    extern __shared__ uint32_t sm[];
    // words: Qs [4 kc][128 rows][16] = 8192 @ 0
    //        KV buf s (s=0,1): K [4 kc][64][16] = 4096 @ 8192+s*8192
    //                          V [2 kc][128][16] = 4096 @ 12288+s*8192
    uint32_t sbase = (uint32_t)__cvta_generic_to_shared(sm);

    // ---- load Q (128 rows x 256B = 2048 x 16B) ----
    #pragma unroll
    for (int j = 0; j < 8; j++) {
        int i = tid + j*256;
        int row = i >> 4, c16 = i & 15;
        int kc = c16 >> 2, wg = c16 & 3;
        uint32_t word = (kc*128 + row)*16 + swz(row, wg)*4;
        cp16(sbase + 4u*word, Qb + row*HD_ + c16*8);
    }
    asm volatile("cp.async.commit_group;" ::: "memory");

    const int NT = 2*qt + 2;

    auto issueKV = [&](int kt) {
        int s = kt & 1;
        uint32_t kw0 = 8192 + s*8192;
        #pragma unroll
        for (int j = 0; j < 4; j++) {
            int i = tid + j*256;
            int row = i >> 4, c16 = i & 15;
            int kc = c16 >> 2, wg = c16 & 3;
            uint32_t word = kw0 + (kc*64 + row)*16 + swz(row, wg)*4;
            cp16(sbase + 4u*word, Kb + (long)(kt*64 + row)*HD_ + c16*8);
        }
        uint32_t vw0 = 12288 + s*8192;
        #pragma unroll
        for (int j = 0; j < 4; j++) {
            int i = tid + j*256;
            int row = i >> 3, c16 = i & 7;
            int kc = c16 >> 2, wg = c16 & 3;
            uint32_t word = vw0 + (kc*128 + row)*16 + swz(row, wg)*4;
            cp16(sbase + 4u*word, Vb + (long)row*T_ + kt*64 + c16*8);
        }
        asm volatile("cp.async.commit_group;" ::: "memory");
    };

    issueKV(0); issueKV(1);   // NT >= 2 always

    float m0 = -1e30f, m1 = -1e30f, l0 = 0.f, l1 = 0.f;
    float oacc[16][4];
    #pragma unroll
    for (int a = 0; a < 16; a++)
        #pragma unroll
        for (int c = 0; c < 4; c++) oacc[a][c] = 0.f;

    const int r0 = w*16 + g;                  // warp-local q row (and +8)
    const int grow = qt*128 + r0;

    for (int kt = 0; kt < NT; kt++) {
        if (kt + 1 < NT) asm volatile("cp.async.wait_group 1;" ::: "memory");
        else             asm volatile("cp.async.wait_group 0;" ::: "memory");
        __syncthreads();

        const uint32_t* Kc = sm + 8192 + (kt & 1)*8192;
        const uint32_t* Vc = sm + 12288 + (kt & 1)*8192;

        // ---- S = Q K^T (warp: 16 rows x 64 cols) ----
        float sacc[8][4];
        #pragma unroll
        for (int a = 0; a < 8; a++)
            #pragma unroll
            for (int c = 0; c < 4; c++) sacc[a][c] = 0.f;

        #pragma unroll
        for (int kc = 0; kc < 4; kc++) {
            const uint32_t* Qc = sm + kc*2048;
            const uint32_t* Kk = Kc + kc*1024;
            #pragma unroll
            for (int ks = 0; ks < 2; ks++) {
                int s0 = swz(r0, ks*2)*4 + t;
                int s1 = swz(r0, ks*2 + 1)*4 + t;
                uint32_t af[4];
                af[0] = Qc[r0*16 + s0];
                af[1] = Qc[(r0+8)*16 + s0];
                af[2] = Qc[r0*16 + s1];
                af[3] = Qc[(r0+8)*16 + s1];
                #pragma unroll
                for (int ni = 0; ni < 8; ni++) {
                    int nr = ni*8 + g;
                    uint32_t bf[2];
                    bf[0] = Kk[nr*16 + swz(nr, ks*2)*4 + t];
                    bf[1] = Kk[nr*16 + swz(nr, ks*2 + 1)*4 + t];
                    mma16(sacc[ni], af, bf);
                }
            }
        }

        // ---- scale + causal mask (tiles overlapping the diagonal) ----
        bool diag = (kt >= 2*qt);
        #pragma unroll
        for (int ni = 0; ni < 8; ni++) {
            int col = kt*64 + ni*8 + t*2;
            float v0 = 0.12f * sacc[ni][0];
            float v1 = 0.12f * sacc[ni][1];
            float v2 = 0.12f * sacc[ni][2];
            float v3 = 0.12f * sacc[ni][3];
            if (diag) {
                if (col     > grow)     v0 = -1e30f;
                if (col + 1 > grow)     v1 = -1e30f;
                if (col     > grow + 8) v2 = -1e30f;
                if (col + 1 > grow + 8) v3 = -1e30f;
            }
            sacc[ni][0] = v0; sacc[ni][1] = v1; sacc[ni][2] = v2; sacc[ni][3] = v3;
        }

        // ---- online softmax (rows g and g+8) ----
        float rm0 = -1e30f, rm1 = -1e30f;
        #pragma unroll
        for (int ni = 0; ni < 8; ni++) {
            rm0 = fmaxf(rm0, fmaxf(sacc[ni][0], sacc[ni][1]));
            rm1 = fmaxf(rm1, fmaxf(sacc[ni][2], sacc[ni][3]));
        }
        rm0 = fmaxf(rm0, __shfl_xor_sync(0xffffffff, rm0, 1));
        rm0 = fmaxf(rm0, __shfl_xor_sync(0xffffffff, rm0, 2));
        rm1 = fmaxf(rm1, __shfl_xor_sync(0xffffffff, rm1, 1));
        rm1 = fmaxf(rm1, __shfl_xor_sync(0xffffffff, rm1, 2));

        float mn0 = fmaxf(m0, rm0), mn1 = fmaxf(m1, rm1);
        float sc0 = __expf(m0 - mn0), sc1 = __expf(m1 - mn1);
        m0 = mn0; m1 = mn1;

        float ls0 = 0.f, ls1 = 0.f;
        uint32_t phg[8], phg8[8];
        #pragma unroll
        for (int ni = 0; ni < 8; ni++) {
            float p0 = __expf(sacc[ni][0] - mn0);
            float p1 = __expf(sacc[ni][1] - mn0);
            float p2 = __expf(sacc[ni][2] - mn1);
            float p3 = __expf(sacc[ni][3] - mn1);
            ls0 += p0 + p1; ls1 += p2 + p3;
            phg[ni]  = packh2(p0, p1);
            phg8[ni] = packh2(p2, p3);
        }
        ls0 += __shfl_xor_sync(0xffffffff, ls0, 1);
        ls0 += __shfl_xor_sync(0xffffffff, ls0, 2);
        ls1 += __shfl_xor_sync(0xffffffff, ls1, 1);
        ls1 += __shfl_xor_sync(0xffffffff, ls1, 2);
        l0 = l0*sc0 + ls0;
        l1 = l1*sc1 + ls1;

        #pragma unroll
        for (int ni = 0; ni < 16; ni++) {
            oacc[ni][0] *= sc0; oacc[ni][1] *= sc0;
            oacc[ni][2] *= sc1; oacc[ni][3] *= sc1;
        }

        // ---- O += P V  (P A-fragments from registers; V n=128, k=64) ----
        #pragma unroll
        for (int kk = 0; kk < 4; kk++) {
            uint32_t af[4] = { phg[2*kk], phg8[2*kk], phg[2*kk+1], phg8[2*kk+1] };
            const uint32_t* Vk = Vc + (kk >> 1)*2048;
            int ks = kk & 1;
            #pragma unroll
            for (int ni = 0; ni < 16; ni++) {
                int nr = ni*8 + g;
                uint32_t bf[2];
                bf[0] = Vk[nr*16 + swz(nr, ks*2)*4 + t];
                bf[1] = Vk[nr*16 + swz(nr, ks*2 + 1)*4 + t];
                mma16(oacc[ni], af, bf);
            }
        }

        __syncthreads();
        if (kt + 2 < NT) issueKV(kt + 2);
    }

    // ---- epilogue: att[b][q][h*128+col] = O / l ----
    float inv0 = 1.f / l0, inv1 = 1.f / l1;
    long base0 = ((long)b*T_ + grow) * D_ + h*HD_;
    long base1 = base0 + 8L*D_;
    #pragma unroll
    for (int ni = 0; ni < 16; ni++) {
        int col = ni*8 + t*2;
        *(uint32_t*)&att[base0 + col] = packh2(oacc[ni][0]*inv0, oacc[ni][1]*inv0);
        *(uint32_t*)&att[base1 + col] = packh2(oacc[ni][2]*inv1, oacc[ni][3]*inv1);
    }
}

// =================================================================================
// fp16 tensor-core GEMM (m16n8k16, fp32 accum), cp.async 4-stage pipeline.
// MT=4: 256x128 block tile, 512 threads; MT=2: 128x128 block tile, 256 threads.
// C[m][n] = sum_k A[m][k] * B[n][k]
// EPI: 0=store half, 1=accumulate into float C, 2=relu^2 store half,
//      4=accumulate + copy to float C2
// =================================================================================
template<int EPI, int MT>
__global__ void
__launch_bounds__(MT == 4 ? 512 : 256, MT == 4 ? 1 : 2)
gpt_gemm(const __half* __restrict__ A, const __half* __restrict__ Bm, void* __restrict__ Cv,
         float* __restrict__ C2,
         int K, int lda, int ldb, int ldc,
         long aZ, long bZ, int zdiv, long c1, long c2, float alpha, int ktri)
{
    constexpr int THREADS = (MT == 4) ? 512 : 256;
    constexpr int BM = MT * 64;
    constexpr int AROWS = THREADS / 4;
    constexpr int APASS = BM / AROWS;
    constexpr int BPASS = 128 / AROWS;

    const int m0 = blockIdx.y * BM, n0 = blockIdx.x * 128;

    int z = blockIdx.z;
    A  += (long)z * aZ;
    Bm += (long)z * bZ;
    long coff = (long)(z / zdiv) * c1 + (long)(z % zdiv) * c2;
    float*  Cf = (float*)Cv + coff;
    __half* Ch = (__half*)Cv + coff;
    if (EPI == 4) C2 += coff;

    const int tid  = threadIdx.x;
    const int lane = tid & 31, warp = tid >> 5;
    const int wm = warp >> 2, wn = warp & 3;
    const int g = lane >> 2, t = lane & 3;

    extern __shared__ uint32_t smem[];
    uint32_t* As = smem;
    uint32_t* Bs = smem + NSTAGE * BM * 16;
    uint32_t as0 = (uint32_t)__cvta_generic_to_shared(As);
    uint32_t bs0 = (uint32_t)__cvta_generic_to_shared(Bs);

    int keff = K;
    if (ktri) { int kk = m0 + BM; keff = kk < K ? kk : K; }
    const int NT = keff / BKH;

    float acc[4][4][4];
    #pragma unroll
    for (int a = 0; a < 4; a++)
        #pragma unroll
        for (int b = 0; b < 4; b++)
            #pragma unroll
            for (int c = 0; c < 4; c++) acc[a][b][c] = 0.f;

    const int ar  = tid >> 2;
    const int acg = tid & 3;
    const __half* apB = A  + (long)(m0 + ar) * lda + acg*8;
    const __half* bpB = Bm + (long)(n0 + ar) * ldb + acg*8;

    auto issue = [&](int kt) {
        int s = kt % NSTAGE;
        const __half* ap = apB + kt*BKH;
        #pragma unroll
        for (int j = 0; j < APASS; j++) {
            int r = ar + AROWS*j;
            cp16(as0 + 4u*(s*BM*16 + r*16 + swz(r, acg)*4), ap + (long)(AROWS*j) * lda);
        }
        const __half* bp = bpB + kt*BKH;
        #pragma unroll
        for (int j = 0; j < BPASS; j++) {
            int r = ar + AROWS*j;
            cp16(bs0 + 4u*(s*128*16 + r*16 + swz(r, acg)*4), bp + (long)(AROWS*j) * ldb);
        }
        asm volatile("cp.async.commit_group;" ::: "memory");
    };

    issue(0); issue(1); issue(2);

    for (int kt = 0; kt < NT; kt++) {
        if (kt + 1 >= NT)      asm volatile("cp.async.wait_group 0;" ::: "memory");
        else if (kt + 2 >= NT) asm volatile("cp.async.wait_group 1;" ::: "memory");
        else                   asm volatile("cp.async.wait_group 2;" ::: "memory");
        __syncthreads();

        const uint32_t* Ab = As + (kt % NSTAGE) * BM * 16;
        const uint32_t* Bb = Bs + (kt % NSTAGE) * 128 * 16;
        #pragma unroll
        for (int ks = 0; ks < 2; ks++) {
            uint32_t af[4][4];
            #pragma unroll
            for (int mi = 0; mi < 4; mi++) {
                int r0 = wm*64 + mi*16 + g;
                int s0 = swz(r0, ks*2)*4 + t;
                int s1 = swz(r0, ks*2 + 1)*4 + t;
                af[mi][0] = Ab[r0*16 + s0];
                af[mi][1] = Ab[(r0+8)*16 + s0];
                af[mi][2] = Ab[r0*16 + s1];
                af[mi][3] = Ab[(r0+8)*16 + s1];
            }
            uint32_t bf[4][2];
            #pragma unroll
            for (int ni = 0; ni < 4; ni++) {
                int nr = wn*32 + ni*8 + g;
                bf[ni][0] = Bb[nr*16 + swz(nr, ks*2)*4 + t];
                bf[ni][1] = Bb[nr*16 + swz(nr, ks*2 + 1)*4 + t];
            }
            #pragma unroll
            for (int mi = 0; mi < 4; mi++)
                #pragma unroll
                for (int ni = 0; ni < 4; ni++)
                    mma16(acc[mi][ni], af[mi], bf[ni]);
        }

        if (kt + NSTAGE - 1 < NT) issue(kt + NSTAGE - 1);
    }

    // ---- epilogue ----
    #pragma unroll
    for (int mi = 0; mi < 4; mi++) {
        int row = m0 + wm*64 + mi*16 + g;
        #pragma unroll
        for (int ni = 0; ni < 4; ni++) {
            int col = n0 + wn*32 + ni*8 + t*2;
            float* a4 = acc[mi][ni];
            #pragma unroll
            for (int half_ = 0; half_ < 2; half_++) {
                int r = row + half_ * 8;
                float c0 = a4[half_*2 + 0], c1 = a4[half_*2 + 1];
                if (EPI == 0) {
                    *(__half2*)&Ch[(long)r * ldc + col] = __floats2half2_rn(c0, c1);
                } else if (EPI == 2) {
                    float r0 = fmaxf(c0, 0.f), r1 = fmaxf(c1, 0.f);
                    *(__half2*)&Ch[(long)r * ldc + col] = __floats2half2_rn(r0*r0, r1*r1);
                } else {
                    float* cp = &Cf[(long)r * ldc + col];
                    float2 o = *(float2*)cp;
                    float2 out = make_float2(o.x + c0, o.y + c1);
                    *(float2*)cp = out;
                    if (EPI == 4) *(float2*)&C2[(long)r * ldc + col] = out;
                }
            }
        }
    }
}

// ---------------- final norm -> output ----------------
__global__ __launch_bounds__(256)
void gpt_finalnorm(const float* __restrict__ x, float* __restrict__ out)
{
    __shared__ float red[256];
    int tid = threadIdx.x;
    const float* xr = x + (long)blockIdx.x * D_;
    float a0 = xr[tid], a1 = xr[tid + 256], a2 = xr[tid + 512];
    float ss = blockReduceSum256(a0*a0 + a1*a1 + a2*a2, red);
    float r = rsqrtf(ss / (float)D_ + EPSF);
    float* yr = out + (long)blockIdx.x * D_;
    yr[tid] = a0 * r; yr[tid + 256] = a1 * r; yr[tid + 512] = a2 * r;
}

// ---------------- host orchestration ----------------
#define SMEM4 (NSTAGE * (256 + 128) * 16 * 4)   // 98304
#define SMEM2 (NSTAGE * (128 + 128) * 16 * 4)   // 65536
#define SMEMF ((8192 + 2*8192) * 4)             // 98304 (flash)

extern "C" void kernel_launch(void* const* d_in, const int* in_sizes, int n_in,
                              void* d_out, int out_size)
{
    const int*   seq         = (const int*)  d_in[0];
    const float* embed_w     = (const float*)d_in[1];
    const float* ve_w        = (const float*)d_in[2];
    const float* qkv_w       = (const float*)d_in[3];
    const float* attn_proj_w = (const float*)d_in[4];
    const float* mlp_fc_w    = (const float*)d_in[5];
    const float* mlp_proj_w  = (const float*)d_in[6];
    const float* scalars     = (const float*)d_in[7];

    cudaFuncSetAttribute(gpt_gemm<0,4>, cudaFuncAttributeMaxDynamicSharedMemorySize, SMEM4);
    cudaFuncSetAttribute(gpt_gemm<2,4>, cudaFuncAttributeMaxDynamicSharedMemorySize, SMEM4);
    cudaFuncSetAttribute(gpt_gemm<1,2>, cudaFuncAttributeMaxDynamicSharedMemorySize, SMEM2);
    cudaFuncSetAttribute(gpt_gemm<4,2>, cudaFuncAttributeMaxDynamicSharedMemorySize, SMEM2);
    cudaFuncSetAttribute(gpt_flash,     cudaFuncAttributeMaxDynamicSharedMemorySize, SMEMF);

    float *x, *x0, *skips, *ve;
    float2 *rtab;
    __half *xn, *qkv, *q, *k, *vt, *att, *hbuf;
    __half *qkvw, *aprojw, *fcw, *mprojw;
    cudaGetSymbolAddress((void**)&x,      g_x);
    cudaGetSymbolAddress((void**)&x0,     g_x0);
    cudaGetSymbolAddress((void**)&xn,     g_xn);
    cudaGetSymbolAddress((void**)&skips,  g_skips);
    cudaGetSymbolAddress((void**)&ve,     g_ve);
    cudaGetSymbolAddress((void**)&qkv,    g_qkv);
    cudaGetSymbolAddress((void**)&q,      g_q);
    cudaGetSymbolAddress((void**)&k,      g_k);
    cudaGetSymbolAddress((void**)&vt,     g_vt);
    cudaGetSymbolAddress((void**)&att,    g_att);
    cudaGetSymbolAddress((void**)&hbuf,   g_hbuf);
    cudaGetSymbolAddress((void**)&rtab,   g_rtab);
    cudaGetSymbolAddress((void**)&qkvw,   g_qkvw);
    cudaGetSymbolAddress((void**)&aprojw, g_aprojw);
    cudaGetSymbolAddress((void**)&fcw,    g_fcw);
    cudaGetSymbolAddress((void**)&mprojw, g_mprojw);

    const int NTOK = B_ * T_;   // 4096

    // convert all weights to fp16 mirrors; build rope table
    gpt_cvtw<<<2048, 256>>>(qkv_w,       qkvw,   (long)L_*3*H_*HD_*D_);
    gpt_cvtw<<<2048, 256>>>(attn_proj_w, aprojw, (long)L_*D_*H_*HD_);
    gpt_cvtw<<<2048, 256>>>(mlp_fc_w,    fcw,    (long)L_*4*D_*D_);
    gpt_cvtw<<<2048, 256>>>(mlp_proj_w,  mprojw, (long)L_*D_*4*D_);
    gpt_ropetab<<<128, 256>>>(rtab);

    gpt_embed<<<NTOK, 256>>>(seq, embed_w, ve_w, x, x0, ve);

    for (int i = 0; i < L_; i++) {
        const float* skip = (i >= 6) ? (skips + (long)(11 - i) * BTD) : nullptr;
        gpt_resnorm<<<NTOK, 256>>>(x, x0, skip, scalars, i, xn);

        if (i != 7) {
            // qkv = xn @ W_qkv^T : [4096,768] x [2304,768]^T  -> half
            gpt_gemm<0,4><<<dim3(18, 16, 1), 512, SMEM4>>>(
                xn, qkvw + (long)i * 3 * H_ * HD_ * D_, qkv, nullptr,
                D_, D_, D_, 3*H_*HD_, 0, 0, 1, 0, 0, 1.f, 0);

            const float* vep = nullptr;
            if (i < 3)       vep = ve + (long)i * BTD;
            else if (i >= 9) vep = ve + (long)(i - 9) * BTD;
            gpt_rope<<<B_*T_*H_/8, 256>>>(qkv, vep, scalars, i, q, k, vt, rtab);

            // fused flash attention -> att (half)
            gpt_flash<<<dim3(8, B_*H_), 256, SMEMF>>>(q, k, vt, att);

            // x += att @ W_proj^T   (float accumulate)
            gpt_gemm<1,2><<<dim3(6, 32, 1), 256, SMEM2>>>(
                att, aprojw + (long)i * D_ * H_ * HD_, x, nullptr,
                H_*HD_, H_*HD_, H_*HD_, D_, 0, 0, 1, 0, 0, 1.f, 0);

            gpt_rmsnorm<<<NTOK, 256>>>(x, xn);
        }

        // h = relu(xn @ W_fc^T)^2 : [4096,768] x [3072,768]^T -> half
        gpt_gemm<2,4><<<dim3(24, 16, 1), 512, SMEM4>>>(
            xn, fcw + (long)i * 4 * D_ * D_, hbuf, nullptr,
            D_, D_, D_, 4*D_, 0, 0, 1, 0, 0, 1.f, 0);
        // x += h @ W_proj^T ; for i<6 also copy x into skip buffer
        if (i < 6) {
            gpt_gemm<4,2><<<dim3(6, 32, 1), 256, SMEM2>>>(
                hbuf, mprojw + (long)i * D_ * 4 * D_, x, skips + (long)i * BTD,
                4*D_, 4*D_, 4*D_, D_, 0, 0, 1, 0, 0, 1.f, 0);
        } else {
            gpt_gemm<1,2><<<dim3(6, 32, 1), 256, SMEM2>>>(
                hbuf, mprojw + (long)i * D_ * 4 * D_, x, nullptr,
                4*D_, 4*D_, 4*D_, D_, 0, 0, 1, 0, 0, 1.f, 0);
        }
    }

    gpt_finalnorm<<<NTOK, 256>>>(x, (float*)d_out);
}

// round 12
// speedup vs baseline: 6.1606x; 1.0004x over previous
#include <cuda_runtime.h>
#include <cuda_fp16.h>
#include <math.h>
#include <stdint.h>

#define B_  4
#define T_  1024
#define D_  768
#define H_  6
#define HD_ 128
#define L_  12
#define BTD (B_*T_*D_)          // 3145728
#define EPSF 1.1920929e-07f
#define BKH 32                  // k-halfs per tile (16 uint32 words)
#define NSTAGE 4

// ---------------- scratch (device globals; no allocation allowed) ----------------
__device__ float  g_x   [BTD];
__device__ float  g_x0  [BTD];
__device__ __half g_xn  [BTD];
__device__ float  g_skips[6*BTD];
__device__ float  g_ve  [3*BTD];
__device__ __half g_qkv [B_*T_*3*H_*HD_];      // [bt][which*768 + h*128 + hd]
__device__ __half g_q   [B_*H_*T_*HD_];        // [b][h][t][hd]
__device__ __half g_k   [B_*H_*T_*HD_];
__device__ __half g_vt  [B_*H_*HD_*T_];        // [b][h][hd][t]  (transposed V)
__device__ __half g_att [BTD];                 // [b][t][h*128+hd]
__device__ __half g_hbuf[B_*T_*4*D_];          // [bt][3072]
__device__ float2 g_rtab[T_*32];               // rope cos/sin table
// fp16 weight mirrors
__device__ __half g_qkvw [L_*3*H_*HD_*D_];
__device__ __half g_aprojw[L_*D_*H_*HD_];
__device__ __half g_fcw  [L_*4*D_*D_];
__device__ __half g_mprojw[L_*D_*4*D_];

// ---------------- helpers ----------------
__device__ __forceinline__ float blockReduceSum256(float v, float* red) {
    int tid = threadIdx.x;
    red[tid] = v; __syncthreads();
    for (int s = 128; s > 0; s >>= 1) {
        if (tid < s) red[tid] += red[tid + s];
        __syncthreads();
    }
    float r = red[0]; __syncthreads();
    return r;
}

__device__ __forceinline__ void mma16(float* c, const uint32_t* a, const uint32_t* b) {
    asm volatile(
        "mma.sync.aligned.m16n8k16.row.col.f32.f16.f16.f32 "
        "{%0,%1,%2,%3}, {%4,%5,%6,%7}, {%8,%9}, {%0,%1,%2,%3};"
        : "+f"(c[0]), "+f"(c[1]), "+f"(c[2]), "+f"(c[3])
        : "r"(a[0]), "r"(a[1]), "r"(a[2]), "r"(a[3]), "r"(b[0]), "r"(b[1]));
}

__device__ __forceinline__ void cp16(uint32_t saddr, const void* gptr) {
    asm volatile("cp.async.cg.shared.global [%0], [%1], 16;" :: "r"(saddr), "l"(gptr));
}

// swizzle: column-group permutation within a 16-word row
__device__ __forceinline__ int swz(int r, int cg) { return cg ^ ((r >> 1) & 3); }

__device__ __forceinline__ uint32_t packh2(float a, float b) {
    __half2 h = __floats2half2_rn(a, b);
    return *(uint32_t*)&h;
}

// ---------------- weight conversion fp32 -> fp16 (rne) ----------------
__global__ __launch_bounds__(256)
void gpt_cvtw(const float* __restrict__ src, __half* __restrict__ dst, long n)
{
    long i = ((long)blockIdx.x * 256 + threadIdx.x) * 4;
    long stride = (long)gridDim.x * 1024;
    for (; i < n; i += stride) {
        float4 v = *(const float4*)&src[i];
        __half2* d = (__half2*)&dst[i];
        d[0] = __floats2half2_rn(v.x, v.y);
        d[1] = __floats2half2_rn(v.z, v.w);
    }
}

// ---------------- rope table: cos/sin(t * freq_j), layer-invariant ----------------
__global__ __launch_bounds__(256)
void gpt_ropetab(float2* __restrict__ rtab)
{
    int i = blockIdx.x * 256 + threadIdx.x;   // t*32 + j, 32768 entries
    int t = i >> 5, j = i & 31;
    float freq = exp2f(-10.0f * (float)j / 31.0f);
    float sn, cs;
    sincosf((float)t * freq, &sn, &cs);
    rtab[i] = make_float2(cs, sn);
}

// ---------------- embedding + norm + ve gather ----------------
__global__ __launch_bounds__(256)
void gpt_embed(const int* __restrict__ seq, const float* __restrict__ ew,
               const float* __restrict__ vew,
               float* __restrict__ x, float* __restrict__ x0, float* __restrict__ ve)
{
    __shared__ float red[256];
    int bt = blockIdx.x;
    int tid = threadIdx.x;
    int idx = seq[bt];
    const float* er = ew + (long)idx * D_;
    float a0 = er[tid], a1 = er[tid + 256], a2 = er[tid + 512];
    float ss = blockReduceSum256(a0*a0 + a1*a1 + a2*a2, red);
    float r = rsqrtf(ss / (float)D_ + EPSF);
    long o = (long)bt * D_;
    x0[o + tid]       = a0 * r;  x[o + tid]       = a0 * r;
    x0[o + tid + 256] = a1 * r;  x[o + tid + 256] = a1 * r;
    x0[o + tid + 512] = a2 * r;  x[o + tid + 512] = a2 * r;
    #pragma unroll
    for (int j = 0; j < 3; j++) {
        const float* vr = vew + ((long)j * 50257 + idx) * D_;
        float* vo = ve + ((long)j * (B_*T_) + bt) * D_;
        for (int d = tid; d < D_; d += 256) vo[d] = vr[d];
    }
}

// ------- fused residual + rms norm: x = l0*(x + sw*skip) + l1*x0 ; xn = h(norm(x))
__global__ __launch_bounds__(256)
void gpt_resnorm(float* __restrict__ x, const float* __restrict__ x0,
                 const float* __restrict__ skip, const float* __restrict__ scalars,
                 int layer, __half* __restrict__ xn)
{
    __shared__ float red[256];
    float l0 = scalars[L_ + 2*layer];
    float l1 = scalars[L_ + 2*layer + 1];
    float sw = skip ? scalars[layer - 6] : 0.f;
    int tid = threadIdx.x;
    long o = (long)blockIdx.x * D_;
    float a[3];
    #pragma unroll
    for (int j = 0; j < 3; j++) {
        long i = o + tid + j*256;
        float v = x[i];
        if (skip) v += sw * skip[i];
        v = l0 * v + l1 * x0[i];
        x[i] = v;
        a[j] = v;
    }
    float ss = blockReduceSum256(a[0]*a[0] + a[1]*a[1] + a[2]*a[2], red);
    float r = rsqrtf(ss / (float)D_ + EPSF);
    #pragma unroll
    for (int j = 0; j < 3; j++)
        xn[o + tid + j*256] = __float2half_rn(a[j] * r);
}

// ---------------- rms norm (row = 768), output fp16 ----------------
__global__ __launch_bounds__(256)
void gpt_rmsnorm(const float* __restrict__ x, __half* __restrict__ y)
{
    __shared__ float red[256];
    int tid = threadIdx.x;
    const float* xr = x + (long)blockIdx.x * D_;
    float a0 = xr[tid], a1 = xr[tid + 256], a2 = xr[tid + 512];
    float ss = blockReduceSum256(a0*a0 + a1*a1 + a2*a2, red);
    float r = rsqrtf(ss / (float)D_ + EPSF);
    __half* yr = y + (long)blockIdx.x * D_;
    yr[tid]       = __float2half_rn(a0 * r);
    yr[tid + 256] = __float2half_rn(a1 * r);
    yr[tid + 512] = __float2half_rn(a2 * r);
}

// ------- warp-level rope: one warp per (b,t,h); lane owns hd = lane + 32*j -------
// pairs (lane, lane+64) rotate with table[t][lane]; (lane+32, lane+96) pass through
__global__ __launch_bounds__(256)
void gpt_rope(const __half* __restrict__ qkv, const float* __restrict__ ve,
              const float* __restrict__ scalars, int layer,
              __half* __restrict__ q, __half* __restrict__ k, __half* __restrict__ vt,
              const float2* __restrict__ rtab)
{
    int z = blockIdx.x * 8 + (threadIdx.x >> 5);
    int lane = threadIdx.x & 31;
    int h = z % H_;
    int t = (z / H_) % T_;
    int b = z / (H_ * T_);
    long bt = (long)b * T_ + t;
    const __half* base = qkv + bt * (3*H_*HD_) + h * HD_;

    float qv[4], kv[4], vv[4];
    #pragma unroll
    for (int j = 0; j < 4; j++) {
        qv[j] = __half2float(base[lane + 32*j]);
        kv[j] = __half2float(base[H_*HD_ + lane + 32*j]);
        vv[j] = __half2float(base[2*H_*HD_ + lane + 32*j]);
    }
    float sq = qv[0]*qv[0] + qv[1]*qv[1] + qv[2]*qv[2] + qv[3]*qv[3];
    float sk = kv[0]*kv[0] + kv[1]*kv[1] + kv[2]*kv[2] + kv[3]*kv[3];
    #pragma unroll
    for (int s = 16; s > 0; s >>= 1) {
        sq += __shfl_xor_sync(0xffffffff, sq, s);
        sk += __shfl_xor_sync(0xffffffff, sk, s);
    }
    float rnq = rsqrtf(sq / (float)HD_ + EPSF);
    float rnk = rsqrtf(sk / (float)HD_ + EPSF);
    #pragma unroll
    for (int j = 0; j < 4; j++) { qv[j] *= rnq; kv[j] *= rnk; }

    float2 cs = rtab[t*32 + lane];
    float oq0 =  qv[0]*cs.x + qv[2]*cs.y;
    float oq2 = -qv[0]*cs.y + qv[2]*cs.x;
    float ok0 =  kv[0]*cs.x + kv[2]*cs.y;
    float ok2 = -kv[0]*cs.y + kv[2]*cs.x;

    long o = (((long)b * H_ + h) * T_ + t) * HD_;
    q[o + lane]      = __float2half_rn(oq0);
    q[o + lane + 32] = __float2half_rn(qv[1]);
    q[o + lane + 64] = __float2half_rn(oq2);
    q[o + lane + 96] = __float2half_rn(qv[3]);
    k[o + lane]      = __float2half_rn(ok0);
    k[o + lane + 32] = __float2half_rn(kv[1]);
    k[o + lane + 64] = __float2half_rn(ok2);
    k[o + lane + 96] = __float2half_rn(kv[3]);

    float sa0 = scalars[3*L_ + 2*layer];
    float sa1 = scalars[3*L_ + 2*layer + 1];
    long vbase = ((long)b * H_ + h) * HD_;
    #pragma unroll
    for (int j = 0; j < 4; j++) {
        float vo = sa0 * vv[j];
        if (ve) vo += sa1 * ve[bt * D_ + h * HD_ + lane + 32*j];
        vt[(vbase + lane + 32*j) * T_ + t] = __float2half_rn(vo);
    }
}

// =================================================================================
// Fused flash attention: 128 q-rows per CTA (8 warps), K/V tiles of 64, online
// softmax, double-buffered cp.async K/V. Q/K: [b][h][t][hd]; V: [b][h][hd][t].
// Output att[b][t][h*128+hd] (half), already softmax-normalized.
// =================================================================================
__global__ void __launch_bounds__(256, 1)
gpt_flash(const __half* __restrict__ Q, const __half* __restrict__ K,
          const __half* __restrict__ Vt, __half* __restrict__ att)
{
    const int qt = 7 - blockIdx.x;            // heavy tiles first
    const int bh = blockIdx.y;
    const int b = bh / H_, h = bh % H_;
    const int tid = threadIdx.x;
    const int w = tid >> 5, lane = tid & 31;
    const int g = lane >> 2, t = lane & 3;

    const __half* Qb = Q  + (((long)bh * T_) + qt*128) * HD_;
    const __half* Kb = K  + (long)bh * T_ * HD_;
    const __half* Vb = Vt + (long)bh * HD_ * T_;

    extern __shared__ uint32_t sm[];
    // words: Qs [4 kc][128 rows][16] = 8192 @ 0
    //        KV buf s (s=0,1): K [4 kc][64][16] = 4096 @ 8192+s*8192
    //                          V [2 kc][128][16] = 4096 @ 12288+s*8192
    uint32_t sbase = (uint32_t)__cvta_generic_to_shared(sm);

    // ---- load Q (128 rows x 256B = 2048 x 16B) ----
    #pragma unroll
    for (int j = 0; j < 8; j++) {
        int i = tid + j*256;
        int row = i >> 4, c16 = i & 15;
        int kc = c16 >> 2, wg = c16 & 3;
        uint32_t word = (kc*128 + row)*16 + swz(row, wg)*4;
        cp16(sbase + 4u*word, Qb + row*HD_ + c16*8);
    }
    asm volatile("cp.async.commit_group;" ::: "memory");

    const int NT = 2*qt + 2;

    auto issueKV = [&](int kt) {
        int s = kt & 1;
        uint32_t kw0 = 8192 + s*8192;
        #pragma unroll
        for (int j = 0; j < 4; j++) {
            int i = tid + j*256;
            int row = i >> 4, c16 = i & 15;
            int kc = c16 >> 2, wg = c16 & 3;
            uint32_t word = kw0 + (kc*64 + row)*16 + swz(row, wg)*4;
            cp16(sbase + 4u*word, Kb + (long)(kt*64 + row)*HD_ + c16*8);
        }
        uint32_t vw0 = 12288 + s*8192;
        #pragma unroll
        for (int j = 0; j < 4; j++) {
            int i = tid + j*256;
            int row = i >> 3, c16 = i & 7;
            int kc = c16 >> 2, wg = c16 & 3;
            uint32_t word = vw0 + (kc*128 + row)*16 + swz(row, wg)*4;
            cp16(sbase + 4u*word, Vb + (long)row*T_ + kt*64 + c16*8);
        }
        asm volatile("cp.async.commit_group;" ::: "memory");
    };

    issueKV(0); issueKV(1);   // NT >= 2 always

    float m0 = -1e30f, m1 = -1e30f, l0 = 0.f, l1 = 0.f;
    float oacc[16][4];
    #pragma unroll
    for (int a = 0; a < 16; a++)
        #pragma unroll
        for (int c = 0; c < 4; c++) oacc[a][c] = 0.f;

    const int r0 = w*16 + g;                  // warp-local q row (and +8)
    const int grow = qt*128 + r0;

    for (int kt = 0; kt < NT; kt++) {
        if (kt + 1 < NT) asm volatile("cp.async.wait_group 1;" ::: "memory");
        else             asm volatile("cp.async.wait_group 0;" ::: "memory");
        __syncthreads();

        const uint32_t* Kc = sm + 8192 + (kt & 1)*8192;
        const uint32_t* Vc = sm + 12288 + (kt & 1)*8192;

        // ---- S = Q K^T (warp: 16 rows x 64 cols) ----
        float sacc[8][4];
        #pragma unroll
        for (int a = 0; a < 8; a++)
            #pragma unroll
            for (int c = 0; c < 4; c++) sacc[a][c] = 0.f;

        #pragma unroll
        for (int kc = 0; kc < 4; kc++) {
            const uint32_t* Qc = sm + kc*2048;
            const uint32_t* Kk = Kc + kc*1024;
            #pragma unroll
            for (int ks = 0; ks < 2; ks++) {
                int s0 = swz(r0, ks*2)*4 + t;
                int s1 = swz(r0, ks*2 + 1)*4 + t;
                uint32_t af[4];
                af[0] = Qc[r0*16 + s0];
                af[1] = Qc[(r0+8)*16 + s0];
                af[2] = Qc[r0*16 + s1];
                af[3] = Qc[(r0+8)*16 + s1];
                #pragma unroll
                for (int ni = 0; ni < 8; ni++) {
                    int nr = ni*8 + g;
                    uint32_t bf[2];
                    bf[0] = Kk[nr*16 + swz(nr, ks*2)*4 + t];
                    bf[1] = Kk[nr*16 + swz(nr, ks*2 + 1)*4 + t];
                    mma16(sacc[ni], af, bf);
                }
            }
        }

        // ---- scale + causal mask (tiles overlapping the diagonal) ----
        bool diag = (kt >= 2*qt);
        #pragma unroll
        for (int ni = 0; ni < 8; ni++) {
            int col = kt*64 + ni*8 + t*2;
            float v0 = 0.12f * sacc[ni][0];
            float v1 = 0.12f * sacc[ni][1];
            float v2 = 0.12f * sacc[ni][2];
            float v3 = 0.12f * sacc[ni][3];
            if (diag) {
                if (col     > grow)     v0 = -1e30f;
                if (col + 1 > grow)     v1 = -1e30f;
                if (col     > grow + 8) v2 = -1e30f;
                if (col + 1 > grow + 8) v3 = -1e30f;
            }
            sacc[ni][0] = v0; sacc[ni][1] = v1; sacc[ni][2] = v2; sacc[ni][3] = v3;
        }

        // ---- online softmax (rows g and g+8) ----
        float rm0 = -1e30f, rm1 = -1e30f;
        #pragma unroll
        for (int ni = 0; ni < 8; ni++) {
            rm0 = fmaxf(rm0, fmaxf(sacc[ni][0], sacc[ni][1]));
            rm1 = fmaxf(rm1, fmaxf(sacc[ni][2], sacc[ni][3]));
        }
        rm0 = fmaxf(rm0, __shfl_xor_sync(0xffffffff, rm0, 1));
        rm0 = fmaxf(rm0, __shfl_xor_sync(0xffffffff, rm0, 2));
        rm1 = fmaxf(rm1, __shfl_xor_sync(0xffffffff, rm1, 1));
        rm1 = fmaxf(rm1, __shfl_xor_sync(0xffffffff, rm1, 2));

        float mn0 = fmaxf(m0, rm0), mn1 = fmaxf(m1, rm1);
        float sc0 = __expf(m0 - mn0), sc1 = __expf(m1 - mn1);
        m0 = mn0; m1 = mn1;

        float ls0 = 0.f, ls1 = 0.f;
        uint32_t phg[8], phg8[8];
        #pragma unroll
        for (int ni = 0; ni < 8; ni++) {
            float p0 = __expf(sacc[ni][0] - mn0);
            float p1 = __expf(sacc[ni][1] - mn0);
            float p2 = __expf(sacc[ni][2] - mn1);
            float p3 = __expf(sacc[ni][3] - mn1);
            ls0 += p0 + p1; ls1 += p2 + p3;
            phg[ni]  = packh2(p0, p1);
            phg8[ni] = packh2(p2, p3);
        }
        ls0 += __shfl_xor_sync(0xffffffff, ls0, 1);
        ls0 += __shfl_xor_sync(0xffffffff, ls0, 2);
        ls1 += __shfl_xor_sync(0xffffffff, ls1, 1);
        ls1 += __shfl_xor_sync(0xffffffff, ls1, 2);
        l0 = l0*sc0 + ls0;
        l1 = l1*sc1 + ls1;

        #pragma unroll
        for (int ni = 0; ni < 16; ni++) {
            oacc[ni][0] *= sc0; oacc[ni][1] *= sc0;
            oacc[ni][2] *= sc1; oacc[ni][3] *= sc1;
        }

        // ---- O += P V  (P A-fragments from registers; V n=128, k=64) ----
        #pragma unroll
        for (int kk = 0; kk < 4; kk++) {
            uint32_t af[4] = { phg[2*kk], phg8[2*kk], phg[2*kk+1], phg8[2*kk+1] };
            const uint32_t* Vk = Vc + (kk >> 1)*2048;
            int ks = kk & 1;
            #pragma unroll
            for (int ni = 0; ni < 16; ni++) {
                int nr = ni*8 + g;
                uint32_t bf[2];
                bf[0] = Vk[nr*16 + swz(nr, ks*2)*4 + t];
                bf[1] = Vk[nr*16 + swz(nr, ks*2 + 1)*4 + t];
                mma16(oacc[ni], af, bf);
            }
        }

        __syncthreads();
        if (kt + 2 < NT) issueKV(kt + 2);
    }

    // ---- epilogue: att[b][q][h*128+col] = O / l ----
    float inv0 = 1.f / l0, inv1 = 1.f / l1;
    long base0 = ((long)b*T_ + grow) * D_ + h*HD_;
    long base1 = base0 + 8L*D_;
    #pragma unroll
    for (int ni = 0; ni < 16; ni++) {
        int col = ni*8 + t*2;
        *(uint32_t*)&att[base0 + col] = packh2(oacc[ni][0]*inv0, oacc[ni][1]*inv0);
        *(uint32_t*)&att[base1 + col] = packh2(oacc[ni][2]*inv1, oacc[ni][3]*inv1);
    }
}

// =================================================================================
// fp16 tensor-core GEMM (m16n8k16, fp32 accum), cp.async 4-stage pipeline.
// MT=4: 256x128 block tile, 512 threads; MT=2: 128x128 block tile, 256 threads.
// C[m][n] = sum_k A[m][k] * B[n][k]
// EPI: 0=store half, 1=accumulate into float C, 2=relu^2 store half,
//      4=accumulate + copy to float C2
// =================================================================================
template<int EPI, int MT>
__global__ void
__launch_bounds__(MT == 4 ? 512 : 256, MT == 4 ? 1 : 2)
gpt_gemm(const __half* __restrict__ A, const __half* __restrict__ Bm, void* __restrict__ Cv,
         float* __restrict__ C2,
         int K, int lda, int ldb, int ldc,
         long aZ, long bZ, int zdiv, long c1, long c2, float alpha, int ktri)
{
    constexpr int THREADS = (MT == 4) ? 512 : 256;
    constexpr int BM = MT * 64;
    constexpr int AROWS = THREADS / 4;
    constexpr int APASS = BM / AROWS;
    constexpr int BPASS = 128 / AROWS;

    const int m0 = blockIdx.y * BM, n0 = blockIdx.x * 128;

    int z = blockIdx.z;
    A  += (long)z * aZ;
    Bm += (long)z * bZ;
    long coff = (long)(z / zdiv) * c1 + (long)(z % zdiv) * c2;
    float*  Cf = (float*)Cv + coff;
    __half* Ch = (__half*)Cv + coff;
    if (EPI == 4) C2 += coff;

    const int tid  = threadIdx.x;
    const int lane = tid & 31, warp = tid >> 5;
    const int wm = warp >> 2, wn = warp & 3;
    const int g = lane >> 2, t = lane & 3;

    extern __shared__ uint32_t smem[];
    uint32_t* As = smem;
    uint32_t* Bs = smem + NSTAGE * BM * 16;
    uint32_t as0 = (uint32_t)__cvta_generic_to_shared(As);
    uint32_t bs0 = (uint32_t)__cvta_generic_to_shared(Bs);

    int keff = K;
    if (ktri) { int kk = m0 + BM; keff = kk < K ? kk : K; }
    const int NT = keff / BKH;

    float acc[4][4][4];
    #pragma unroll
    for (int a = 0; a < 4; a++)
        #pragma unroll
        for (int b = 0; b < 4; b++)
            #pragma unroll
            for (int c = 0; c < 4; c++) acc[a][b][c] = 0.f;

    const int ar  = tid >> 2;
    const int acg = tid & 3;
    const __half* apB = A  + (long)(m0 + ar) * lda + acg*8;
    const __half* bpB = Bm + (long)(n0 + ar) * ldb + acg*8;

    auto issue = [&](int kt) {
        int s = kt % NSTAGE;
        const __half* ap = apB + kt*BKH;
        #pragma unroll
        for (int j = 0; j < APASS; j++) {
            int r = ar + AROWS*j;
            cp16(as0 + 4u*(s*BM*16 + r*16 + swz(r, acg)*4), ap + (long)(AROWS*j) * lda);
        }
        const __half* bp = bpB + kt*BKH;
        #pragma unroll
        for (int j = 0; j < BPASS; j++) {
            int r = ar + AROWS*j;
            cp16(bs0 + 4u*(s*128*16 + r*16 + swz(r, acg)*4), bp + (long)(AROWS*j) * ldb);
        }
        asm volatile("cp.async.commit_group;" ::: "memory");
    };

    issue(0); issue(1); issue(2);

    for (int kt = 0; kt < NT; kt++) {
        if (kt + 1 >= NT)      asm volatile("cp.async.wait_group 0;" ::: "memory");
        else if (kt + 2 >= NT) asm volatile("cp.async.wait_group 1;" ::: "memory");
        else                   asm volatile("cp.async.wait_group 2;" ::: "memory");
        __syncthreads();

        const uint32_t* Ab = As + (kt % NSTAGE) * BM * 16;
        const uint32_t* Bb = Bs + (kt % NSTAGE) * 128 * 16;
        #pragma unroll
        for (int ks = 0; ks < 2; ks++) {
            uint32_t af[4][4];
            #pragma unroll
            for (int mi = 0; mi < 4; mi++) {
                int r0 = wm*64 + mi*16 + g;
                int s0 = swz(r0, ks*2)*4 + t;
                int s1 = swz(r0, ks*2 + 1)*4 + t;
                af[mi][0] = Ab[r0*16 + s0];
                af[mi][1] = Ab[(r0+8)*16 + s0];
                af[mi][2] = Ab[r0*16 + s1];
                af[mi][3] = Ab[(r0+8)*16 + s1];
            }
            uint32_t bf[4][2];
            #pragma unroll
            for (int ni = 0; ni < 4; ni++) {
                int nr = wn*32 + ni*8 + g;
                bf[ni][0] = Bb[nr*16 + swz(nr, ks*2)*4 + t];
                bf[ni][1] = Bb[nr*16 + swz(nr, ks*2 + 1)*4 + t];
            }
            #pragma unroll
            for (int mi = 0; mi < 4; mi++)
                #pragma unroll
                for (int ni = 0; ni < 4; ni++)
                    mma16(acc[mi][ni], af[mi], bf[ni]);
        }

        if (kt + NSTAGE - 1 < NT) issue(kt + NSTAGE - 1);
    }

    // ---- epilogue ----
    #pragma unroll
    for (int mi = 0; mi < 4; mi++) {
        int row = m0 + wm*64 + mi*16 + g;
        #pragma unroll
        for (int ni = 0; ni < 4; ni++) {
            int col = n0 + wn*32 + ni*8 + t*2;
            float* a4 = acc[mi][ni];
            #pragma unroll
            for (int half_ = 0; half_ < 2; half_++) {
                int r = row + half_ * 8;
                float c0 = a4[half_*2 + 0], c1 = a4[half_*2 + 1];
                if (EPI == 0) {
                    *(__half2*)&Ch[(long)r * ldc + col] = __floats2half2_rn(c0, c1);
                } else if (EPI == 2) {
                    float r0 = fmaxf(c0, 0.f), r1 = fmaxf(c1, 0.f);
                    *(__half2*)&Ch[(long)r * ldc + col] = __floats2half2_rn(r0*r0, r1*r1);
                } else {
                    float* cp = &Cf[(long)r * ldc + col];
                    float2 o = *(float2*)cp;
                    float2 out = make_float2(o.x + c0, o.y + c1);
                    *(float2*)cp = out;
                    if (EPI == 4) *(float2*)&C2[(long)r * ldc + col] = out;
                }
            }
        }
    }
}

// ---------------- final norm -> output ----------------
__global__ __launch_bounds__(256)
void gpt_finalnorm(const float* __restrict__ x, float* __restrict__ out)
{
    __shared__ float red[256];
    int tid = threadIdx.x;
    const float* xr = x + (long)blockIdx.x * D_;
    float a0 = xr[tid], a1 = xr[tid + 256], a2 = xr[tid + 512];
    float ss = blockReduceSum256(a0*a0 + a1*a1 + a2*a2, red);
    float r = rsqrtf(ss / (float)D_ + EPSF);
    float* yr = out + (long)blockIdx.x * D_;
    yr[tid] = a0 * r; yr[tid + 256] = a1 * r; yr[tid + 512] = a2 * r;
}

// ---------------- host orchestration ----------------
#define SMEM4 (NSTAGE * (256 + 128) * 16 * 4)   // 98304
#define SMEM2 (NSTAGE * (128 + 128) * 16 * 4)   // 65536
#define SMEMF ((8192 + 2*8192) * 4)             // 98304 (flash)

extern "C" void kernel_launch(void* const* d_in, const int* in_sizes, int n_in,
                              void* d_out, int out_size)
{
    const int*   seq         = (const int*)  d_in[0];
    const float* embed_w     = (const float*)d_in[1];
    const float* ve_w        = (const float*)d_in[2];
    const float* qkv_w       = (const float*)d_in[3];
    const float* attn_proj_w = (const float*)d_in[4];
    const float* mlp_fc_w    = (const float*)d_in[5];
    const float* mlp_proj_w  = (const float*)d_in[6];
    const float* scalars     = (const float*)d_in[7];

    cudaFuncSetAttribute(gpt_gemm<0,4>, cudaFuncAttributeMaxDynamicSharedMemorySize, SMEM4);
    cudaFuncSetAttribute(gpt_gemm<2,4>, cudaFuncAttributeMaxDynamicSharedMemorySize, SMEM4);
    cudaFuncSetAttribute(gpt_gemm<1,2>, cudaFuncAttributeMaxDynamicSharedMemorySize, SMEM2);
    cudaFuncSetAttribute(gpt_gemm<4,2>, cudaFuncAttributeMaxDynamicSharedMemorySize, SMEM2);
    cudaFuncSetAttribute(gpt_flash,     cudaFuncAttributeMaxDynamicSharedMemorySize, SMEMF);

    float *x, *x0, *skips, *ve;
    float2 *rtab;
    __half *xn, *qkv, *q, *k, *vt, *att, *hbuf;
    __half *qkvw, *aprojw, *fcw, *mprojw;
    cudaGetSymbolAddress((void**)&x,      g_x);
    cudaGetSymbolAddress((void**)&x0,     g_x0);
    cudaGetSymbolAddress((void**)&xn,     g_xn);
    cudaGetSymbolAddress((void**)&skips,  g_skips);
    cudaGetSymbolAddress((void**)&ve,     g_ve);
    cudaGetSymbolAddress((void**)&qkv,    g_qkv);
    cudaGetSymbolAddress((void**)&q,      g_q);
    cudaGetSymbolAddress((void**)&k,      g_k);
    cudaGetSymbolAddress((void**)&vt,     g_vt);
    cudaGetSymbolAddress((void**)&att,    g_att);
    cudaGetSymbolAddress((void**)&hbuf,   g_hbuf);
    cudaGetSymbolAddress((void**)&rtab,   g_rtab);
    cudaGetSymbolAddress((void**)&qkvw,   g_qkvw);
    cudaGetSymbolAddress((void**)&aprojw, g_aprojw);
    cudaGetSymbolAddress((void**)&fcw,    g_fcw);
    cudaGetSymbolAddress((void**)&mprojw, g_mprojw);

    const int NTOK = B_ * T_;   // 4096

    // convert all weights to fp16 mirrors; build rope table
    gpt_cvtw<<<2048, 256>>>(qkv_w,       qkvw,   (long)L_*3*H_*HD_*D_);
    gpt_cvtw<<<2048, 256>>>(attn_proj_w, aprojw, (long)L_*D_*H_*HD_);
    gpt_cvtw<<<2048, 256>>>(mlp_fc_w,    fcw,    (long)L_*4*D_*D_);
    gpt_cvtw<<<2048, 256>>>(mlp_proj_w,  mprojw, (long)L_*D_*4*D_);
    gpt_ropetab<<<128, 256>>>(rtab);

    gpt_embed<<<NTOK, 256>>>(seq, embed_w, ve_w, x, x0, ve);

    for (int i = 0; i < L_; i++) {
        const float* skip = (i >= 6) ? (skips + (long)(11 - i) * BTD) : nullptr;
        gpt_resnorm<<<NTOK, 256>>>(x, x0, skip, scalars, i, xn);

        if (i != 7) {
            // qkv = xn @ W_qkv^T : [4096,768] x [2304,768]^T  -> half
            gpt_gemm<0,4><<<dim3(18, 16, 1), 512, SMEM4>>>(
                xn, qkvw + (long)i * 3 * H_ * HD_ * D_, qkv, nullptr,
                D_, D_, D_, 3*H_*HD_, 0, 0, 1, 0, 0, 1.f, 0);

            const float* vep = nullptr;
            if (i < 3)       vep = ve + (long)i * BTD;
            else if (i >= 9) vep = ve + (long)(i - 9) * BTD;
            gpt_rope<<<B_*T_*H_/8, 256>>>(qkv, vep, scalars, i, q, k, vt, rtab);

            // fused flash attention -> att (half)
            gpt_flash<<<dim3(8, B_*H_), 256, SMEMF>>>(q, k, vt, att);

            // x += att @ W_proj^T   (float accumulate)
            gpt_gemm<1,2><<<dim3(6, 32, 1), 256, SMEM2>>>(
                att, aprojw + (long)i * D_ * H_ * HD_, x, nullptr,
                H_*HD_, H_*HD_, H_*HD_, D_, 0, 0, 1, 0, 0, 1.f, 0);

            gpt_rmsnorm<<<NTOK, 256>>>(x, xn);
        }

        // h = relu(xn @ W_fc^T)^2 : [4096,768] x [3072,768]^T -> half
        gpt_gemm<2,4><<<dim3(24, 16, 1), 512, SMEM4>>>(
            xn, fcw + (long)i * 4 * D_ * D_, hbuf, nullptr,
            D_, D_, D_, 4*D_, 0, 0, 1, 0, 0, 1.f, 0);
        // x += h @ W_proj^T ; for i<6 also copy x into skip buffer
        if (i < 6) {
            gpt_gemm<4,2><<<dim3(6, 32, 1), 256, SMEM2>>>(
                hbuf, mprojw + (long)i * D_ * 4 * D_, x, skips + (long)i * BTD,
                4*D_, 4*D_, 4*D_, D_, 0, 0, 1, 0, 0, 1.f, 0);
        } else {
            gpt_gemm<1,2><<<dim3(6, 32, 1), 256, SMEM2>>>(
                hbuf, mprojw + (long)i * D_ * 4 * D_, x, nullptr,
                4*D_, 4*D_, 4*D_, D_, 0, 0, 1, 0, 0, 1.f, 0);
        }
    }

    gpt_finalnorm<<<NTOK, 256>>>(x, (float*)d_out);
}

// round 13
// speedup vs baseline: 6.6686x; 1.0825x over previous
#include <cuda_runtime.h>
#include <cuda_fp16.h>
#include <math.h>
#include <stdint.h>

#define B_  4
#define T_  1024
#define D_  768
#define H_  6
#define HD_ 128
#define L_  12
#define BTD (B_*T_*D_)          // 3145728
#define EPSF 1.1920929e-07f
#define BKH 32                  // k-halfs per tile (16 uint32 words)
#define NSTAGE 4

// ---------------- scratch (device globals; no allocation allowed) ----------------
__device__ float  g_x   [BTD];
__device__ float  g_x0  [BTD];
__device__ __half g_xn  [BTD];
__device__ float  g_skips[6*BTD];
__device__ float  g_ve  [3*BTD];
__device__ __half g_qkv [B_*T_*3*H_*HD_];      // [bt][which*768 + h*128 + hd]
__device__ __half g_q   [B_*H_*T_*HD_];        // [b][h][t][hd]
__device__ __half g_k   [B_*H_*T_*HD_];
__device__ __half g_vt  [B_*H_*HD_*T_];        // [b][h][hd][t]  (transposed V)
__device__ __half g_att [BTD];                 // [b][t][h*128+hd]
__device__ __half g_hbuf[B_*T_*4*D_];          // [bt][3072]
__device__ float2 g_rtab[T_*32];               // rope cos/sin table
// fp16 weight mirrors
__device__ __half g_qkvw [L_*3*H_*HD_*D_];
__device__ __half g_aprojw[L_*D_*H_*HD_];
__device__ __half g_fcw  [L_*4*D_*D_];
__device__ __half g_mprojw[L_*D_*4*D_];

// ---------------- helpers ----------------
__device__ __forceinline__ float blockReduceSum256(float v, float* red) {
    int tid = threadIdx.x;
    red[tid] = v; __syncthreads();
    for (int s = 128; s > 0; s >>= 1) {
        if (tid < s) red[tid] += red[tid + s];
        __syncthreads();
    }
    float r = red[0]; __syncthreads();
    return r;
}

__device__ __forceinline__ void mma16(float* c, const uint32_t* a, const uint32_t* b) {
    asm volatile(
        "mma.sync.aligned.m16n8k16.row.col.f32.f16.f16.f32 "
        "{%0,%1,%2,%3}, {%4,%5,%6,%7}, {%8,%9}, {%0,%1,%2,%3};"
        : "+f"(c[0]), "+f"(c[1]), "+f"(c[2]), "+f"(c[3])
        : "r"(a[0]), "r"(a[1]), "r"(a[2]), "r"(a[3]), "r"(b[0]), "r"(b[1]));
}

__device__ __forceinline__ void cp16(uint32_t saddr, const void* gptr) {
    asm volatile("cp.async.cg.shared.global [%0], [%1], 16;" :: "r"(saddr), "l"(gptr));
}

// swizzle: column-group permutation within a 16-word row
__device__ __forceinline__ int swz(int r, int cg) { return cg ^ ((r >> 1) & 3); }

__device__ __forceinline__ uint32_t packh2(float a, float b) {
    __half2 h = __floats2half2_rn(a, b);
    return *(uint32_t*)&h;
}

// ---------------- weight conversion fp32 -> fp16 (rne) ----------------
__global__ __launch_bounds__(256)
void gpt_cvtw(const float* __restrict__ src, __half* __restrict__ dst, long n)
{
    long i = ((long)blockIdx.x * 256 + threadIdx.x) * 4;
    long stride = (long)gridDim.x * 1024;
    for (; i < n; i += stride) {
        float4 v = *(const float4*)&src[i];
        __half2* d = (__half2*)&dst[i];
        d[0] = __floats2half2_rn(v.x, v.y);
        d[1] = __floats2half2_rn(v.z, v.w);
    }
}

// ---------------- rope table: cos/sin(t * freq_j), layer-invariant ----------------
__global__ __launch_bounds__(256)
void gpt_ropetab(float2* __restrict__ rtab)
{
    int i = blockIdx.x * 256 + threadIdx.x;   // t*32 + j, 32768 entries
    int t = i >> 5, j = i & 31;
    float freq = exp2f(-10.0f * (float)j / 31.0f);
    float sn, cs;
    sincosf((float)t * freq, &sn, &cs);
    rtab[i] = make_float2(cs, sn);
}

// ---------------- embedding + norm + ve gather ----------------
__global__ __launch_bounds__(256)
void gpt_embed(const int* __restrict__ seq, const float* __restrict__ ew,
               const float* __restrict__ vew,
               float* __restrict__ x, float* __restrict__ x0, float* __restrict__ ve)
{
    __shared__ float red[256];
    int bt = blockIdx.x;
    int tid = threadIdx.x;
    int idx = seq[bt];
    const float* er = ew + (long)idx * D_;
    float a0 = er[tid], a1 = er[tid + 256], a2 = er[tid + 512];
    float ss = blockReduceSum256(a0*a0 + a1*a1 + a2*a2, red);
    float r = rsqrtf(ss / (float)D_ + EPSF);
    long o = (long)bt * D_;
    x0[o + tid]       = a0 * r;  x[o + tid]       = a0 * r;
    x0[o + tid + 256] = a1 * r;  x[o + tid + 256] = a1 * r;
    x0[o + tid + 512] = a2 * r;  x[o + tid + 512] = a2 * r;
    #pragma unroll
    for (int j = 0; j < 3; j++) {
        const float* vr = vew + ((long)j * 50257 + idx) * D_;
        float* vo = ve + ((long)j * (B_*T_) + bt) * D_;
        for (int d = tid; d < D_; d += 256) vo[d] = vr[d];
    }
}

// ------- fused residual + rms norm: x = l0*(x + sw*skip) + l1*x0 ; xn = h(norm(x))
__global__ __launch_bounds__(256)
void gpt_resnorm(float* __restrict__ x, const float* __restrict__ x0,
                 const float* __restrict__ skip, const float* __restrict__ scalars,
                 int layer, __half* __restrict__ xn)
{
    __shared__ float red[256];
    float l0 = scalars[L_ + 2*layer];
    float l1 = scalars[L_ + 2*layer + 1];
    float sw = skip ? scalars[layer - 6] : 0.f;
    int tid = threadIdx.x;
    long o = (long)blockIdx.x * D_;
    float a[3];
    #pragma unroll
    for (int j = 0; j < 3; j++) {
        long i = o + tid + j*256;
        float v = x[i];
        if (skip) v += sw * skip[i];
        v = l0 * v + l1 * x0[i];
        x[i] = v;
        a[j] = v;
    }
    float ss = blockReduceSum256(a[0]*a[0] + a[1]*a[1] + a[2]*a[2], red);
    float r = rsqrtf(ss / (float)D_ + EPSF);
    #pragma unroll
    for (int j = 0; j < 3; j++)
        xn[o + tid + j*256] = __float2half_rn(a[j] * r);
}

// ---------------- rms norm (row = 768), output fp16 ----------------
__global__ __launch_bounds__(256)
void gpt_rmsnorm(const float* __restrict__ x, __half* __restrict__ y)
{
    __shared__ float red[256];
    int tid = threadIdx.x;
    const float* xr = x + (long)blockIdx.x * D_;
    float a0 = xr[tid], a1 = xr[tid + 256], a2 = xr[tid + 512];
    float ss = blockReduceSum256(a0*a0 + a1*a1 + a2*a2, red);
    float r = rsqrtf(ss / (float)D_ + EPSF);
    __half* yr = y + (long)blockIdx.x * D_;
    yr[tid]       = __float2half_rn(a0 * r);
    yr[tid + 256] = __float2half_rn(a1 * r);
    yr[tid + 512] = __float2half_rn(a2 * r);
}

// ---------------- copy (for skip buffers) ----------------
__global__ __launch_bounds__(256)
void gpt_copy(float* __restrict__ dst, const float* __restrict__ src)
{
    long i = ((long)blockIdx.x * 256 + threadIdx.x) * 4;
    float4 v = *(const float4*)&src[i];
    *(float4*)&dst[i] = v;
}

// ------- warp-level rope: one warp per (b,t,h); lane owns hd = lane + 32*j -------
__global__ __launch_bounds__(256)
void gpt_rope(const __half* __restrict__ qkv, const float* __restrict__ ve,
              const float* __restrict__ scalars, int layer,
              __half* __restrict__ q, __half* __restrict__ k, __half* __restrict__ vt,
              const float2* __restrict__ rtab)
{
    int z = blockIdx.x * 8 + (threadIdx.x >> 5);
    int lane = threadIdx.x & 31;
    int h = z % H_;
    int t = (z / H_) % T_;
    int b = z / (H_ * T_);
    long bt = (long)b * T_ + t;
    const __half* base = qkv + bt * (3*H_*HD_) + h * HD_;

    float qv[4], kv[4], vv[4];
    #pragma unroll
    for (int j = 0; j < 4; j++) {
        qv[j] = __half2float(base[lane + 32*j]);
        kv[j] = __half2float(base[H_*HD_ + lane + 32*j]);
        vv[j] = __half2float(base[2*H_*HD_ + lane + 32*j]);
    }
    float sq = qv[0]*qv[0] + qv[1]*qv[1] + qv[2]*qv[2] + qv[3]*qv[3];
    float sk = kv[0]*kv[0] + kv[1]*kv[1] + kv[2]*kv[2] + kv[3]*kv[3];
    #pragma unroll
    for (int s = 16; s > 0; s >>= 1) {
        sq += __shfl_xor_sync(0xffffffff, sq, s);
        sk += __shfl_xor_sync(0xffffffff, sk, s);
    }
    float rnq = rsqrtf(sq / (float)HD_ + EPSF);
    float rnk = rsqrtf(sk / (float)HD_ + EPSF);
    #pragma unroll
    for (int j = 0; j < 4; j++) { qv[j] *= rnq; kv[j] *= rnk; }

    float2 cs = rtab[t*32 + lane];
    float oq0 =  qv[0]*cs.x + qv[2]*cs.y;
    float oq2 = -qv[0]*cs.y + qv[2]*cs.x;
    float ok0 =  kv[0]*cs.x + kv[2]*cs.y;
    float ok2 = -kv[0]*cs.y + kv[2]*cs.x;

    long o = (((long)b * H_ + h) * T_ + t) * HD_;
    q[o + lane]      = __float2half_rn(oq0);
    q[o + lane + 32] = __float2half_rn(qv[1]);
    q[o + lane + 64] = __float2half_rn(oq2);
    q[o + lane + 96] = __float2half_rn(qv[3]);
    k[o + lane]      = __float2half_rn(ok0);
    k[o + lane + 32] = __float2half_rn(kv[1]);
    k[o + lane + 64] = __float2half_rn(ok2);
    k[o + lane + 96] = __float2half_rn(kv[3]);

    float sa0 = scalars[3*L_ + 2*layer];
    float sa1 = scalars[3*L_ + 2*layer + 1];
    long vbase = ((long)b * H_ + h) * HD_;
    #pragma unroll
    for (int j = 0; j < 4; j++) {
        float vo = sa0 * vv[j];
        if (ve) vo += sa1 * ve[bt * D_ + h * HD_ + lane + 32*j];
        vt[(vbase + lane + 32*j) * T_ + t] = __float2half_rn(vo);
    }
}

// =================================================================================
// Fused flash attention: 128 q-rows per CTA (8 warps), K/V tiles of 64, online
// softmax, double-buffered cp.async K/V. Q/K: [b][h][t][hd]; V: [b][h][hd][t].
// =================================================================================
__global__ void __launch_bounds__(256, 1)
gpt_flash(const __half* __restrict__ Q, const __half* __restrict__ K,
          const __half* __restrict__ Vt, __half* __restrict__ att)
{
    const int qt = 7 - blockIdx.x;            // heavy tiles first
    const int bh = blockIdx.y;
    const int b = bh / H_, h = bh % H_;
    const int tid = threadIdx.x;
    const int w = tid >> 5, lane = tid & 31;
    const int g = lane >> 2, t = lane & 3;

    const __half* Qb = Q  + (((long)bh * T_) + qt*128) * HD_;
    const __half* Kb = K  + (long)bh * T_ * HD_;
    const __half* Vb = Vt + (long)bh * HD_ * T_;

    extern __shared__ uint32_t sm[];
    uint32_t sbase = (uint32_t)__cvta_generic_to_shared(sm);

    #pragma unroll
    for (int j = 0; j < 8; j++) {
        int i = tid + j*256;
        int row = i >> 4, c16 = i & 15;
        int kc = c16 >> 2, wg = c16 & 3;
        uint32_t word = (kc*128 + row)*16 + swz(row, wg)*4;
        cp16(sbase + 4u*word, Qb + row*HD_ + c16*8);
    }
    asm volatile("cp.async.commit_group;" ::: "memory");

    const int NT = 2*qt + 2;

    auto issueKV = [&](int kt) {
        int s = kt & 1;
        uint32_t kw0 = 8192 + s*8192;
        #pragma unroll
        for (int j = 0; j < 4; j++) {
            int i = tid + j*256;
            int row = i >> 4, c16 = i & 15;
            int kc = c16 >> 2, wg = c16 & 3;
            uint32_t word = kw0 + (kc*64 + row)*16 + swz(row, wg)*4;
            cp16(sbase + 4u*word, Kb + (long)(kt*64 + row)*HD_ + c16*8);
        }
        uint32_t vw0 = 12288 + s*8192;
        #pragma unroll
        for (int j = 0; j < 4; j++) {
            int i = tid + j*256;
            int row = i >> 3, c16 = i & 7;
            int kc = c16 >> 2, wg = c16 & 3;
            uint32_t word = vw0 + (kc*128 + row)*16 + swz(row, wg)*4;
            cp16(sbase + 4u*word, Vb + (long)row*T_ + kt*64 + c16*8);
        }
        asm volatile("cp.async.commit_group;" ::: "memory");
    };

    issueKV(0); issueKV(1);

    float m0 = -1e30f, m1 = -1e30f, l0 = 0.f, l1 = 0.f;
    float oacc[16][4];
    #pragma unroll
    for (int a = 0; a < 16; a++)
        #pragma unroll
        for (int c = 0; c < 4; c++) oacc[a][c] = 0.f;

    const int r0 = w*16 + g;
    const int grow = qt*128 + r0;

    for (int kt = 0; kt < NT; kt++) {
        if (kt + 1 < NT) asm volatile("cp.async.wait_group 1;" ::: "memory");
        else             asm volatile("cp.async.wait_group 0;" ::: "memory");
        __syncthreads();

        const uint32_t* Kc = sm + 8192 + (kt & 1)*8192;
        const uint32_t* Vc = sm + 12288 + (kt & 1)*8192;

        float sacc[8][4];
        #pragma unroll
        for (int a = 0; a < 8; a++)
            #pragma unroll
            for (int c = 0; c < 4; c++) sacc[a][c] = 0.f;

        #pragma unroll
        for (int kc = 0; kc < 4; kc++) {
            const uint32_t* Qc = sm + kc*2048;
            const uint32_t* Kk = Kc + kc*1024;
            #pragma unroll
            for (int ks = 0; ks < 2; ks++) {
                int s0 = swz(r0, ks*2)*4 + t;
                int s1 = swz(r0, ks*2 + 1)*4 + t;
                uint32_t af[4];
                af[0] = Qc[r0*16 + s0];
                af[1] = Qc[(r0+8)*16 + s0];
                af[2] = Qc[r0*16 + s1];
                af[3] = Qc[(r0+8)*16 + s1];
                #pragma unroll
                for (int ni = 0; ni < 8; ni++) {
                    int nr = ni*8 + g;
                    uint32_t bf[2];
                    bf[0] = Kk[nr*16 + swz(nr, ks*2)*4 + t];
                    bf[1] = Kk[nr*16 + swz(nr, ks*2 + 1)*4 + t];
                    mma16(sacc[ni], af, bf);
                }
            }
        }

        bool diag = (kt >= 2*qt);
        #pragma unroll
        for (int ni = 0; ni < 8; ni++) {
            int col = kt*64 + ni*8 + t*2;
            float v0 = 0.12f * sacc[ni][0];
            float v1 = 0.12f * sacc[ni][1];
            float v2 = 0.12f * sacc[ni][2];
            float v3 = 0.12f * sacc[ni][3];
            if (diag) {
                if (col     > grow)     v0 = -1e30f;
                if (col + 1 > grow)     v1 = -1e30f;
                if (col     > grow + 8) v2 = -1e30f;
                if (col + 1 > grow + 8) v3 = -1e30f;
            }
            sacc[ni][0] = v0; sacc[ni][1] = v1; sacc[ni][2] = v2; sacc[ni][3] = v3;
        }

        float rm0 = -1e30f, rm1 = -1e30f;
        #pragma unroll
        for (int ni = 0; ni < 8; ni++) {
            rm0 = fmaxf(rm0, fmaxf(sacc[ni][0], sacc[ni][1]));
            rm1 = fmaxf(rm1, fmaxf(sacc[ni][2], sacc[ni][3]));
        }
        rm0 = fmaxf(rm0, __shfl_xor_sync(0xffffffff, rm0, 1));
        rm0 = fmaxf(rm0, __shfl_xor_sync(0xffffffff, rm0, 2));
        rm1 = fmaxf(rm1, __shfl_xor_sync(0xffffffff, rm1, 1));
        rm1 = fmaxf(rm1, __shfl_xor_sync(0xffffffff, rm1, 2));

        float mn0 = fmaxf(m0, rm0), mn1 = fmaxf(m1, rm1);
        float sc0 = __expf(m0 - mn0), sc1 = __expf(m1 - mn1);
        m0 = mn0; m1 = mn1;

        float ls0 = 0.f, ls1 = 0.f;
        uint32_t phg[8], phg8[8];
        #pragma unroll
        for (int ni = 0; ni < 8; ni++) {
            float p0 = __expf(sacc[ni][0] - mn0);
            float p1 = __expf(sacc[ni][1] - mn0);
            float p2 = __expf(sacc[ni][2] - mn1);
            float p3 = __expf(sacc[ni][3] - mn1);
            ls0 += p0 + p1; ls1 += p2 + p3;
            phg[ni]  = packh2(p0, p1);
            phg8[ni] = packh2(p2, p3);
        }
        ls0 += __shfl_xor_sync(0xffffffff, ls0, 1);
        ls0 += __shfl_xor_sync(0xffffffff, ls0, 2);
        ls1 += __shfl_xor_sync(0xffffffff, ls1, 1);
        ls1 += __shfl_xor_sync(0xffffffff, ls1, 2);
        l0 = l0*sc0 + ls0;
        l1 = l1*sc1 + ls1;

        #pragma unroll
        for (int ni = 0; ni < 16; ni++) {
            oacc[ni][0] *= sc0; oacc[ni][1] *= sc0;
            oacc[ni][2] *= sc1; oacc[ni][3] *= sc1;
        }

        #pragma unroll
        for (int kk = 0; kk < 4; kk++) {
            uint32_t af[4] = { phg[2*kk], phg8[2*kk], phg[2*kk+1], phg8[2*kk+1] };
            const uint32_t* Vk = Vc + (kk >> 1)*2048;
            int ks = kk & 1;
            #pragma unroll
            for (int ni = 0; ni < 16; ni++) {
                int nr = ni*8 + g;
                uint32_t bf[2];
                bf[0] = Vk[nr*16 + swz(nr, ks*2)*4 + t];
                bf[1] = Vk[nr*16 + swz(nr, ks*2 + 1)*4 + t];
                mma16(oacc[ni], af, bf);
            }
        }

        __syncthreads();
        if (kt + 2 < NT) issueKV(kt + 2);
    }

    float inv0 = 1.f / l0, inv1 = 1.f / l1;
    long base0 = ((long)b*T_ + grow) * D_ + h*HD_;
    long base1 = base0 + 8L*D_;
    #pragma unroll
    for (int ni = 0; ni < 16; ni++) {
        int col = ni*8 + t*2;
        *(uint32_t*)&att[base0 + col] = packh2(oacc[ni][0]*inv0, oacc[ni][1]*inv0);
        *(uint32_t*)&att[base1 + col] = packh2(oacc[ni][2]*inv1, oacc[ni][3]*inv1);
    }
}

// =================================================================================
// fp16 tensor-core GEMM (m16n8k16, fp32 accum), cp.async 4-stage pipeline.
// EPI: 0=store half, 1=accumulate into float C, 2=relu^2 store half,
//      5=split-K atomicAdd into float C (blockIdx.z = K-split; aZ/bZ = col offset)
// =================================================================================
template<int EPI, int MT>
__global__ void
__launch_bounds__(MT == 4 ? 512 : 256, MT == 4 ? 1 : 2)
gpt_gemm(const __half* __restrict__ A, const __half* __restrict__ Bm, void* __restrict__ Cv,
         float* __restrict__ C2,
         int K, int lda, int ldb, int ldc,
         long aZ, long bZ, int zdiv, long c1, long c2, float alpha, int ktri)
{
    constexpr int THREADS = (MT == 4) ? 512 : 256;
    constexpr int BM = MT * 64;
    constexpr int AROWS = THREADS / 4;
    constexpr int APASS = BM / AROWS;
    constexpr int BPASS = 128 / AROWS;

    const int m0 = blockIdx.y * BM, n0 = blockIdx.x * 128;

    int z = blockIdx.z;
    A  += (long)z * aZ;
    Bm += (long)z * bZ;
    long coff = (long)(z / zdiv) * c1 + (long)(z % zdiv) * c2;
    float*  Cf = (float*)Cv + coff;
    __half* Ch = (__half*)Cv + coff;

    const int tid  = threadIdx.x;
    const int lane = tid & 31, warp = tid >> 5;
    const int wm = warp >> 2, wn = warp & 3;
    const int g = lane >> 2, t = lane & 3;

    extern __shared__ uint32_t smem[];
    uint32_t* As = smem;
    uint32_t* Bs = smem + NSTAGE * BM * 16;
    uint32_t as0 = (uint32_t)__cvta_generic_to_shared(As);
    uint32_t bs0 = (uint32_t)__cvta_generic_to_shared(Bs);

    int keff = K;
    if (ktri) { int kk = m0 + BM; keff = kk < K ? kk : K; }
    const int NT = keff / BKH;

    float acc[4][4][4];
    #pragma unroll
    for (int a = 0; a < 4; a++)
        #pragma unroll
        for (int b = 0; b < 4; b++)
            #pragma unroll
            for (int c = 0; c < 4; c++) acc[a][b][c] = 0.f;

    const int ar  = tid >> 2;
    const int acg = tid & 3;
    const __half* apB = A  + (long)(m0 + ar) * lda + acg*8;
    const __half* bpB = Bm + (long)(n0 + ar) * ldb + acg*8;

    auto issue = [&](int kt) {
        int s = kt % NSTAGE;
        const __half* ap = apB + kt*BKH;
        #pragma unroll
        for (int j = 0; j < APASS; j++) {
            int r = ar + AROWS*j;
            cp16(as0 + 4u*(s*BM*16 + r*16 + swz(r, acg)*4), ap + (long)(AROWS*j) * lda);
        }
        const __half* bp = bpB + kt*BKH;
        #pragma unroll
        for (int j = 0; j < BPASS; j++) {
            int r = ar + AROWS*j;
            cp16(bs0 + 4u*(s*128*16 + r*16 + swz(r, acg)*4), bp + (long)(AROWS*j) * ldb);
        }
        asm volatile("cp.async.commit_group;" ::: "memory");
    };

    issue(0); issue(1); issue(2);

    for (int kt = 0; kt < NT; kt++) {
        if (kt + 1 >= NT)      asm volatile("cp.async.wait_group 0;" ::: "memory");
        else if (kt + 2 >= NT) asm volatile("cp.async.wait_group 1;" ::: "memory");
        else                   asm volatile("cp.async.wait_group 2;" ::: "memory");
        __syncthreads();

        const uint32_t* Ab = As + (kt % NSTAGE) * BM * 16;
        const uint32_t* Bb = Bs + (kt % NSTAGE) * 128 * 16;
        #pragma unroll
        for (int ks = 0; ks < 2; ks++) {
            uint32_t af[4][4];
            #pragma unroll
            for (int mi = 0; mi < 4; mi++) {
                int r0 = wm*64 + mi*16 + g;
                int s0 = swz(r0, ks*2)*4 + t;
                int s1 = swz(r0, ks*2 + 1)*4 + t;
                af[mi][0] = Ab[r0*16 + s0];
                af[mi][1] = Ab[(r0+8)*16 + s0];
                af[mi][2] = Ab[r0*16 + s1];
                af[mi][3] = Ab[(r0+8)*16 + s1];
            }
            uint32_t bf[4][2];
            #pragma unroll
            for (int ni = 0; ni < 4; ni++) {
                int nr = wn*32 + ni*8 + g;
                bf[ni][0] = Bb[nr*16 + swz(nr, ks*2)*4 + t];
                bf[ni][1] = Bb[nr*16 + swz(nr, ks*2 + 1)*4 + t];
            }
            #pragma unroll
            for (int mi = 0; mi < 4; mi++)
                #pragma unroll
                for (int ni = 0; ni < 4; ni++)
                    mma16(acc[mi][ni], af[mi], bf[ni]);
        }

        if (kt + NSTAGE - 1 < NT) issue(kt + NSTAGE - 1);
    }

    // ---- epilogue ----
    #pragma unroll
    for (int mi = 0; mi < 4; mi++) {
        int row = m0 + wm*64 + mi*16 + g;
        #pragma unroll
        for (int ni = 0; ni < 4; ni++) {
            int col = n0 + wn*32 + ni*8 + t*2;
            float* a4 = acc[mi][ni];
            #pragma unroll
            for (int half_ = 0; half_ < 2; half_++) {
                int r = row + half_ * 8;
                float c0 = a4[half_*2 + 0], c1 = a4[half_*2 + 1];
                if (EPI == 0) {
                    *(__half2*)&Ch[(long)r * ldc + col] = __floats2half2_rn(c0, c1);
                } else if (EPI == 2) {
                    float r0 = fmaxf(c0, 0.f), r1 = fmaxf(c1, 0.f);
                    *(__half2*)&Ch[(long)r * ldc + col] = __floats2half2_rn(r0*r0, r1*r1);
                } else if (EPI == 5) {
                    atomicAdd(&Cf[(long)r * ldc + col],     c0);
                    atomicAdd(&Cf[(long)r * ldc + col + 1], c1);
                } else {  // EPI == 1
                    float* cp = &Cf[(long)r * ldc + col];
                    float2 o = *(float2*)cp;
                    *(float2*)cp = make_float2(o.x + c0, o.y + c1);
                }
            }
        }
    }
}

// ---------------- final norm -> output ----------------
__global__ __launch_bounds__(256)
void gpt_finalnorm(const float* __restrict__ x, float* __restrict__ out)
{
    __shared__ float red[256];
    int tid = threadIdx.x;
    const float* xr = x + (long)blockIdx.x * D_;
    float a0 = xr[tid], a1 = xr[tid + 256], a2 = xr[tid + 512];
    float ss = blockReduceSum256(a0*a0 + a1*a1 + a2*a2, red);
    float r = rsqrtf(ss / (float)D_ + EPSF);
    float* yr = out + (long)blockIdx.x * D_;
    yr[tid] = a0 * r; yr[tid + 256] = a1 * r; yr[tid + 512] = a2 * r;
}

// ---------------- host orchestration ----------------
#define SMEM4 (NSTAGE * (256 + 128) * 16 * 4)   // 98304
#define SMEM2 (NSTAGE * (128 + 128) * 16 * 4)   // 65536
#define SMEMF ((8192 + 2*8192) * 4)             // 98304 (flash)

extern "C" void kernel_launch(void* const* d_in, const int* in_sizes, int n_in,
                              void* d_out, int out_size)
{
    const int*   seq         = (const int*)  d_in[0];
    const float* embed_w     = (const float*)d_in[1];
    const float* ve_w        = (const float*)d_in[2];
    const float* qkv_w       = (const float*)d_in[3];
    const float* attn_proj_w = (const float*)d_in[4];
    const float* mlp_fc_w    = (const float*)d_in[5];
    const float* mlp_proj_w  = (const float*)d_in[6];
    const float* scalars     = (const float*)d_in[7];

    cudaFuncSetAttribute(gpt_gemm<0,4>, cudaFuncAttributeMaxDynamicSharedMemorySize, SMEM4);
    cudaFuncSetAttribute(gpt_gemm<2,4>, cudaFuncAttributeMaxDynamicSharedMemorySize, SMEM4);
    cudaFuncSetAttribute(gpt_gemm<5,2>, cudaFuncAttributeMaxDynamicSharedMemorySize, SMEM2);
    cudaFuncSetAttribute(gpt_flash,     cudaFuncAttributeMaxDynamicSharedMemorySize, SMEMF);

    float *x, *x0, *skips, *ve;
    float2 *rtab;
    __half *xn, *qkv, *q, *k, *vt, *att, *hbuf;
    __half *qkvw, *aprojw, *fcw, *mprojw;
    cudaGetSymbolAddress((void**)&x,      g_x);
    cudaGetSymbolAddress((void**)&x0,     g_x0);
    cudaGetSymbolAddress((void**)&xn,     g_xn);
    cudaGetSymbolAddress((void**)&skips,  g_skips);
    cudaGetSymbolAddress((void**)&ve,     g_ve);
    cudaGetSymbolAddress((void**)&qkv,    g_qkv);
    cudaGetSymbolAddress((void**)&q,      g_q);
    cudaGetSymbolAddress((void**)&k,      g_k);
    cudaGetSymbolAddress((void**)&vt,     g_vt);
    cudaGetSymbolAddress((void**)&att,    g_att);
    cudaGetSymbolAddress((void**)&hbuf,   g_hbuf);
    cudaGetSymbolAddress((void**)&rtab,   g_rtab);
    cudaGetSymbolAddress((void**)&qkvw,   g_qkvw);
    cudaGetSymbolAddress((void**)&aprojw, g_aprojw);
    cudaGetSymbolAddress((void**)&fcw,    g_fcw);
    cudaGetSymbolAddress((void**)&mprojw, g_mprojw);

    const int NTOK = B_ * T_;   // 4096

    gpt_cvtw<<<2048, 256>>>(qkv_w,       qkvw,   (long)L_*3*H_*HD_*D_);
    gpt_cvtw<<<2048, 256>>>(attn_proj_w, aprojw, (long)L_*D_*H_*HD_);
    gpt_cvtw<<<2048, 256>>>(mlp_fc_w,    fcw,    (long)L_*4*D_*D_);
    gpt_cvtw<<<2048, 256>>>(mlp_proj_w,  mprojw, (long)L_*D_*4*D_);
    gpt_ropetab<<<128, 256>>>(rtab);

    gpt_embed<<<NTOK, 256>>>(seq, embed_w, ve_w, x, x0, ve);

    for (int i = 0; i < L_; i++) {
        const float* skip = (i >= 6) ? (skips + (long)(11 - i) * BTD) : nullptr;
        gpt_resnorm<<<NTOK, 256>>>(x, x0, skip, scalars, i, xn);

        if (i != 7) {
            // qkv = xn @ W_qkv^T : [4096,768] x [2304,768]^T  -> half
            gpt_gemm<0,4><<<dim3(18, 16, 1), 512, SMEM4>>>(
                xn, qkvw + (long)i * 3 * H_ * HD_ * D_, qkv, nullptr,
                D_, D_, D_, 3*H_*HD_, 0, 0, 1, 0, 0, 1.f, 0);

            const float* vep = nullptr;
            if (i < 3)       vep = ve + (long)i * BTD;
            else if (i >= 9) vep = ve + (long)(i - 9) * BTD;
            gpt_rope<<<B_*T_*H_/8, 256>>>(qkv, vep, scalars, i, q, k, vt, rtab);

            // fused flash attention -> att (half)
            gpt_flash<<<dim3(8, B_*H_), 256, SMEMF>>>(q, k, vt, att);

            // x += att @ W_proj^T  (split-K=2, atomicAdd)
            gpt_gemm<5,2><<<dim3(6, 32, 2), 256, SMEM2>>>(
                att, aprojw + (long)i * D_ * H_ * HD_, x, nullptr,
                (H_*HD_)/2, H_*HD_, H_*HD_, D_,
                (H_*HD_)/2, (H_*HD_)/2, 1, 0, 0, 1.f, 0);

            gpt_rmsnorm<<<NTOK, 256>>>(x, xn);
        }

        // h = relu(xn @ W_fc^T)^2 : [4096,768] x [3072,768]^T -> half
        gpt_gemm<2,4><<<dim3(24, 16, 1), 512, SMEM4>>>(
            xn, fcw + (long)i * 4 * D_ * D_, hbuf, nullptr,
            D_, D_, D_, 4*D_, 0, 0, 1, 0, 0, 1.f, 0);

        // x += h @ W_proj^T  (split-K=2, atomicAdd)
        gpt_gemm<5,2><<<dim3(6, 32, 2), 256, SMEM2>>>(
            hbuf, mprojw + (long)i * D_ * 4 * D_, x, nullptr,
            (4*D_)/2, 4*D_, 4*D_, D_,
            (4*D_)/2, (4*D_)/2, 1, 0, 0, 1.f, 0);

        if (i < 6) gpt_copy<<<BTD/1024, 256>>>(skips + (long)i * BTD, x);
    }

    gpt_finalnorm<<<NTOK, 256>>>(x, (float*)d_out);
}

// round 14
// speedup vs baseline: 6.6717x; 1.0005x over previous
#include <cuda_runtime.h>
#include <cuda_fp16.h>
#include <math.h>
#include <stdint.h>

#define B_  4
#define T_  1024
#define D_  768
#define H_  6
#define HD_ 128
#define L_  12
#define BTD (B_*T_*D_)          // 3145728
#define EPSF 1.1920929e-07f
#define BKH 32                  // k-halfs per tile (16 uint32 words)
#define NSTAGE 4

// ---------------- scratch (device globals; no allocation allowed) ----------------
__device__ float  g_x   [BTD];
__device__ float  g_x0  [BTD];
__device__ __half g_xn  [BTD];
__device__ float  g_skips[6*BTD];
__device__ float  g_ve  [3*BTD];
__device__ __half g_qkv [B_*T_*3*H_*HD_];      // [bt][which*768 + h*128 + hd]
__device__ __half g_q   [B_*H_*T_*HD_];        // [b][h][t][hd]
__device__ __half g_k   [B_*H_*T_*HD_];
__device__ __half g_vt  [B_*H_*HD_*T_];        // [b][h][hd][t]  (transposed V)
__device__ __half g_att [BTD];                 // [b][t][h*128+hd]
__device__ __half g_hbuf[B_*T_*4*D_];          // [bt][3072]
__device__ float2 g_rtab[T_*32];               // rope cos/sin table
// fp16 weight mirrors
__device__ __half g_qkvw [L_*3*H_*HD_*D_];
__device__ __half g_aprojw[L_*D_*H_*HD_];
__device__ __half g_fcw  [L_*4*D_*D_];
__device__ __half g_mprojw[L_*D_*4*D_];

// ---------------- helpers ----------------
__device__ __forceinline__ float blockReduceSum256(float v, float* red) {
    int tid = threadIdx.x;
    red[tid] = v; __syncthreads();
    for (int s = 128; s > 0; s >>= 1) {
        if (tid < s) red[tid] += red[tid + s];
        __syncthreads();
    }
    float r = red[0]; __syncthreads();
    return r;
}

__device__ __forceinline__ void mma16(float* c, const uint32_t* a, const uint32_t* b) {
    asm volatile(
        "mma.sync.aligned.m16n8k16.row.col.f32.f16.f16.f32 "
        "{%0,%1,%2,%3}, {%4,%5,%6,%7}, {%8,%9}, {%0,%1,%2,%3};"
        : "+f"(c[0]), "+f"(c[1]), "+f"(c[2]), "+f"(c[3])
        : "r"(a[0]), "r"(a[1]), "r"(a[2]), "r"(a[3]), "r"(b[0]), "r"(b[1]));
}

__device__ __forceinline__ void cp16(uint32_t saddr, const void* gptr) {
    asm volatile("cp.async.cg.shared.global [%0], [%1], 16;" :: "r"(saddr), "l"(gptr));
}

// swizzle: column-group permutation within a 16-word row
__device__ __forceinline__ int swz(int r, int cg) { return cg ^ ((r >> 1) & 3); }

__device__ __forceinline__ uint32_t packh2(float a, float b) {
    __half2 h = __floats2half2_rn(a, b);
    return *(uint32_t*)&h;
}

// ---------------- weight conversion fp32 -> fp16 (rne) ----------------
__global__ __launch_bounds__(256)
void gpt_cvtw(const float* __restrict__ src, __half* __restrict__ dst, long n)
{
    long i = ((long)blockIdx.x * 256 + threadIdx.x) * 4;
    long stride = (long)gridDim.x * 1024;
    for (; i < n; i += stride) {
        float4 v = *(const float4*)&src[i];
        __half2* d = (__half2*)&dst[i];
        d[0] = __floats2half2_rn(v.x, v.y);
        d[1] = __floats2half2_rn(v.z, v.w);
    }
}

// ---------------- rope table: cos/sin(t * freq_j), layer-invariant ----------------
__global__ __launch_bounds__(256)
void gpt_ropetab(float2* __restrict__ rtab)
{
    int i = blockIdx.x * 256 + threadIdx.x;   // t*32 + j, 32768 entries
    int t = i >> 5, j = i & 31;
    float freq = exp2f(-10.0f * (float)j / 31.0f);
    float sn, cs;
    sincosf((float)t * freq, &sn, &cs);
    rtab[i] = make_float2(cs, sn);
}

// ---------------- embedding + norm + ve gather ----------------
__global__ __launch_bounds__(256)
void gpt_embed(const int* __restrict__ seq, const float* __restrict__ ew,
               const float* __restrict__ vew,
               float* __restrict__ x, float* __restrict__ x0, float* __restrict__ ve)
{
    __shared__ float red[256];
    int bt = blockIdx.x;
    int tid = threadIdx.x;
    int idx = seq[bt];
    const float* er = ew + (long)idx * D_;
    float a0 = er[tid], a1 = er[tid + 256], a2 = er[tid + 512];
    float ss = blockReduceSum256(a0*a0 + a1*a1 + a2*a2, red);
    float r = rsqrtf(ss / (float)D_ + EPSF);
    long o = (long)bt * D_;
    x0[o + tid]       = a0 * r;  x[o + tid]       = a0 * r;
    x0[o + tid + 256] = a1 * r;  x[o + tid + 256] = a1 * r;
    x0[o + tid + 512] = a2 * r;  x[o + tid + 512] = a2 * r;
    #pragma unroll
    for (int j = 0; j < 3; j++) {
        const float* vr = vew + ((long)j * 50257 + idx) * D_;
        float* vo = ve + ((long)j * (B_*T_) + bt) * D_;
        for (int d = tid; d < D_; d += 256) vo[d] = vr[d];
    }
}

// ------- fused residual + rms norm: x = l0*(x + sw*skip) + l1*x0 ; xn = h(norm(x))
__global__ __launch_bounds__(256)
void gpt_resnorm(float* __restrict__ x, const float* __restrict__ x0,
                 const float* __restrict__ skip, const float* __restrict__ scalars,
                 int layer, __half* __restrict__ xn)
{
    __shared__ float red[256];
    float l0 = scalars[L_ + 2*layer];
    float l1 = scalars[L_ + 2*layer + 1];
    float sw = skip ? scalars[layer - 6] : 0.f;
    int tid = threadIdx.x;
    long o = (long)blockIdx.x * D_;
    float a[3];
    #pragma unroll
    for (int j = 0; j < 3; j++) {
        long i = o + tid + j*256;
        float v = x[i];
        if (skip) v += sw * skip[i];
        v = l0 * v + l1 * x0[i];
        x[i] = v;
        a[j] = v;
    }
    float ss = blockReduceSum256(a[0]*a[0] + a[1]*a[1] + a[2]*a[2], red);
    float r = rsqrtf(ss / (float)D_ + EPSF);
    #pragma unroll
    for (int j = 0; j < 3; j++)
        xn[o + tid + j*256] = __float2half_rn(a[j] * r);
}

// ---------------- rms norm (row = 768), output fp16 ----------------
__global__ __launch_bounds__(256)
void gpt_rmsnorm(const float* __restrict__ x, __half* __restrict__ y)
{
    __shared__ float red[256];
    int tid = threadIdx.x;
    const float* xr = x + (long)blockIdx.x * D_;
    float a0 = xr[tid], a1 = xr[tid + 256], a2 = xr[tid + 512];
    float ss = blockReduceSum256(a0*a0 + a1*a1 + a2*a2, red);
    float r = rsqrtf(ss / (float)D_ + EPSF);
    __half* yr = y + (long)blockIdx.x * D_;
    yr[tid]       = __float2half_rn(a0 * r);
    yr[tid + 256] = __float2half_rn(a1 * r);
    yr[tid + 512] = __float2half_rn(a2 * r);
}

// ---------------- copy (for skip buffers) ----------------
__global__ __launch_bounds__(256)
void gpt_copy(float* __restrict__ dst, const float* __restrict__ src)
{
    long i = ((long)blockIdx.x * 256 + threadIdx.x) * 4;
    float4 v = *(const float4*)&src[i];
    *(float4*)&dst[i] = v;
}

// ------- warp-level rope: one warp per (b,t,h); lane owns hd = lane + 32*j -------
__global__ __launch_bounds__(256)
void gpt_rope(const __half* __restrict__ qkv, const float* __restrict__ ve,
              const float* __restrict__ scalars, int layer,
              __half* __restrict__ q, __half* __restrict__ k, __half* __restrict__ vt,
              const float2* __restrict__ rtab)
{
    int z = blockIdx.x * 8 + (threadIdx.x >> 5);
    int lane = threadIdx.x & 31;
    int h = z % H_;
    int t = (z / H_) % T_;
    int b = z / (H_ * T_);
    long bt = (long)b * T_ + t;
    const __half* base = qkv + bt * (3*H_*HD_) + h * HD_;

    float qv[4], kv[4], vv[4];
    #pragma unroll
    for (int j = 0; j < 4; j++) {
        qv[j] = __half2float(base[lane + 32*j]);
        kv[j] = __half2float(base[H_*HD_ + lane + 32*j]);
        vv[j] = __half2float(base[2*H_*HD_ + lane + 32*j]);
    }
    float sq = qv[0]*qv[0] + qv[1]*qv[1] + qv[2]*qv[2] + qv[3]*qv[3];
    float sk = kv[0]*kv[0] + kv[1]*kv[1] + kv[2]*kv[2] + kv[3]*kv[3];
    #pragma unroll
    for (int s = 16; s > 0; s >>= 1) {
        sq += __shfl_xor_sync(0xffffffff, sq, s);
        sk += __shfl_xor_sync(0xffffffff, sk, s);
    }
    float rnq = rsqrtf(sq / (float)HD_ + EPSF);
    float rnk = rsqrtf(sk / (float)HD_ + EPSF);
    #pragma unroll
    for (int j = 0; j < 4; j++) { qv[j] *= rnq; kv[j] *= rnk; }

    float2 cs = rtab[t*32 + lane];
    float oq0 =  qv[0]*cs.x + qv[2]*cs.y;
    float oq2 = -qv[0]*cs.y + qv[2]*cs.x;
    float ok0 =  kv[0]*cs.x + kv[2]*cs.y;
    float ok2 = -kv[0]*cs.y + kv[2]*cs.x;

    long o = (((long)b * H_ + h) * T_ + t) * HD_;
    q[o + lane]      = __float2half_rn(oq0);
    q[o + lane + 32] = __float2half_rn(qv[1]);
    q[o + lane + 64] = __float2half_rn(oq2);
    q[o + lane + 96] = __float2half_rn(qv[3]);
    k[o + lane]      = __float2half_rn(ok0);
    k[o + lane + 32] = __float2half_rn(kv[1]);
    k[o + lane + 64] = __float2half_rn(ok2);
    k[o + lane + 96] = __float2half_rn(kv[3]);

    float sa0 = scalars[3*L_ + 2*layer];
    float sa1 = scalars[3*L_ + 2*layer + 1];
    long vbase = ((long)b * H_ + h) * HD_;
    #pragma unroll
    for (int j = 0; j < 4; j++) {
        float vo = sa0 * vv[j];
        if (ve) vo += sa1 * ve[bt * D_ + h * HD_ + lane + 32*j];
        vt[(vbase + lane + 32*j) * T_ + t] = __float2half_rn(vo);
    }
}

// =================================================================================
// Fused flash attention: 128 q-rows per CTA (8 warps), K/V tiles of 64, online
// softmax, double-buffered cp.async K/V. Q/K: [b][h][t][hd]; V: [b][h][hd][t].
// =================================================================================
__global__ void __launch_bounds__(256, 1)
gpt_flash(const __half* __restrict__ Q, const __half* __restrict__ K,
          const __half* __restrict__ Vt, __half* __restrict__ att)
{
    const int qt = 7 - blockIdx.x;            // heavy tiles first
    const int bh = blockIdx.y;
    const int b = bh / H_, h = bh % H_;
    const int tid = threadIdx.x;
    const int w = tid >> 5, lane = tid & 31;
    const int g = lane >> 2, t = lane & 3;

    const __half* Qb = Q  + (((long)bh * T_) + qt*128) * HD_;
    const __half* Kb = K  + (long)bh * T_ * HD_;
    const __half* Vb = Vt + (long)bh * HD_ * T_;

    extern __shared__ uint32_t sm[];
    uint32_t sbase = (uint32_t)__cvta_generic_to_shared(sm);

    #pragma unroll
    for (int j = 0; j < 8; j++) {
        int i = tid + j*256;
        int row = i >> 4, c16 = i & 15;
        int kc = c16 >> 2, wg = c16 & 3;
        uint32_t word = (kc*128 + row)*16 + swz(row, wg)*4;
        cp16(sbase + 4u*word, Qb + row*HD_ + c16*8);
    }
    asm volatile("cp.async.commit_group;" ::: "memory");

    const int NT = 2*qt + 2;

    auto issueKV = [&](int kt) {
        int s = kt & 1;
        uint32_t kw0 = 8192 + s*8192;
        #pragma unroll
        for (int j = 0; j < 4; j++) {
            int i = tid + j*256;
            int row = i >> 4, c16 = i & 15;
            int kc = c16 >> 2, wg = c16 & 3;
            uint32_t word = kw0 + (kc*64 + row)*16 + swz(row, wg)*4;
            cp16(sbase + 4u*word, Kb + (long)(kt*64 + row)*HD_ + c16*8);
        }
        uint32_t vw0 = 12288 + s*8192;
        #pragma unroll
        for (int j = 0; j < 4; j++) {
            int i = tid + j*256;
            int row = i >> 3, c16 = i & 7;
            int kc = c16 >> 2, wg = c16 & 3;
            uint32_t word = vw0 + (kc*128 + row)*16 + swz(row, wg)*4;
            cp16(sbase + 4u*word, Vb + (long)row*T_ + kt*64 + c16*8);
        }
        asm volatile("cp.async.commit_group;" ::: "memory");
    };

    issueKV(0); issueKV(1);

    float m0 = -1e30f, m1 = -1e30f, l0 = 0.f, l1 = 0.f;
    float oacc[16][4];
    #pragma unroll
    for (int a = 0; a < 16; a++)
        #pragma unroll
        for (int c = 0; c < 4; c++) oacc[a][c] = 0.f;

    const int r0 = w*16 + g;
    const int grow = qt*128 + r0;

    for (int kt = 0; kt < NT; kt++) {
        if (kt + 1 < NT) asm volatile("cp.async.wait_group 1;" ::: "memory");
        else             asm volatile("cp.async.wait_group 0;" ::: "memory");
        __syncthreads();

        const uint32_t* Kc = sm + 8192 + (kt & 1)*8192;
        const uint32_t* Vc = sm + 12288 + (kt & 1)*8192;

        float sacc[8][4];
        #pragma unroll
        for (int a = 0; a < 8; a++)
            #pragma unroll
            for (int c = 0; c < 4; c++) sacc[a][c] = 0.f;

        #pragma unroll
        for (int kc = 0; kc < 4; kc++) {
            const uint32_t* Qc = sm + kc*2048;
            const uint32_t* Kk = Kc + kc*1024;
            #pragma unroll
            for (int ks = 0; ks < 2; ks++) {
                int s0 = swz(r0, ks*2)*4 + t;
                int s1 = swz(r0, ks*2 + 1)*4 + t;
                uint32_t af[4];
                af[0] = Qc[r0*16 + s0];
                af[1] = Qc[(r0+8)*16 + s0];
                af[2] = Qc[r0*16 + s1];
                af[3] = Qc[(r0+8)*16 + s1];
                #pragma unroll
                for (int ni = 0; ni < 8; ni++) {
                    int nr = ni*8 + g;
                    uint32_t bf[2];
                    bf[0] = Kk[nr*16 + swz(nr, ks*2)*4 + t];
                    bf[1] = Kk[nr*16 + swz(nr, ks*2 + 1)*4 + t];
                    mma16(sacc[ni], af, bf);
                }
            }
        }

        bool diag = (kt >= 2*qt);
        #pragma unroll
        for (int ni = 0; ni < 8; ni++) {
            int col = kt*64 + ni*8 + t*2;
            float v0 = 0.12f * sacc[ni][0];
            float v1 = 0.12f * sacc[ni][1];
            float v2 = 0.12f * sacc[ni][2];
            float v3 = 0.12f * sacc[ni][3];
            if (diag) {
                if (col     > grow)     v0 = -1e30f;
                if (col + 1 > grow)     v1 = -1e30f;
                if (col     > grow + 8) v2 = -1e30f;
                if (col + 1 > grow + 8) v3 = -1e30f;
            }
            sacc[ni][0] = v0; sacc[ni][1] = v1; sacc[ni][2] = v2; sacc[ni][3] = v3;
        }

        float rm0 = -1e30f, rm1 = -1e30f;
        #pragma unroll
        for (int ni = 0; ni < 8; ni++) {
            rm0 = fmaxf(rm0, fmaxf(sacc[ni][0], sacc[ni][1]));
            rm1 = fmaxf(rm1, fmaxf(sacc[ni][2], sacc[ni][3]));
        }
        rm0 = fmaxf(rm0, __shfl_xor_sync(0xffffffff, rm0, 1));
        rm0 = fmaxf(rm0, __shfl_xor_sync(0xffffffff, rm0, 2));
        rm1 = fmaxf(rm1, __shfl_xor_sync(0xffffffff, rm1, 1));
        rm1 = fmaxf(rm1, __shfl_xor_sync(0xffffffff, rm1, 2));

        float mn0 = fmaxf(m0, rm0), mn1 = fmaxf(m1, rm1);
        float sc0 = __expf(m0 - mn0), sc1 = __expf(m1 - mn1);
        m0 = mn0; m1 = mn1;

        float ls0 = 0.f, ls1 = 0.f;
        uint32_t phg[8], phg8[8];
        #pragma unroll
        for (int ni = 0; ni < 8; ni++) {
            float p0 = __expf(sacc[ni][0] - mn0);
            float p1 = __expf(sacc[ni][1] - mn0);
            float p2 = __expf(sacc[ni][2] - mn1);
            float p3 = __expf(sacc[ni][3] - mn1);
            ls0 += p0 + p1; ls1 += p2 + p3;
            phg[ni]  = packh2(p0, p1);
            phg8[ni] = packh2(p2, p3);
        }
        ls0 += __shfl_xor_sync(0xffffffff, ls0, 1);
        ls0 += __shfl_xor_sync(0xffffffff, ls0, 2);
        ls1 += __shfl_xor_sync(0xffffffff, ls1, 1);
        ls1 += __shfl_xor_sync(0xffffffff, ls1, 2);
        l0 = l0*sc0 + ls0;
        l1 = l1*sc1 + ls1;

        #pragma unroll
        for (int ni = 0; ni < 16; ni++) {
            oacc[ni][0] *= sc0; oacc[ni][1] *= sc0;
            oacc[ni][2] *= sc1; oacc[ni][3] *= sc1;
        }

        #pragma unroll
        for (int kk = 0; kk < 4; kk++) {
            uint32_t af[4] = { phg[2*kk], phg8[2*kk], phg[2*kk+1], phg8[2*kk+1] };
            const uint32_t* Vk = Vc + (kk >> 1)*2048;
            int ks = kk & 1;
            #pragma unroll
            for (int ni = 0; ni < 16; ni++) {
                int nr = ni*8 + g;
                uint32_t bf[2];
                bf[0] = Vk[nr*16 + swz(nr, ks*2)*4 + t];
                bf[1] = Vk[nr*16 + swz(nr, ks*2 + 1)*4 + t];
                mma16(oacc[ni], af, bf);
            }
        }

        __syncthreads();
        if (kt + 2 < NT) issueKV(kt + 2);
    }

    float inv0 = 1.f / l0, inv1 = 1.f / l1;
    long base0 = ((long)b*T_ + grow) * D_ + h*HD_;
    long base1 = base0 + 8L*D_;
    #pragma unroll
    for (int ni = 0; ni < 16; ni++) {
        int col = ni*8 + t*2;
        *(uint32_t*)&att[base0 + col] = packh2(oacc[ni][0]*inv0, oacc[ni][1]*inv0);
        *(uint32_t*)&att[base1 + col] = packh2(oacc[ni][2]*inv1, oacc[ni][3]*inv1);
    }
}

// =================================================================================
// fp16 tensor-core GEMM (m16n8k16, fp32 accum), cp.async 4-stage pipeline.
// EPI: 0=store half, 1=accumulate into float C, 2=relu^2 store half,
//      5=split-K atomicAdd into float C (blockIdx.z = K-split; aZ/bZ = col offset)
// =================================================================================
template<int EPI, int MT>
__global__ void
__launch_bounds__(MT == 4 ? 512 : 256, MT == 4 ? 1 : 2)
gpt_gemm(const __half* __restrict__ A, const __half* __restrict__ Bm, void* __restrict__ Cv,
         float* __restrict__ C2,
         int K, int lda, int ldb, int ldc,
         long aZ, long bZ, int zdiv, long c1, long c2, float alpha, int ktri)
{
    constexpr int THREADS = (MT == 4) ? 512 : 256;
    constexpr int BM = MT * 64;
    constexpr int AROWS = THREADS / 4;
    constexpr int APASS = BM / AROWS;
    constexpr int BPASS = 128 / AROWS;

    const int m0 = blockIdx.y * BM, n0 = blockIdx.x * 128;

    int z = blockIdx.z;
    A  += (long)z * aZ;
    Bm += (long)z * bZ;
    long coff = (long)(z / zdiv) * c1 + (long)(z % zdiv) * c2;
    float*  Cf = (float*)Cv + coff;
    __half* Ch = (__half*)Cv + coff;

    const int tid  = threadIdx.x;
    const int lane = tid & 31, warp = tid >> 5;
    const int wm = warp >> 2, wn = warp & 3;
    const int g = lane >> 2, t = lane & 3;

    extern __shared__ uint32_t smem[];
    uint32_t* As = smem;
    uint32_t* Bs = smem + NSTAGE * BM * 16;
    uint32_t as0 = (uint32_t)__cvta_generic_to_shared(As);
    uint32_t bs0 = (uint32_t)__cvta_generic_to_shared(Bs);

    int keff = K;
    if (ktri) { int kk = m0 + BM; keff = kk < K ? kk : K; }
    const int NT = keff / BKH;

    float acc[4][4][4];
    #pragma unroll
    for (int a = 0; a < 4; a++)
        #pragma unroll
        for (int b = 0; b < 4; b++)
            #pragma unroll
            for (int c = 0; c < 4; c++) acc[a][b][c] = 0.f;

    const int ar  = tid >> 2;
    const int acg = tid & 3;
    const __half* apB = A  + (long)(m0 + ar) * lda + acg*8;
    const __half* bpB = Bm + (long)(n0 + ar) * ldb + acg*8;

    auto issue = [&](int kt) {
        int s = kt % NSTAGE;
        const __half* ap = apB + kt*BKH;
        #pragma unroll
        for (int j = 0; j < APASS; j++) {
            int r = ar + AROWS*j;
            cp16(as0 + 4u*(s*BM*16 + r*16 + swz(r, acg)*4), ap + (long)(AROWS*j) * lda);
        }
        const __half* bp = bpB + kt*BKH;
        #pragma unroll
        for (int j = 0; j < BPASS; j++) {
            int r = ar + AROWS*j;
            cp16(bs0 + 4u*(s*128*16 + r*16 + swz(r, acg)*4), bp + (long)(AROWS*j) * ldb);
        }
        asm volatile("cp.async.commit_group;" ::: "memory");
    };

    issue(0); issue(1); issue(2);

    for (int kt = 0; kt < NT; kt++) {
        if (kt + 1 >= NT)      asm volatile("cp.async.wait_group 0;" ::: "memory");
        else if (kt + 2 >= NT) asm volatile("cp.async.wait_group 1;" ::: "memory");
        else                   asm volatile("cp.async.wait_group 2;" ::: "memory");
        __syncthreads();

        const uint32_t* Ab = As + (kt % NSTAGE) * BM * 16;
        const uint32_t* Bb = Bs + (kt % NSTAGE) * 128 * 16;
        #pragma unroll
        for (int ks = 0; ks < 2; ks++) {
            uint32_t af[4][4];
            #pragma unroll
            for (int mi = 0; mi < 4; mi++) {
                int r0 = wm*64 + mi*16 + g;
                int s0 = swz(r0, ks*2)*4 + t;
                int s1 = swz(r0, ks*2 + 1)*4 + t;
                af[mi][0] = Ab[r0*16 + s0];
                af[mi][1] = Ab[(r0+8)*16 + s0];
                af[mi][2] = Ab[r0*16 + s1];
                af[mi][3] = Ab[(r0+8)*16 + s1];
            }
            uint32_t bf[4][2];
            #pragma unroll
            for (int ni = 0; ni < 4; ni++) {
                int nr = wn*32 + ni*8 + g;
                bf[ni][0] = Bb[nr*16 + swz(nr, ks*2)*4 + t];
                bf[ni][1] = Bb[nr*16 + swz(nr, ks*2 + 1)*4 + t];
            }
            #pragma unroll
            for (int mi = 0; mi < 4; mi++)
                #pragma unroll
                for (int ni = 0; ni < 4; ni++)
                    mma16(acc[mi][ni], af[mi], bf[ni]);
        }

        if (kt + NSTAGE - 1 < NT) issue(kt + NSTAGE - 1);
    }

    // ---- epilogue ----
    #pragma unroll
    for (int mi = 0; mi < 4; mi++) {
        int row = m0 + wm*64 + mi*16 + g;
        #pragma unroll
        for (int ni = 0; ni < 4; ni++) {
            int col = n0 + wn*32 + ni*8 + t*2;
            float* a4 = acc[mi][ni];
            #pragma unroll
            for (int half_ = 0; half_ < 2; half_++) {
                int r = row + half_ * 8;
                float c0 = a4[half_*2 + 0], c1 = a4[half_*2 + 1];
                if (EPI == 0) {
                    *(__half2*)&Ch[(long)r * ldc + col] = __floats2half2_rn(c0, c1);
                } else if (EPI == 2) {
                    float r0 = fmaxf(c0, 0.f), r1 = fmaxf(c1, 0.f);
                    *(__half2*)&Ch[(long)r * ldc + col] = __floats2half2_rn(r0*r0, r1*r1);
                } else if (EPI == 5) {
                    atomicAdd(&Cf[(long)r * ldc + col],     c0);
                    atomicAdd(&Cf[(long)r * ldc + col + 1], c1);
                } else {  // EPI == 1
                    float* cp = &Cf[(long)r * ldc + col];
                    float2 o = *(float2*)cp;
                    *(float2*)cp = make_float2(o.x + c0, o.y + c1);
                }
            }
        }
    }
}

// ---------------- final norm -> output ----------------
__global__ __launch_bounds__(256)
void gpt_finalnorm(const float* __restrict__ x, float* __restrict__ out)
{
    __shared__ float red[256];
    int tid = threadIdx.x;
    const float* xr = x + (long)blockIdx.x * D_;
    float a0 = xr[tid], a1 = xr[tid + 256], a2 = xr[tid + 512];
    float ss = blockReduceSum256(a0*a0 + a1*a1 + a2*a2, red);
    float r = rsqrtf(ss / (float)D_ + EPSF);
    float* yr = out + (long)blockIdx.x * D_;
    yr[tid] = a0 * r; yr[tid + 256] = a1 * r; yr[tid + 512] = a2 * r;
}

// ---------------- host orchestration ----------------
#define SMEM4 (NSTAGE * (256 + 128) * 16 * 4)   // 98304
#define SMEM2 (NSTAGE * (128 + 128) * 16 * 4)   // 65536
#define SMEMF ((8192 + 2*8192) * 4)             // 98304 (flash)

extern "C" void kernel_launch(void* const* d_in, const int* in_sizes, int n_in,
                              void* d_out, int out_size)
{
    const int*   seq         = (const int*)  d_in[0];
    const float* embed_w     = (const float*)d_in[1];
    const float* ve_w        = (const float*)d_in[2];
    const float* qkv_w       = (const float*)d_in[3];
    const float* attn_proj_w = (const float*)d_in[4];
    const float* mlp_fc_w    = (const float*)d_in[5];
    const float* mlp_proj_w  = (const float*)d_in[6];
    const float* scalars     = (const float*)d_in[7];

    cudaFuncSetAttribute(gpt_gemm<0,4>, cudaFuncAttributeMaxDynamicSharedMemorySize, SMEM4);
    cudaFuncSetAttribute(gpt_gemm<2,4>, cudaFuncAttributeMaxDynamicSharedMemorySize, SMEM4);
    cudaFuncSetAttribute(gpt_gemm<5,2>, cudaFuncAttributeMaxDynamicSharedMemorySize, SMEM2);
    cudaFuncSetAttribute(gpt_flash,     cudaFuncAttributeMaxDynamicSharedMemorySize, SMEMF);

    float *x, *x0, *skips, *ve;
    float2 *rtab;
    __half *xn, *qkv, *q, *k, *vt, *att, *hbuf;
    __half *qkvw, *aprojw, *fcw, *mprojw;
    cudaGetSymbolAddress((void**)&x,      g_x);
    cudaGetSymbolAddress((void**)&x0,     g_x0);
    cudaGetSymbolAddress((void**)&xn,     g_xn);
    cudaGetSymbolAddress((void**)&skips,  g_skips);
    cudaGetSymbolAddress((void**)&ve,     g_ve);
    cudaGetSymbolAddress((void**)&qkv,    g_qkv);
    cudaGetSymbolAddress((void**)&q,      g_q);
    cudaGetSymbolAddress((void**)&k,      g_k);
    cudaGetSymbolAddress((void**)&vt,     g_vt);
    cudaGetSymbolAddress((void**)&att,    g_att);
    cudaGetSymbolAddress((void**)&hbuf,   g_hbuf);
    cudaGetSymbolAddress((void**)&rtab,   g_rtab);
    cudaGetSymbolAddress((void**)&qkvw,   g_qkvw);
    cudaGetSymbolAddress((void**)&aprojw, g_aprojw);
    cudaGetSymbolAddress((void**)&fcw,    g_fcw);
    cudaGetSymbolAddress((void**)&mprojw, g_mprojw);

    const int NTOK = B_ * T_;   // 4096

    gpt_cvtw<<<2048, 256>>>(qkv_w,       qkvw,   (long)L_*3*H_*HD_*D_);
    gpt_cvtw<<<2048, 256>>>(attn_proj_w, aprojw, (long)L_*D_*H_*HD_);
    gpt_cvtw<<<2048, 256>>>(mlp_fc_w,    fcw,    (long)L_*4*D_*D_);
    gpt_cvtw<<<2048, 256>>>(mlp_proj_w,  mprojw, (long)L_*D_*4*D_);
    gpt_ropetab<<<128, 256>>>(rtab);

    gpt_embed<<<NTOK, 256>>>(seq, embed_w, ve_w, x, x0, ve);

    for (int i = 0; i < L_; i++) {
        const float* skip = (i >= 6) ? (skips + (long)(11 - i) * BTD) : nullptr;
        gpt_resnorm<<<NTOK, 256>>>(x, x0, skip, scalars, i, xn);

        if (i != 7) {
            // qkv = xn @ W_qkv^T : [4096,768] x [2304,768]^T  -> half
            gpt_gemm<0,4><<<dim3(18, 16, 1), 512, SMEM4>>>(
                xn, qkvw + (long)i * 3 * H_ * HD_ * D_, qkv, nullptr,
                D_, D_, D_, 3*H_*HD_, 0, 0, 1, 0, 0, 1.f, 0);

            const float* vep = nullptr;
            if (i < 3)       vep = ve + (long)i * BTD;
            else if (i >= 9) vep = ve + (long)(i - 9) * BTD;
            gpt_rope<<<B_*T_*H_/8, 256>>>(qkv, vep, scalars, i, q, k, vt, rtab);

            // fused flash attention -> att (half)
            gpt_flash<<<dim3(8, B_*H_), 256, SMEMF>>>(q, k, vt, att);

            // x += att @ W_proj^T  (split-K=2, atomicAdd)
            gpt_gemm<5,2><<<dim3(6, 32, 2), 256, SMEM2>>>(
                att, aprojw + (long)i * D_ * H_ * HD_, x, nullptr,
                (H_*HD_)/2, H_*HD_, H_*HD_, D_,
                (H_*HD_)/2, (H_*HD_)/2, 1, 0, 0, 1.f, 0);

            gpt_rmsnorm<<<NTOK, 256>>>(x, xn);
        }

        // h = relu(xn @ W_fc^T)^2 : [4096,768] x [3072,768]^T -> half
        gpt_gemm<2,4><<<dim3(24, 16, 1), 512, SMEM4>>>(
            xn, fcw + (long)i * 4 * D_ * D_, hbuf, nullptr,
            D_, D_, D_, 4*D_, 0, 0, 1, 0, 0, 1.f, 0);

        // x += h @ W_proj^T  (split-K=2, atomicAdd)
        gpt_gemm<5,2><<<dim3(6, 32, 2), 256, SMEM2>>>(
            hbuf, mprojw + (long)i * D_ * 4 * D_, x, nullptr,
            (4*D_)/2, 4*D_, 4*D_, D_,
            (4*D_)/2, (4*D_)/2, 1, 0, 0, 1.f, 0);

        if (i < 6) gpt_copy<<<BTD/1024, 256>>>(skips + (long)i * BTD, x);
    }

    gpt_finalnorm<<<NTOK, 256>>>(x, (float*)d_out);
}